// round 3
// baseline (speedup 1.0000x reference)
#include <cuda_runtime.h>
#include <math.h>

// ---------------- problem constants ----------------
#define TK   4096      // tokens = B*S
#define HH   1024      // hidden
#define SS   2048      // seq len
#define NHH  16        // heads
#define BHN  32        // B*NH
#define II   384       // expert intermediate
#define NE   8         // routed experts

// ---------------- scratch (device globals; no allocation allowed) ----------------
__device__ float g_xi [TK*HH];
__device__ float g_cq [TK*128];
__device__ float g_ckv[TK*128];
__device__ float g_qn [TK*512];
__device__ float g_qr [TK*512];
__device__ float g_kn [TK*512];
__device__ float g_kr [TK*512];
__device__ float g_vx [TK*HH];
__device__ float g_q  [TK*HH];   // [bh][s][64]
__device__ float g_k  [TK*HH];
__device__ float g_v  [TK*HH];
__device__ float g_o  [TK*HH];   // [b][s][h*64+d]
__device__ float g_h  [TK*HH];
__device__ float g_hn [TK*HH];
__device__ float g_gt [TK*II];
__device__ float g_ut [TK*II];
__device__ float g_act[TK*II];
__device__ int   g_cnt[NE];
__device__ int   g_tok[NE*TK];
__device__ float g_twt[NE*TK];

// ---------------- generic SGEMM ----------------
// C[m][n] = sum_k A[m][k]*B[k][n], with options:
//   ridx + gatherA : A row = ridx[m]       (compact output rows)
//   ridx + scatterC: C row = ridx[m]       (compact input rows)
//   rscale         : C[crow] += rscale[m]*acc
//   accflag        : C += acc
//   addsrc         : C = acc + addsrc[m][n]
//   cntp           : dynamic effective M (device counter)
template<int BM, int BN, int TM, int TN>
__global__ void __launch_bounds__(256) sgemm_k(
    const float* __restrict__ A, int lda,
    const float* __restrict__ B, int ldb,
    float* __restrict__ C, int ldc,
    int M, int N, int K,
    const int* __restrict__ ridx, int gatherA, int scatterC,
    const float* __restrict__ rscale,
    const float* __restrict__ addsrc, int accflag,
    const int* __restrict__ cntp)
{
    constexpr int BK = 8;
    __shared__ float As[BK][BM];
    __shared__ float Bs[BK][BN];
    __shared__ int   idxs[BM];

    const int m0 = blockIdx.y * BM;
    const int n0 = blockIdx.x * BN;
    const int effM = cntp ? *cntp : M;
    if (m0 >= effM) return;                    // uniform across block

    const int tid = threadIdx.x;
    if (ridx) {
        for (int i = tid; i < BM; i += 256) {
            int m = m0 + i;
            idxs[i] = (m < effM) ? ridx[m] : 0;
        }
    }
    __syncthreads();

    const int tx = tid % (BN / TN);
    const int ty = tid / (BN / TN);

    float r[TM][TN];
    #pragma unroll
    for (int i = 0; i < TM; i++)
        #pragma unroll
        for (int j = 0; j < TN; j++) r[i][j] = 0.f;

    constexpr int ALD = BM * BK / 256;
    constexpr int BLD = BN * BK / 256;

    for (int kt = 0; kt < K; kt += BK) {
        #pragma unroll
        for (int i = 0; i < ALD; i++) {
            int flat = tid + i * 256;
            int am = flat >> 3, ak = flat & 7;
            int m = m0 + am;
            float v = 0.f;
            if (m < effM) {
                int row = gatherA ? idxs[am] : m;
                v = A[(size_t)row * lda + kt + ak];
            }
            As[ak][am] = v;
        }
        #pragma unroll
        for (int i = 0; i < BLD; i++) {
            int flat = tid + i * 256;
            int bn = flat % BN;
            int bk = flat / BN;
            Bs[bk][bn] = B[(size_t)(kt + bk) * ldb + n0 + bn];
        }
        __syncthreads();
        #pragma unroll
        for (int kk = 0; kk < BK; kk++) {
            float a[TM], b[TN];
            #pragma unroll
            for (int i = 0; i < TM; i++) a[i] = As[kk][ty * TM + i];
            #pragma unroll
            for (int j = 0; j < TN; j++) b[j] = Bs[kk][tx * TN + j];
            #pragma unroll
            for (int i = 0; i < TM; i++)
                #pragma unroll
                for (int j = 0; j < TN; j++) r[i][j] += a[i] * b[j];
        }
        __syncthreads();
    }

    #pragma unroll
    for (int i = 0; i < TM; i++) {
        int ml = ty * TM + i;
        int m = m0 + ml;
        if (m >= effM) continue;
        int crow = scatterC ? idxs[ml] : m;
        float sc = rscale ? rscale[m] : 1.f;
        #pragma unroll
        for (int j = 0; j < TN; j++) {
            int n = n0 + tx * TN + j;
            float* cp = C + (size_t)crow * ldc + n;
            float v = r[i][j];
            if (rscale)            *cp += sc * v;
            else if (accflag)      *cp += v;
            else if (addsrc)       *cp  = v + addsrc[(size_t)m * ldc + n];
            else                   *cp  = v;
        }
    }
}

// ---------------- RMSNorm (one block per row; in-place safe) ----------------
__global__ void rms_k(const float* __restrict__ x, const float* __restrict__ w,
                      float* __restrict__ y, int D)
{
    int t = blockIdx.x;
    const float* xr = x + (size_t)t * D;
    float* yr = y + (size_t)t * D;
    float ss = 0.f;
    for (int k = threadIdx.x; k < D; k += blockDim.x) { float v = xr[k]; ss += v * v; }
    __shared__ float sh[32];
    int lane = threadIdx.x & 31, wid = threadIdx.x >> 5;
    #pragma unroll
    for (int o = 16; o > 0; o >>= 1) ss += __shfl_xor_sync(0xffffffffu, ss, o);
    if (lane == 0) sh[wid] = ss;
    __syncthreads();
    if (threadIdx.x == 0) {
        float tot = 0.f;
        int nw = blockDim.x >> 5;
        for (int i = 0; i < nw; i++) tot += sh[i];
        sh[0] = tot;
    }
    __syncthreads();
    float r = rsqrtf(sh[0] / (float)D + 1e-5f);
    for (int k = threadIdx.x; k < D; k += blockDim.x) yr[k] = w[k] * xr[k] * r;
}

// ---------------- assemble Q/K/V with RoPE ----------------
// layouts: g_q/g_k/g_v = [bh][s][64]
__global__ void assemble_k(const float* __restrict__ qn, const float* __restrict__ qr,
                           const float* __restrict__ kn, const float* __restrict__ kr,
                           const float* __restrict__ vx,
                           const float* __restrict__ cosp, const float* __restrict__ sinp,
                           float* __restrict__ Q, float* __restrict__ K, float* __restrict__ V)
{
    int idx = blockIdx.x * blockDim.x + threadIdx.x;
    if (idx >= BHN * SS * 64) return;
    int d  = idx & 63;
    int s  = (idx >> 6) & (SS - 1);
    int bh = idx >> 17;
    int b  = bh >> 4, h = bh & 15;
    int t  = b * SS + s;
    float qv, kv;
    if (d < 32) {
        qv = qn[(size_t)t * 512 + h * 32 + d];
        kv = kn[(size_t)t * 512 + h * 32 + d];
    } else {
        int j = d - 32;
        float c  = cosp[s * 32 + j];
        float sn = sinp[s * 32 + j];
        float q1 = qr[(size_t)t * 512 + h * 32 + j];
        float q2 = (j < 16) ? -qr[(size_t)t * 512 + h * 32 + j + 16]
                            :  qr[(size_t)t * 512 + h * 32 + j - 16];
        qv = q1 * c + q2 * sn;
        float k1 = kr[(size_t)t * 512 + h * 32 + j];
        float k2 = (j < 16) ? -kr[(size_t)t * 512 + h * 32 + j + 16]
                            :  kr[(size_t)t * 512 + h * 32 + j - 16];
        kv = k1 * c + k2 * sn;
    }
    Q[idx] = qv;
    K[idx] = kv;
    V[idx] = vx[(size_t)t * HH + h * 64 + d];
}

// ---------------- flash attention (fp32, non-causal, +mask) ----------------
__global__ void __launch_bounds__(256) flash_k(
    const float* __restrict__ Q, const float* __restrict__ Kg,
    const float* __restrict__ Vg, const float* __restrict__ maskp,
    float* __restrict__ O)
{
    extern __shared__ float sm[];
    float* Qt = sm;              // [64][64]  Qt[d][m]
    float* Kt = sm + 4096;       // [64][64]  Kt[d][n]
    float* Vs = sm + 8192;       // [64][64]  Vs[n][d]
    float* Pt = sm + 12288;      // [64][65]  Pt[n][m] (pad 65 to dodge conflicts)

    const int bh = blockIdx.y;
    const int q0 = blockIdx.x * 64;
    const int b  = bh >> 4, hh = bh & 15;
    const float* Qb = Q  + (size_t)bh * SS * 64;
    const float* Kb = Kg + (size_t)bh * SS * 64;
    const float* Vb = Vg + (size_t)bh * SS * 64;

    const int tid = threadIdx.x;
    const int tx = tid & 15, ty = tid >> 4;
    const int lr  = tid >> 2;            // 0..63 load row
    const int ld0 = (tid & 3) * 16;      // load col base

    { // load Q tile transposed
        const float4* src = (const float4*)(Qb + (size_t)(q0 + lr) * 64 + ld0);
        #pragma unroll
        for (int i = 0; i < 4; i++) {
            float4 v = src[i];
            int d = ld0 + i * 4;
            Qt[(d + 0) * 64 + lr] = v.x; Qt[(d + 1) * 64 + lr] = v.y;
            Qt[(d + 2) * 64 + lr] = v.z; Qt[(d + 3) * 64 + lr] = v.w;
        }
    }
    float acc[4][4];
    float mrow[4], lrow[4];
    #pragma unroll
    for (int i = 0; i < 4; i++) {
        mrow[i] = -1e30f; lrow[i] = 0.f;
        #pragma unroll
        for (int j = 0; j < 4; j++) acc[i][j] = 0.f;
    }
    __syncthreads();

    for (int k0 = 0; k0 < SS; k0 += 64) {
        { // load K transposed + V direct
            const float4* ks   = (const float4*)(Kb + (size_t)(k0 + lr) * 64 + ld0);
            const float4* vsrc = (const float4*)(Vb + (size_t)(k0 + lr) * 64 + ld0);
            float4* vd = (float4*)(Vs + lr * 64 + ld0);
            #pragma unroll
            for (int i = 0; i < 4; i++) {
                float4 kv = ks[i];
                int d = ld0 + i * 4;
                Kt[(d + 0) * 64 + lr] = kv.x; Kt[(d + 1) * 64 + lr] = kv.y;
                Kt[(d + 2) * 64 + lr] = kv.z; Kt[(d + 3) * 64 + lr] = kv.w;
                vd[i] = vsrc[i];
            }
        }
        __syncthreads();

        float s[4][4];
        #pragma unroll
        for (int i = 0; i < 4; i++)
            #pragma unroll
            for (int j = 0; j < 4; j++) s[i][j] = 0.f;

        #pragma unroll 8
        for (int d = 0; d < 64; d++) {
            float a[4], bb[4];
            #pragma unroll
            for (int i = 0; i < 4; i++) a[i]  = Qt[d * 64 + ty * 4 + i];
            #pragma unroll
            for (int j = 0; j < 4; j++) bb[j] = Kt[d * 64 + tx * 4 + j];
            #pragma unroll
            for (int i = 0; i < 4; i++)
                #pragma unroll
                for (int j = 0; j < 4; j++) s[i][j] += a[i] * bb[j];
        }
        // scale + mask
        #pragma unroll
        for (int i = 0; i < 4; i++) {
            const float* mp = maskp + (size_t)(q0 + ty * 4 + i) * SS + (k0 + tx * 4);
            #pragma unroll
            for (int j = 0; j < 4; j++) s[i][j] = s[i][j] * 0.125f + mp[j];
        }
        // row max (reduce across the 16 tx lanes of this row group)
        float rmax[4];
        #pragma unroll
        for (int i = 0; i < 4; i++) {
            rmax[i] = fmaxf(fmaxf(s[i][0], s[i][1]), fmaxf(s[i][2], s[i][3]));
        }
        #pragma unroll
        for (int o = 1; o < 16; o <<= 1)
            #pragma unroll
            for (int i = 0; i < 4; i++)
                rmax[i] = fmaxf(rmax[i], __shfl_xor_sync(0xffffffffu, rmax[i], o));

        #pragma unroll
        for (int i = 0; i < 4; i++) {
            float mnew = fmaxf(mrow[i], rmax[i]);
            float corr = __expf(mrow[i] - mnew);
            float rs = 0.f;
            #pragma unroll
            for (int j = 0; j < 4; j++) { s[i][j] = __expf(s[i][j] - mnew); rs += s[i][j]; }
            #pragma unroll
            for (int o = 1; o < 16; o <<= 1) rs += __shfl_xor_sync(0xffffffffu, rs, o);
            mrow[i] = mnew;
            lrow[i] = lrow[i] * corr + rs;
            #pragma unroll
            for (int j = 0; j < 4; j++) acc[i][j] *= corr;
        }
        // store P transposed for the PV gemm
        #pragma unroll
        for (int i = 0; i < 4; i++)
            #pragma unroll
            for (int j = 0; j < 4; j++)
                Pt[(tx * 4 + j) * 65 + ty * 4 + i] = s[i][j];
        __syncthreads();

        #pragma unroll 8
        for (int n = 0; n < 64; n++) {
            float a[4], bb[4];
            #pragma unroll
            for (int i = 0; i < 4; i++) a[i]  = Pt[n * 65 + ty * 4 + i];
            #pragma unroll
            for (int j = 0; j < 4; j++) bb[j] = Vs[n * 64 + tx * 4 + j];
            #pragma unroll
            for (int i = 0; i < 4; i++)
                #pragma unroll
                for (int j = 0; j < 4; j++) acc[i][j] += a[i] * bb[j];
        }
        __syncthreads();
    }

    #pragma unroll
    for (int i = 0; i < 4; i++) {
        float inv = 1.f / lrow[i];
        int qrow = q0 + ty * 4 + i;
        float* op = O + ((size_t)(b * SS + qrow)) * HH + hh * 64 + tx * 4;
        #pragma unroll
        for (int j = 0; j < 4; j++) op[j] = acc[i][j] * inv;
    }
}

// ---------------- router: sigmoid top-2, build compact per-expert lists ----------------
__global__ void router_k(const float* __restrict__ hn, const float* __restrict__ rw,
                         const float* __restrict__ rb,
                         int* __restrict__ cnt, int* __restrict__ tok, float* __restrict__ twt)
{
    int t = blockIdx.x;
    __shared__ float red[128][NE];
    float accv[NE];
    #pragma unroll
    for (int e = 0; e < NE; e++) accv[e] = 0.f;
    const float* xr = hn + (size_t)t * HH;
    for (int k = threadIdx.x; k < HH; k += 128) {
        float xv = xr[k];
        const float* w = rw + (size_t)k * NE;
        #pragma unroll
        for (int e = 0; e < NE; e++) accv[e] += xv * w[e];
    }
    #pragma unroll
    for (int e = 0; e < NE; e++) red[threadIdx.x][e] = accv[e];
    __syncthreads();
    for (int s = 64; s > 0; s >>= 1) {
        if (threadIdx.x < s)
            #pragma unroll
            for (int e = 0; e < NE; e++) red[threadIdx.x][e] += red[threadIdx.x + s][e];
        __syncthreads();
    }
    if (threadIdx.x == 0) {
        float p[NE];
        #pragma unroll
        for (int e = 0; e < NE; e++) {
            float lg = red[0][e] + rb[e];
            p[e] = 1.f / (1.f + expf(-lg));
        }
        int e1 = 0;
        for (int e = 1; e < NE; e++) if (p[e] > p[e1]) e1 = e;
        int e2 = -1;
        for (int e = 0; e < NE; e++) if (e != e1 && (e2 < 0 || p[e] > p[e2])) e2 = e;
        float s2 = p[e1] + p[e2];
        float w1 = p[e1] / s2, w2 = p[e2] / s2;
        int a = atomicAdd(&cnt[e1], 1); tok[e1 * TK + a] = t; twt[e1 * TK + a] = w1;
        int b = atomicAdd(&cnt[e2], 1); tok[e2 * TK + b] = t; twt[e2 * TK + b] = w2;
    }
}

__global__ void silu_mul_k(const float* __restrict__ g, const float* __restrict__ u,
                           float* __restrict__ y, int n)
{
    int i = blockIdx.x * 256 + threadIdx.x;
    if (i < n) {
        float gv = g[i];
        y[i] = (gv / (1.f + expf(-gv))) * u[i];
    }
}

__global__ void usage_k(const int* __restrict__ cnt, float* __restrict__ out)
{
    int e = threadIdx.x;
    if (e < NE) out[e] = (float)cnt[e];
}

// ---------------- host-side launch helpers ----------------
static inline void gemm128(const float* A, int lda, const float* B, int ldb,
                           float* C, int ldc, int M, int N, int K,
                           const int* ridx, int ga, int sc,
                           const float* rs, const float* as, int acc, const int* cnt)
{
    dim3 g(N / 128, (M + 127) / 128);
    sgemm_k<128, 128, 8, 8><<<g, 256>>>(A, lda, B, ldb, C, ldc, M, N, K,
                                        ridx, ga, sc, rs, as, acc, cnt);
}
static inline void gemm64(const float* A, int lda, const float* B, int ldb,
                          float* C, int ldc, int M, int N, int K)
{
    dim3 g(N / 64, (M + 63) / 64);
    sgemm_k<64, 64, 4, 4><<<g, 256>>>(A, lda, B, ldb, C, ldc, M, N, K,
                                      nullptr, 0, 0, nullptr, nullptr, 0, nullptr);
}

extern "C" void kernel_launch(void* const* d_in, const int* in_sizes, int n_in,
                              void* d_out, int out_size)
{
    const float* x        = (const float*)d_in[0];
    const float* cosp     = (const float*)d_in[1];
    const float* sinp     = (const float*)d_in[2];
    const float* maskp    = (const float*)d_in[3];
    const float* ln1      = (const float*)d_in[4];
    const float* ln2      = (const float*)d_in[5];
    const float* kv_down  = (const float*)d_in[6];
    const float* kv_norm  = (const float*)d_in[7];
    const float* w_uk     = (const float*)d_in[8];
    const float* w_ur     = (const float*)d_in[9];
    const float* w_uv     = (const float*)d_in[10];
    const float* q_down   = (const float*)d_in[11];
    const float* q_norm   = (const float*)d_in[12];
    const float* w_uq     = (const float*)d_in[13];
    const float* w_qr     = (const float*)d_in[14];
    const float* o_proj   = (const float*)d_in[15];
    const float* sh_gate  = (const float*)d_in[16];
    const float* sh_up    = (const float*)d_in[17];
    const float* sh_down  = (const float*)d_in[18];
    const float* r_gate   = (const float*)d_in[19];
    const float* r_up     = (const float*)d_in[20];
    const float* r_down   = (const float*)d_in[21];
    const float* router_w = (const float*)d_in[22];
    const float* router_b = (const float*)d_in[23];
    float* out = (float*)d_out;

    float *xi, *cq, *ckv, *qn, *qr, *kn, *kr, *vx, *q, *k, *v, *o, *h, *hn, *gt, *ut, *act, *twt;
    int *cnt, *tok;
    cudaGetSymbolAddress((void**)&xi,  g_xi);
    cudaGetSymbolAddress((void**)&cq,  g_cq);
    cudaGetSymbolAddress((void**)&ckv, g_ckv);
    cudaGetSymbolAddress((void**)&qn,  g_qn);
    cudaGetSymbolAddress((void**)&qr,  g_qr);
    cudaGetSymbolAddress((void**)&kn,  g_kn);
    cudaGetSymbolAddress((void**)&kr,  g_kr);
    cudaGetSymbolAddress((void**)&vx,  g_vx);
    cudaGetSymbolAddress((void**)&q,   g_q);
    cudaGetSymbolAddress((void**)&k,   g_k);
    cudaGetSymbolAddress((void**)&v,   g_v);
    cudaGetSymbolAddress((void**)&o,   g_o);
    cudaGetSymbolAddress((void**)&h,   g_h);
    cudaGetSymbolAddress((void**)&hn,  g_hn);
    cudaGetSymbolAddress((void**)&gt,  g_gt);
    cudaGetSymbolAddress((void**)&ut,  g_ut);
    cudaGetSymbolAddress((void**)&act, g_act);
    cudaGetSymbolAddress((void**)&twt, g_twt);
    cudaGetSymbolAddress((void**)&cnt, g_cnt);
    cudaGetSymbolAddress((void**)&tok, g_tok);

    // ---- MLA attention ----
    rms_k<<<TK, 256>>>(x, ln1, xi, HH);
    gemm64(xi, HH, q_down, 128, cq, 128, TK, 128, HH);
    gemm64(xi, HH, kv_down, 128, ckv, 128, TK, 128, HH);
    rms_k<<<TK, 128>>>(cq, q_norm, cq, 128);
    rms_k<<<TK, 128>>>(ckv, kv_norm, ckv, 128);
    gemm128(cq, 128, w_uq, 512, qn, 512, TK, 512, 128, nullptr, 0, 0, nullptr, nullptr, 0, nullptr);
    gemm128(cq, 128, w_qr, 512, qr, 512, TK, 512, 128, nullptr, 0, 0, nullptr, nullptr, 0, nullptr);
    gemm128(ckv, 128, w_uk, 512, kn, 512, TK, 512, 128, nullptr, 0, 0, nullptr, nullptr, 0, nullptr);
    gemm128(ckv, 128, w_ur, 512, kr, 512, TK, 512, 128, nullptr, 0, 0, nullptr, nullptr, 0, nullptr);
    gemm128(ckv, 128, w_uv, 1024, vx, 1024, TK, 1024, 128, nullptr, 0, 0, nullptr, nullptr, 0, nullptr);
    assemble_k<<<(BHN * SS * 64) / 256, 256>>>(qn, qr, kn, kr, vx, cosp, sinp, q, k, v);

    cudaFuncSetAttribute(flash_k, cudaFuncAttributeMaxDynamicSharedMemorySize, 65792);
    flash_k<<<dim3(SS / 64, BHN), 256, 65792>>>(q, k, v, maskp, o);

    gemm128(o, HH, o_proj, HH, h, HH, TK, HH, HH, nullptr, 0, 0, nullptr, x, 0, nullptr);  // h = x + o@Wo

    // ---- MoE ----
    rms_k<<<TK, 256>>>(h, ln2, hn, HH);
    cudaMemsetAsync(cnt, 0, NE * sizeof(int), 0);
    router_k<<<TK, 128>>>(hn, router_w, router_b, cnt, tok, twt);
    cudaMemcpyAsync(out, h, (size_t)TK * HH * sizeof(float), cudaMemcpyDeviceToDevice, 0);

    // shared experts (dense)
    for (int e = 0; e < 2; e++) {
        gemm128(hn, HH, sh_gate + (size_t)e * HH * II, II, gt, II, TK, II, HH,
                nullptr, 0, 0, nullptr, nullptr, 0, nullptr);
        gemm128(hn, HH, sh_up + (size_t)e * HH * II, II, ut, II, TK, II, HH,
                nullptr, 0, 0, nullptr, nullptr, 0, nullptr);
        silu_mul_k<<<(TK * II + 255) / 256, 256>>>(gt, ut, act, TK * II);
        gemm128(act, II, sh_down + (size_t)e * II * HH, HH, out, HH, TK, HH, II,
                nullptr, 0, 0, nullptr, nullptr, 1, nullptr);
    }
    // routed experts (sparse: only assigned tokens)
    for (int e = 0; e < NE; e++) {
        const int* idx = tok + e * TK;
        gemm128(hn, HH, r_gate + (size_t)e * HH * II, II, gt, II, TK, II, HH,
                idx, 1, 0, nullptr, nullptr, 0, cnt + e);
        gemm128(hn, HH, r_up + (size_t)e * HH * II, II, ut, II, TK, II, HH,
                idx, 1, 0, nullptr, nullptr, 0, cnt + e);
        silu_mul_k<<<(TK * II + 255) / 256, 256>>>(gt, ut, act, TK * II);
        gemm128(act, II, r_down + (size_t)e * II * HH, HH, out, HH, TK, HH, II,
                idx, 0, 1, twt + e * TK, nullptr, 0, cnt + e);
    }
    usage_k<<<1, NE>>>(cnt, out + (size_t)TK * HH);
}

// round 4
// speedup vs baseline: 2.3079x; 2.3079x over previous
#include <cuda_runtime.h>
#include <math.h>
#include <stdint.h>

// ---------------- problem constants ----------------
#define TK   4096      // tokens = B*S
#define HH   1024      // hidden
#define SS   2048      // seq len
#define NHH  16        // heads
#define BHN  32        // B*NH
#define II   384       // expert intermediate
#define NE   8         // routed experts

// ---------------- scratch (device globals; no allocation allowed) ----------------
__device__ float g_xi [TK*HH];
__device__ float g_cq [TK*128];
__device__ float g_ckv[TK*128];
__device__ float g_qn [TK*512];
__device__ float g_qr [TK*512];
__device__ float g_kn [TK*512];
__device__ float g_kr [TK*512];
__device__ float g_vx [TK*HH];
__device__ float g_q  [TK*HH];   // [bh][s][64]
__device__ float g_k  [TK*HH];
__device__ float g_v  [TK*HH];
__device__ float g_o  [TK*HH];   // [b][s][h*64+d]
__device__ float g_h  [TK*HH];
__device__ float g_hn [TK*HH];
__device__ float g_gt [NE*TK*II];
__device__ float g_ut [NE*TK*II];
__device__ float g_act[NE*TK*II];
__device__ int   g_cnt[NE];
__device__ int   g_tok[NE*TK];
__device__ float g_twt[NE*TK];

// ---------------- tf32 helpers ----------------
__device__ __forceinline__ uint32_t f2tf(float f) {
    uint32_t r;
    asm("cvt.rna.tf32.f32 %0, %1;" : "=r"(r) : "f"(f));
    return r;
}
__device__ __forceinline__ void mma8(float* c, const uint32_t* a, const uint32_t* b) {
    asm volatile(
        "mma.sync.aligned.m16n8k8.row.col.f32.tf32.tf32.f32 "
        "{%0,%1,%2,%3}, {%4,%5,%6,%7}, {%8,%9}, {%0,%1,%2,%3};\n"
        : "+f"(c[0]), "+f"(c[1]), "+f"(c[2]), "+f"(c[3])
        : "r"(a[0]), "r"(a[1]), "r"(a[2]), "r"(a[3]), "r"(b[0]), "r"(b[1]));
}

// ---------------- tensor-core GEMM ----------------
// C[m][n] = sum_k A[m][k]*B[k][n]   (per blockIdx.z "expert" e)
//   A += e*eastride; B += e*ebstride; C += e*ecstride
//   tokBase: per-expert gather/scatter row index list (stride TK)
//   wtBase : per-expert per-row scale (stride TK) -> atomicAdd(C, w*acc)
//   accAtomic: atomicAdd(C, acc)
//   addsrc : C = acc + addsrc[m]
//   cntBase: per-expert dynamic M
// PREC=1 single tf32, PREC=3 split-precision 3xTF32 (fp32-quality).
template<int PREC>
__global__ void __launch_bounds__(256) gemm_tc(
    const float* __restrict__ A, int lda, size_t eastride,
    const float* __restrict__ B, int ldb, size_t ebstride,
    float* __restrict__ C, int ldc, size_t ecstride,
    int M, int N, int K,
    const int* __restrict__ tokBase, int gatherA, int scatterC,
    const float* __restrict__ wtBase,
    const float* __restrict__ addsrc, int accAtomic,
    const int* __restrict__ cntBase)
{
    constexpr int NC = (PREC == 3) ? 2 : 1;       // smem copies (hi, lo)
    constexpr int NPASS = (PREC == 3) ? 3 : 1;
    constexpr int ASTR = 20;                      // A smem row stride (u32)
    constexpr int BSTR = 136;                     // B smem row stride (u32)
    constexpr int ASZ = 128 * ASTR;               // 2560
    constexpr int BSZ = 16 * BSTR;                // 2176

    extern __shared__ uint32_t smem_u[];
    uint32_t* As = smem_u;                        // [2][NC][ASZ]
    uint32_t* Bs = smem_u + 2 * NC * ASZ;         // [2][NC][BSZ]
    int* idxs = (int*)(smem_u + 2 * NC * (ASZ + BSZ));

    const int e = blockIdx.z;
    A += (size_t)e * eastride;
    B += (size_t)e * ebstride;
    C += (size_t)e * ecstride;
    const int* idx = tokBase ? tokBase + (size_t)e * TK : nullptr;
    const float* wt = wtBase ? wtBase + (size_t)e * TK : nullptr;
    const int effM = cntBase ? cntBase[e] : M;

    const int m0 = blockIdx.y * 128;
    const int n0 = blockIdx.x * 128;
    if (m0 >= effM) return;

    const int tid = threadIdx.x;
    if (idx) {
        for (int i = tid; i < 128; i += 256) {
            int m = m0 + i;
            idxs[i] = (m < effM) ? idx[m] : 0;
        }
    }
    __syncthreads();

    // tile loader
    auto loadTile = [&](int buf, int kt) {
        uint32_t* Ad = As + buf * NC * ASZ;
        #pragma unroll
        for (int i = 0; i < 8; i++) {
            int flat = tid + i * 256;
            int m = flat >> 4, k = flat & 15;
            float v = 0.f;
            int mg = m0 + m;
            if (mg < effM) {
                int row = gatherA ? idxs[m] : mg;
                v = A[(size_t)row * lda + kt + k];
            }
            uint32_t hi = f2tf(v);
            Ad[m * ASTR + k] = hi;
            if (NC == 2) Ad[ASZ + m * ASTR + k] = f2tf(v - __uint_as_float(hi));
        }
        uint32_t* Bd = Bs + buf * NC * BSZ;
        #pragma unroll
        for (int i = 0; i < 8; i++) {
            int flat = tid + i * 256;
            int n = flat & 127, k = flat >> 7;
            float v = B[(size_t)(kt + k) * ldb + n0 + n];
            uint32_t hi = f2tf(v);
            Bd[k * BSTR + n] = hi;
            if (NC == 2) Bd[BSZ + k * BSTR + n] = f2tf(v - __uint_as_float(hi));
        }
    };

    const int lane = tid & 31, wid = tid >> 5;
    const int wm = (wid >> 2) * 64;    // warp M offset (0/64)
    const int wn = (wid & 3) * 32;     // warp N offset (0/32/64/96)
    const int g = lane >> 2, c = lane & 3;

    float acc[4][4][4];
    #pragma unroll
    for (int i = 0; i < 4; i++)
        #pragma unroll
        for (int j = 0; j < 4; j++)
            #pragma unroll
            for (int r = 0; r < 4; r++) acc[i][j][r] = 0.f;

    loadTile(0, 0);
    __syncthreads();

    const int nkt = K >> 4;
    for (int t = 0; t < nkt; t++) {
        int cur = t & 1;
        if (t + 1 < nkt) loadTile(cur ^ 1, (t + 1) << 4);

        #pragma unroll
        for (int pass = 0; pass < NPASS; pass++) {
            const uint32_t* Ab = As + cur * NC * ASZ + ((pass == 2) ? ASZ : 0);
            const uint32_t* Bb = Bs + cur * NC * BSZ + ((pass == 1) ? BSZ : 0);
            #pragma unroll
            for (int ks = 0; ks < 16; ks += 8) {
                uint32_t af[4][4];
                #pragma unroll
                for (int mt = 0; mt < 4; mt++) {
                    int mb = wm + mt * 16;
                    af[mt][0] = Ab[(mb + g) * ASTR + ks + c];
                    af[mt][1] = Ab[(mb + g + 8) * ASTR + ks + c];
                    af[mt][2] = Ab[(mb + g) * ASTR + ks + c + 4];
                    af[mt][3] = Ab[(mb + g + 8) * ASTR + ks + c + 4];
                }
                uint32_t bf[4][2];
                #pragma unroll
                for (int nt = 0; nt < 4; nt++) {
                    int nb = wn + nt * 8;
                    bf[nt][0] = Bb[(ks + c) * BSTR + nb + g];
                    bf[nt][1] = Bb[(ks + c + 4) * BSTR + nb + g];
                }
                #pragma unroll
                for (int mt = 0; mt < 4; mt++)
                    #pragma unroll
                    for (int nt = 0; nt < 4; nt++)
                        mma8(acc[mt][nt], af[mt], bf[nt]);
            }
        }
        __syncthreads();
    }

    // epilogue
    #pragma unroll
    for (int mt = 0; mt < 4; mt++) {
        #pragma unroll
        for (int h2 = 0; h2 < 2; h2++) {
            int ml = wm + mt * 16 + g + h2 * 8;
            int m = m0 + ml;
            if (m >= effM) continue;
            int crow = scatterC ? idxs[ml] : m;
            float sc = wt ? wt[m] : 1.f;
            #pragma unroll
            for (int nt = 0; nt < 4; nt++) {
                int ncol = n0 + wn + nt * 8 + c * 2;
                float v0 = acc[mt][nt][h2 * 2 + 0];
                float v1 = acc[mt][nt][h2 * 2 + 1];
                float* cp = C + (size_t)crow * ldc + ncol;
                if (wt) {
                    atomicAdd(cp, sc * v0); atomicAdd(cp + 1, sc * v1);
                } else if (accAtomic) {
                    atomicAdd(cp, v0); atomicAdd(cp + 1, v1);
                } else if (addsrc) {
                    const float* ap = addsrc + (size_t)m * ldc + ncol;
                    cp[0] = v0 + ap[0]; cp[1] = v1 + ap[1];
                } else {
                    cp[0] = v0; cp[1] = v1;
                }
            }
        }
    }
}

// ---------------- RMSNorm (one block per row; in-place safe) ----------------
__global__ void rms_k(const float* __restrict__ x, const float* __restrict__ w,
                      float* __restrict__ y, int D)
{
    int t = blockIdx.x;
    const float* xr = x + (size_t)t * D;
    float* yr = y + (size_t)t * D;
    float ss = 0.f;
    for (int k = threadIdx.x; k < D; k += blockDim.x) { float v = xr[k]; ss += v * v; }
    __shared__ float sh[32];
    int lane = threadIdx.x & 31, wid = threadIdx.x >> 5;
    #pragma unroll
    for (int o = 16; o > 0; o >>= 1) ss += __shfl_xor_sync(0xffffffffu, ss, o);
    if (lane == 0) sh[wid] = ss;
    __syncthreads();
    if (threadIdx.x == 0) {
        float tot = 0.f;
        int nw = blockDim.x >> 5;
        for (int i = 0; i < nw; i++) tot += sh[i];
        sh[0] = tot;
    }
    __syncthreads();
    float r = rsqrtf(sh[0] / (float)D + 1e-5f);
    for (int k = threadIdx.x; k < D; k += blockDim.x) yr[k] = w[k] * xr[k] * r;
}

// ---------------- assemble Q/K/V with RoPE ----------------
__global__ void assemble_k(const float* __restrict__ qn, const float* __restrict__ qr,
                           const float* __restrict__ kn, const float* __restrict__ kr,
                           const float* __restrict__ vx,
                           const float* __restrict__ cosp, const float* __restrict__ sinp,
                           float* __restrict__ Q, float* __restrict__ K, float* __restrict__ V)
{
    int idx = blockIdx.x * blockDim.x + threadIdx.x;
    if (idx >= BHN * SS * 64) return;
    int d  = idx & 63;
    int s  = (idx >> 6) & (SS - 1);
    int bh = idx >> 17;
    int b  = bh >> 4, h = bh & 15;
    int t  = b * SS + s;
    float qv, kv;
    if (d < 32) {
        qv = qn[(size_t)t * 512 + h * 32 + d];
        kv = kn[(size_t)t * 512 + h * 32 + d];
    } else {
        int j = d - 32;
        float cc = cosp[s * 32 + j];
        float sn = sinp[s * 32 + j];
        float q1 = qr[(size_t)t * 512 + h * 32 + j];
        float q2 = (j < 16) ? -qr[(size_t)t * 512 + h * 32 + j + 16]
                            :  qr[(size_t)t * 512 + h * 32 + j - 16];
        qv = q1 * cc + q2 * sn;
        float k1 = kr[(size_t)t * 512 + h * 32 + j];
        float k2 = (j < 16) ? -kr[(size_t)t * 512 + h * 32 + j + 16]
                            :  kr[(size_t)t * 512 + h * 32 + j - 16];
        kv = k1 * cc + k2 * sn;
    }
    Q[idx] = qv;
    K[idx] = kv;
    V[idx] = vx[(size_t)t * HH + h * 64 + d];
}

// ---------------- flash attention (fp32, non-causal, +mask) ----------------
__global__ void __launch_bounds__(256) flash_k(
    const float* __restrict__ Q, const float* __restrict__ Kg,
    const float* __restrict__ Vg, const float* __restrict__ maskp,
    float* __restrict__ O)
{
    extern __shared__ float sm[];
    float* Qt = sm;              // [64][64]  Qt[d][m]
    float* Kt = sm + 4096;       // [64][64]  Kt[d][n]
    float* Vs = sm + 8192;       // [64][64]  Vs[n][d]
    float* Pt = sm + 12288;      // [64][65]  Pt[n][m]

    const int bh = blockIdx.y;
    const int q0 = blockIdx.x * 64;
    const int b  = bh >> 4, hh = bh & 15;
    const float* Qb = Q  + (size_t)bh * SS * 64;
    const float* Kb = Kg + (size_t)bh * SS * 64;
    const float* Vb = Vg + (size_t)bh * SS * 64;

    const int tid = threadIdx.x;
    const int tx = tid & 15, ty = tid >> 4;
    const int lr  = tid >> 2;
    const int ld0 = (tid & 3) * 16;

    {
        const float4* src = (const float4*)(Qb + (size_t)(q0 + lr) * 64 + ld0);
        #pragma unroll
        for (int i = 0; i < 4; i++) {
            float4 v = src[i];
            int d = ld0 + i * 4;
            Qt[(d + 0) * 64 + lr] = v.x; Qt[(d + 1) * 64 + lr] = v.y;
            Qt[(d + 2) * 64 + lr] = v.z; Qt[(d + 3) * 64 + lr] = v.w;
        }
    }
    float acc[4][4];
    float mrow[4], lrow[4];
    #pragma unroll
    for (int i = 0; i < 4; i++) {
        mrow[i] = -1e30f; lrow[i] = 0.f;
        #pragma unroll
        for (int j = 0; j < 4; j++) acc[i][j] = 0.f;
    }
    __syncthreads();

    for (int k0 = 0; k0 < SS; k0 += 64) {
        {
            const float4* ks   = (const float4*)(Kb + (size_t)(k0 + lr) * 64 + ld0);
            const float4* vsrc = (const float4*)(Vb + (size_t)(k0 + lr) * 64 + ld0);
            float4* vd = (float4*)(Vs + lr * 64 + ld0);
            #pragma unroll
            for (int i = 0; i < 4; i++) {
                float4 kv = ks[i];
                int d = ld0 + i * 4;
                Kt[(d + 0) * 64 + lr] = kv.x; Kt[(d + 1) * 64 + lr] = kv.y;
                Kt[(d + 2) * 64 + lr] = kv.z; Kt[(d + 3) * 64 + lr] = kv.w;
                vd[i] = vsrc[i];
            }
        }
        __syncthreads();

        float s[4][4];
        #pragma unroll
        for (int i = 0; i < 4; i++)
            #pragma unroll
            for (int j = 0; j < 4; j++) s[i][j] = 0.f;

        #pragma unroll 8
        for (int d = 0; d < 64; d++) {
            float a[4], bb[4];
            #pragma unroll
            for (int i = 0; i < 4; i++) a[i]  = Qt[d * 64 + ty * 4 + i];
            #pragma unroll
            for (int j = 0; j < 4; j++) bb[j] = Kt[d * 64 + tx * 4 + j];
            #pragma unroll
            for (int i = 0; i < 4; i++)
                #pragma unroll
                for (int j = 0; j < 4; j++) s[i][j] += a[i] * bb[j];
        }
        #pragma unroll
        for (int i = 0; i < 4; i++) {
            const float* mp = maskp + (size_t)(q0 + ty * 4 + i) * SS + (k0 + tx * 4);
            #pragma unroll
            for (int j = 0; j < 4; j++) s[i][j] = s[i][j] * 0.125f + mp[j];
        }
        float rmax[4];
        #pragma unroll
        for (int i = 0; i < 4; i++)
            rmax[i] = fmaxf(fmaxf(s[i][0], s[i][1]), fmaxf(s[i][2], s[i][3]));
        #pragma unroll
        for (int o = 1; o < 16; o <<= 1)
            #pragma unroll
            for (int i = 0; i < 4; i++)
                rmax[i] = fmaxf(rmax[i], __shfl_xor_sync(0xffffffffu, rmax[i], o));

        #pragma unroll
        for (int i = 0; i < 4; i++) {
            float mnew = fmaxf(mrow[i], rmax[i]);
            float corr = __expf(mrow[i] - mnew);
            float rs = 0.f;
            #pragma unroll
            for (int j = 0; j < 4; j++) { s[i][j] = __expf(s[i][j] - mnew); rs += s[i][j]; }
            #pragma unroll
            for (int o = 1; o < 16; o <<= 1) rs += __shfl_xor_sync(0xffffffffu, rs, o);
            mrow[i] = mnew;
            lrow[i] = lrow[i] * corr + rs;
            #pragma unroll
            for (int j = 0; j < 4; j++) acc[i][j] *= corr;
        }
        #pragma unroll
        for (int i = 0; i < 4; i++)
            #pragma unroll
            for (int j = 0; j < 4; j++)
                Pt[(tx * 4 + j) * 65 + ty * 4 + i] = s[i][j];
        __syncthreads();

        #pragma unroll 8
        for (int n = 0; n < 64; n++) {
            float a[4], bb[4];
            #pragma unroll
            for (int i = 0; i < 4; i++) a[i]  = Pt[n * 65 + ty * 4 + i];
            #pragma unroll
            for (int j = 0; j < 4; j++) bb[j] = Vs[n * 64 + tx * 4 + j];
            #pragma unroll
            for (int i = 0; i < 4; i++)
                #pragma unroll
                for (int j = 0; j < 4; j++) acc[i][j] += a[i] * bb[j];
        }
        __syncthreads();
    }

    #pragma unroll
    for (int i = 0; i < 4; i++) {
        float inv = 1.f / lrow[i];
        int qrow = q0 + ty * 4 + i;
        float* op = O + ((size_t)(b * SS + qrow)) * HH + hh * 64 + tx * 4;
        #pragma unroll
        for (int j = 0; j < 4; j++) op[j] = acc[i][j] * inv;
    }
}

// ---------------- router ----------------
__global__ void router_k(const float* __restrict__ hn, const float* __restrict__ rw,
                         const float* __restrict__ rb,
                         int* __restrict__ cnt, int* __restrict__ tok, float* __restrict__ twt)
{
    int t = blockIdx.x;
    __shared__ float red[128][NE];
    float accv[NE];
    #pragma unroll
    for (int e = 0; e < NE; e++) accv[e] = 0.f;
    const float* xr = hn + (size_t)t * HH;
    for (int k = threadIdx.x; k < HH; k += 128) {
        float xv = xr[k];
        const float* w = rw + (size_t)k * NE;
        #pragma unroll
        for (int e = 0; e < NE; e++) accv[e] += xv * w[e];
    }
    #pragma unroll
    for (int e = 0; e < NE; e++) red[threadIdx.x][e] = accv[e];
    __syncthreads();
    for (int s = 64; s > 0; s >>= 1) {
        if (threadIdx.x < s)
            #pragma unroll
            for (int e = 0; e < NE; e++) red[threadIdx.x][e] += red[threadIdx.x + s][e];
        __syncthreads();
    }
    if (threadIdx.x == 0) {
        float p[NE];
        #pragma unroll
        for (int e = 0; e < NE; e++) {
            float lg = red[0][e] + rb[e];
            p[e] = 1.f / (1.f + expf(-lg));
        }
        int e1 = 0;
        for (int e = 1; e < NE; e++) if (p[e] > p[e1]) e1 = e;
        int e2 = -1;
        for (int e = 0; e < NE; e++) if (e != e1 && (e2 < 0 || p[e] > p[e2])) e2 = e;
        float s2 = p[e1] + p[e2];
        float w1 = p[e1] / s2, w2 = p[e2] / s2;
        int a = atomicAdd(&cnt[e1], 1); tok[e1 * TK + a] = t; twt[e1 * TK + a] = w1;
        int b = atomicAdd(&cnt[e2], 1); tok[e2 * TK + b] = t; twt[e2 * TK + b] = w2;
    }
}

__global__ void silu_mul_k(const float* __restrict__ g, const float* __restrict__ u,
                           float* __restrict__ y, int n)
{
    int i = blockIdx.x * 256 + threadIdx.x;
    if (i < n) {
        float gv = g[i];
        y[i] = (gv / (1.f + expf(-gv))) * u[i];
    }
}

__global__ void usage_k(const int* __restrict__ cnt, float* __restrict__ out)
{
    int e = threadIdx.x;
    if (e < NE) out[e] = (float)cnt[e];
}

// ---------------- host-side GEMM dispatch ----------------
static const int SMEM1 = (2 * 1 * (2560 + 2176) + 128) * 4;   // 38400
static const int SMEM3 = (2 * 2 * (2560 + 2176) + 128) * 4;   // 76288

static void G(int prec,
              const float* A, int lda, size_t eas,
              const float* B, int ldb, size_t ebs,
              float* C, int ldc, size_t ecs,
              int M, int N, int K, int nz,
              const int* tokB, int ga, int sc,
              const float* wtB, const float* adds, int accA,
              const int* cntB)
{
    dim3 grid(N / 128, (M + 127) / 128, nz);
    if (prec == 3)
        gemm_tc<3><<<grid, 256, SMEM3>>>(A, lda, eas, B, ldb, ebs, C, ldc, ecs,
                                         M, N, K, tokB, ga, sc, wtB, adds, accA, cntB);
    else
        gemm_tc<1><<<grid, 256, SMEM1>>>(A, lda, eas, B, ldb, ebs, C, ldc, ecs,
                                         M, N, K, tokB, ga, sc, wtB, adds, accA, cntB);
}

extern "C" void kernel_launch(void* const* d_in, const int* in_sizes, int n_in,
                              void* d_out, int out_size)
{
    const float* x        = (const float*)d_in[0];
    const float* cosp     = (const float*)d_in[1];
    const float* sinp     = (const float*)d_in[2];
    const float* maskp    = (const float*)d_in[3];
    const float* ln1      = (const float*)d_in[4];
    const float* ln2      = (const float*)d_in[5];
    const float* kv_down  = (const float*)d_in[6];
    const float* kv_norm  = (const float*)d_in[7];
    const float* w_uk     = (const float*)d_in[8];
    const float* w_ur     = (const float*)d_in[9];
    const float* w_uv     = (const float*)d_in[10];
    const float* q_down   = (const float*)d_in[11];
    const float* q_norm   = (const float*)d_in[12];
    const float* w_uq     = (const float*)d_in[13];
    const float* w_qr     = (const float*)d_in[14];
    const float* o_proj   = (const float*)d_in[15];
    const float* sh_gate  = (const float*)d_in[16];
    const float* sh_up    = (const float*)d_in[17];
    const float* sh_down  = (const float*)d_in[18];
    const float* r_gate   = (const float*)d_in[19];
    const float* r_up     = (const float*)d_in[20];
    const float* r_down   = (const float*)d_in[21];
    const float* router_w = (const float*)d_in[22];
    const float* router_b = (const float*)d_in[23];
    float* out = (float*)d_out;

    float *xi, *cq, *ckv, *qn, *qr, *kn, *kr, *vx, *q, *k, *v, *o, *h, *hn, *gt, *ut, *act, *twt;
    int *cnt, *tok;
    cudaGetSymbolAddress((void**)&xi,  g_xi);
    cudaGetSymbolAddress((void**)&cq,  g_cq);
    cudaGetSymbolAddress((void**)&ckv, g_ckv);
    cudaGetSymbolAddress((void**)&qn,  g_qn);
    cudaGetSymbolAddress((void**)&qr,  g_qr);
    cudaGetSymbolAddress((void**)&kn,  g_kn);
    cudaGetSymbolAddress((void**)&kr,  g_kr);
    cudaGetSymbolAddress((void**)&vx,  g_vx);
    cudaGetSymbolAddress((void**)&q,   g_q);
    cudaGetSymbolAddress((void**)&k,   g_k);
    cudaGetSymbolAddress((void**)&v,   g_v);
    cudaGetSymbolAddress((void**)&o,   g_o);
    cudaGetSymbolAddress((void**)&h,   g_h);
    cudaGetSymbolAddress((void**)&hn,  g_hn);
    cudaGetSymbolAddress((void**)&gt,  g_gt);
    cudaGetSymbolAddress((void**)&ut,  g_ut);
    cudaGetSymbolAddress((void**)&act, g_act);
    cudaGetSymbolAddress((void**)&twt, g_twt);
    cudaGetSymbolAddress((void**)&cnt, g_cnt);
    cudaGetSymbolAddress((void**)&tok, g_tok);

    cudaFuncSetAttribute(gemm_tc<1>, cudaFuncAttributeMaxDynamicSharedMemorySize, SMEM1);
    cudaFuncSetAttribute(gemm_tc<3>, cudaFuncAttributeMaxDynamicSharedMemorySize, SMEM3);
    cudaFuncSetAttribute(flash_k,    cudaFuncAttributeMaxDynamicSharedMemorySize, 65792);

    const size_t TI = (size_t)TK * II;

    // ---- MLA attention (all projections 3xTF32: feeds the router downstream) ----
    rms_k<<<TK, 256>>>(x, ln1, xi, HH);
    G(3, xi, HH, 0,  q_down, 128, 0,  cq, 128, 0,  TK, 128, HH, 1,
      nullptr, 0, 0, nullptr, nullptr, 0, nullptr);
    G(3, xi, HH, 0,  kv_down, 128, 0,  ckv, 128, 0,  TK, 128, HH, 1,
      nullptr, 0, 0, nullptr, nullptr, 0, nullptr);
    rms_k<<<TK, 128>>>(cq, q_norm, cq, 128);
    rms_k<<<TK, 128>>>(ckv, kv_norm, ckv, 128);
    G(3, cq, 128, 0,  w_uq, 512, 0,  qn, 512, 0,  TK, 512, 128, 1,
      nullptr, 0, 0, nullptr, nullptr, 0, nullptr);
    G(3, cq, 128, 0,  w_qr, 512, 0,  qr, 512, 0,  TK, 512, 128, 1,
      nullptr, 0, 0, nullptr, nullptr, 0, nullptr);
    G(3, ckv, 128, 0,  w_uk, 512, 0,  kn, 512, 0,  TK, 512, 128, 1,
      nullptr, 0, 0, nullptr, nullptr, 0, nullptr);
    G(3, ckv, 128, 0,  w_ur, 512, 0,  kr, 512, 0,  TK, 512, 128, 1,
      nullptr, 0, 0, nullptr, nullptr, 0, nullptr);
    G(3, ckv, 128, 0,  w_uv, 1024, 0,  vx, 1024, 0,  TK, 1024, 128, 1,
      nullptr, 0, 0, nullptr, nullptr, 0, nullptr);
    assemble_k<<<(BHN * SS * 64) / 256, 256>>>(qn, qr, kn, kr, vx, cosp, sinp, q, k, v);

    flash_k<<<dim3(SS / 64, BHN), 256, 65792>>>(q, k, v, maskp, o);

    G(3, o, HH, 0,  o_proj, HH, 0,  h, HH, 0,  TK, HH, HH, 1,
      nullptr, 0, 0, nullptr, x, 0, nullptr);   // h = x + o@Wo

    // ---- MoE ----
    rms_k<<<TK, 256>>>(h, ln2, hn, HH);
    cudaMemsetAsync(cnt, 0, NE * sizeof(int), 0);
    router_k<<<TK, 128>>>(hn, router_w, router_b, cnt, tok, twt);
    cudaMemcpyAsync(out, h, (size_t)TK * HH * sizeof(float), cudaMemcpyDeviceToDevice, 0);

    // shared experts (dense, batched z=2)
    G(1, hn, HH, 0,  sh_gate, II, (size_t)HH * II,  gt, II, TI,  TK, II, HH, 2,
      nullptr, 0, 0, nullptr, nullptr, 0, nullptr);
    G(1, hn, HH, 0,  sh_up, II, (size_t)HH * II,  ut, II, TI,  TK, II, HH, 2,
      nullptr, 0, 0, nullptr, nullptr, 0, nullptr);
    silu_mul_k<<<(2 * (int)TI + 255) / 256, 256>>>(gt, ut, act, 2 * (int)TI);
    G(1, act, II, TI,  sh_down, HH, (size_t)II * HH,  out, HH, 0,  TK, HH, II, 2,
      nullptr, 0, 0, nullptr, nullptr, 1, nullptr);

    // routed experts (sparse compact rows, batched z=8)
    G(1, hn, HH, 0,  r_gate, II, (size_t)HH * II,  gt, II, TI,  TK, II, HH, NE,
      tok, 1, 0, nullptr, nullptr, 0, cnt);
    G(1, hn, HH, 0,  r_up, II, (size_t)HH * II,  ut, II, TI,  TK, II, HH, NE,
      tok, 1, 0, nullptr, nullptr, 0, cnt);
    silu_mul_k<<<(NE * (int)TI + 255) / 256, 256>>>(gt, ut, act, NE * (int)TI);
    G(1, act, II, TI,  r_down, HH, (size_t)II * HH,  out, HH, 0,  TK, HH, II, NE,
      tok, 0, 1, twt, nullptr, 0, cnt);

    usage_k<<<1, NE>>>(cnt, out + (size_t)TK * HH);
}

// round 5
// speedup vs baseline: 2.7387x; 1.1866x over previous
#include <cuda_runtime.h>
#include <math.h>
#include <stdint.h>

// ---------------- problem constants ----------------
#define TK   4096      // tokens = B*S
#define HH   1024      // hidden
#define SS   2048      // seq len
#define NHH  16        // heads
#define BHN  32        // B*NH
#define II   384       // expert intermediate
#define NE   8         // routed experts

// ---------------- scratch (device globals; no allocation allowed) ----------------
__device__ float g_xi [TK*HH];
__device__ float g_cq [TK*128];
__device__ float g_ckv[TK*128];
__device__ float g_qn [TK*512];
__device__ float g_qr [TK*512];
__device__ float g_kn [TK*512];
__device__ float g_kr [TK*512];
__device__ float g_vx [TK*HH];
__device__ float g_q  [TK*HH];   // [bh][s][64]
__device__ float g_k  [TK*HH];
__device__ float g_o  [TK*HH];   // [b][s][h*64+d]
__device__ float g_h  [TK*HH];
__device__ float g_hn [TK*HH];
__device__ float g_gt [NE*TK*II];
__device__ float g_ut [NE*TK*II];
__device__ float g_act[NE*TK*II];
__device__ int   g_cnt[NE];
__device__ int   g_tok[NE*TK];
__device__ float g_twt[NE*TK];

// ---------------- tf32 helpers ----------------
__device__ __forceinline__ uint32_t f2tf(float f) {
    uint32_t r;
    asm("cvt.rna.tf32.f32 %0, %1;" : "=r"(r) : "f"(f));
    return r;
}
__device__ __forceinline__ void mma8(float* c, const uint32_t* a, const uint32_t* b) {
    asm volatile(
        "mma.sync.aligned.m16n8k8.row.col.f32.tf32.tf32.f32 "
        "{%0,%1,%2,%3}, {%4,%5,%6,%7}, {%8,%9}, {%0,%1,%2,%3};\n"
        : "+f"(c[0]), "+f"(c[1]), "+f"(c[2]), "+f"(c[3])
        : "r"(a[0]), "r"(a[1]), "r"(a[2]), "r"(a[3]), "r"(b[0]), "r"(b[1]));
}

// ---------------- tensor-core GEMM ----------------
template<int PREC>
__global__ void __launch_bounds__(256) gemm_tc(
    const float* __restrict__ A, int lda, size_t eastride,
    const float* __restrict__ B, int ldb, size_t ebstride,
    float* __restrict__ C, int ldc, size_t ecstride,
    int M, int N, int K,
    const int* __restrict__ tokBase, int gatherA, int scatterC,
    const float* __restrict__ wtBase,
    const float* __restrict__ addsrc, int accAtomic,
    const int* __restrict__ cntBase)
{
    constexpr int NC = (PREC == 3) ? 2 : 1;
    constexpr int NPASS = (PREC == 3) ? 3 : 1;
    constexpr int ASTR = 20;
    constexpr int BSTR = 136;
    constexpr int ASZ = 128 * ASTR;
    constexpr int BSZ = 16 * BSTR;

    extern __shared__ uint32_t smem_u[];
    uint32_t* As = smem_u;
    uint32_t* Bs = smem_u + 2 * NC * ASZ;
    int* idxs = (int*)(smem_u + 2 * NC * (ASZ + BSZ));

    const int e = blockIdx.z;
    A += (size_t)e * eastride;
    B += (size_t)e * ebstride;
    C += (size_t)e * ecstride;
    const int* idx = tokBase ? tokBase + (size_t)e * TK : nullptr;
    const float* wt = wtBase ? wtBase + (size_t)e * TK : nullptr;
    const int effM = cntBase ? cntBase[e] : M;

    const int m0 = blockIdx.y * 128;
    const int n0 = blockIdx.x * 128;
    if (m0 >= effM) return;

    const int tid = threadIdx.x;
    if (idx) {
        for (int i = tid; i < 128; i += 256) {
            int m = m0 + i;
            idxs[i] = (m < effM) ? idx[m] : 0;
        }
    }
    __syncthreads();

    auto loadTile = [&](int buf, int kt) {
        uint32_t* Ad = As + buf * NC * ASZ;
        #pragma unroll
        for (int i = 0; i < 8; i++) {
            int flat = tid + i * 256;
            int m = flat >> 4, k = flat & 15;
            float v = 0.f;
            int mg = m0 + m;
            if (mg < effM) {
                int row = gatherA ? idxs[m] : mg;
                v = A[(size_t)row * lda + kt + k];
            }
            uint32_t hi = f2tf(v);
            Ad[m * ASTR + k] = hi;
            if (NC == 2) Ad[ASZ + m * ASTR + k] = f2tf(v - __uint_as_float(hi));
        }
        uint32_t* Bd = Bs + buf * NC * BSZ;
        #pragma unroll
        for (int i = 0; i < 8; i++) {
            int flat = tid + i * 256;
            int n = flat & 127, k = flat >> 7;
            float v = B[(size_t)(kt + k) * ldb + n0 + n];
            uint32_t hi = f2tf(v);
            Bd[k * BSTR + n] = hi;
            if (NC == 2) Bd[BSZ + k * BSTR + n] = f2tf(v - __uint_as_float(hi));
        }
    };

    const int lane = tid & 31, wid = tid >> 5;
    const int wm = (wid >> 2) * 64;
    const int wn = (wid & 3) * 32;
    const int g = lane >> 2, c = lane & 3;

    float acc[4][4][4];
    #pragma unroll
    for (int i = 0; i < 4; i++)
        #pragma unroll
        for (int j = 0; j < 4; j++)
            #pragma unroll
            for (int r = 0; r < 4; r++) acc[i][j][r] = 0.f;

    loadTile(0, 0);
    __syncthreads();

    const int nkt = K >> 4;
    for (int t = 0; t < nkt; t++) {
        int cur = t & 1;
        if (t + 1 < nkt) loadTile(cur ^ 1, (t + 1) << 4);

        #pragma unroll
        for (int pass = 0; pass < NPASS; pass++) {
            const uint32_t* Ab = As + cur * NC * ASZ + ((pass == 2) ? ASZ : 0);
            const uint32_t* Bb = Bs + cur * NC * BSZ + ((pass == 1) ? BSZ : 0);
            #pragma unroll
            for (int ks = 0; ks < 16; ks += 8) {
                uint32_t af[4][4];
                #pragma unroll
                for (int mt = 0; mt < 4; mt++) {
                    int mb = wm + mt * 16;
                    af[mt][0] = Ab[(mb + g) * ASTR + ks + c];
                    af[mt][1] = Ab[(mb + g + 8) * ASTR + ks + c];
                    af[mt][2] = Ab[(mb + g) * ASTR + ks + c + 4];
                    af[mt][3] = Ab[(mb + g + 8) * ASTR + ks + c + 4];
                }
                uint32_t bf[4][2];
                #pragma unroll
                for (int nt = 0; nt < 4; nt++) {
                    int nb = wn + nt * 8;
                    bf[nt][0] = Bb[(ks + c) * BSTR + nb + g];
                    bf[nt][1] = Bb[(ks + c + 4) * BSTR + nb + g];
                }
                #pragma unroll
                for (int mt = 0; mt < 4; mt++)
                    #pragma unroll
                    for (int nt = 0; nt < 4; nt++)
                        mma8(acc[mt][nt], af[mt], bf[nt]);
            }
        }
        __syncthreads();
    }

    #pragma unroll
    for (int mt = 0; mt < 4; mt++) {
        #pragma unroll
        for (int h2 = 0; h2 < 2; h2++) {
            int ml = wm + mt * 16 + g + h2 * 8;
            int m = m0 + ml;
            if (m >= effM) continue;
            int crow = scatterC ? idxs[ml] : m;
            float sc = wt ? wt[m] : 1.f;
            #pragma unroll
            for (int nt = 0; nt < 4; nt++) {
                int ncol = n0 + wn + nt * 8 + c * 2;
                float v0 = acc[mt][nt][h2 * 2 + 0];
                float v1 = acc[mt][nt][h2 * 2 + 1];
                float* cp = C + (size_t)crow * ldc + ncol;
                if (wt) {
                    atomicAdd(cp, sc * v0); atomicAdd(cp + 1, sc * v1);
                } else if (accAtomic) {
                    atomicAdd(cp, v0); atomicAdd(cp + 1, v1);
                } else if (addsrc) {
                    const float* ap = addsrc + (size_t)m * ldc + ncol;
                    cp[0] = v0 + ap[0]; cp[1] = v1 + ap[1];
                } else {
                    cp[0] = v0; cp[1] = v1;
                }
            }
        }
    }
}

// ---------------- RMSNorm ----------------
__global__ void rms_k(const float* __restrict__ x, const float* __restrict__ w,
                      float* __restrict__ y, int D)
{
    int t = blockIdx.x;
    const float* xr = x + (size_t)t * D;
    float* yr = y + (size_t)t * D;
    float ss = 0.f;
    for (int k = threadIdx.x; k < D; k += blockDim.x) { float v = xr[k]; ss += v * v; }
    __shared__ float sh[32];
    int lane = threadIdx.x & 31, wid = threadIdx.x >> 5;
    #pragma unroll
    for (int o = 16; o > 0; o >>= 1) ss += __shfl_xor_sync(0xffffffffu, ss, o);
    if (lane == 0) sh[wid] = ss;
    __syncthreads();
    if (threadIdx.x == 0) {
        float tot = 0.f;
        int nw = blockDim.x >> 5;
        for (int i = 0; i < nw; i++) tot += sh[i];
        sh[0] = tot;
    }
    __syncthreads();
    float r = rsqrtf(sh[0] / (float)D + 1e-5f);
    for (int k = threadIdx.x; k < D; k += blockDim.x) yr[k] = w[k] * xr[k] * r;
}

// ---------------- assemble Q/K with RoPE ----------------
__global__ void assemble_k(const float* __restrict__ qn, const float* __restrict__ qr,
                           const float* __restrict__ kn, const float* __restrict__ kr,
                           const float* __restrict__ cosp, const float* __restrict__ sinp,
                           float* __restrict__ Q, float* __restrict__ K)
{
    int idx = blockIdx.x * blockDim.x + threadIdx.x;
    if (idx >= BHN * SS * 64) return;
    int d  = idx & 63;
    int s  = (idx >> 6) & (SS - 1);
    int bh = idx >> 17;
    int b  = bh >> 4, h = bh & 15;
    int t  = b * SS + s;
    float qv, kv;
    if (d < 32) {
        qv = qn[(size_t)t * 512 + h * 32 + d];
        kv = kn[(size_t)t * 512 + h * 32 + d];
    } else {
        int j = d - 32;
        float cc = cosp[s * 32 + j];
        float sn = sinp[s * 32 + j];
        float q1 = qr[(size_t)t * 512 + h * 32 + j];
        float q2 = (j < 16) ? -qr[(size_t)t * 512 + h * 32 + j + 16]
                            :  qr[(size_t)t * 512 + h * 32 + j - 16];
        qv = q1 * cc + q2 * sn;
        float k1 = kr[(size_t)t * 512 + h * 32 + j];
        float k2 = (j < 16) ? -kr[(size_t)t * 512 + h * 32 + j + 16]
                            :  kr[(size_t)t * 512 + h * 32 + j - 16];
        kv = k1 * cc + k2 * sn;
    }
    Q[idx] = qv;
    K[idx] = kv;
}

// ---------------- flash attention, tf32 tensor cores ----------------
// BM=64 q rows, BN=64 keys/iter, 128 threads = 4 warps x 16 rows.
// smem: Qs[64][68] tf32, KP = Kt[64 d][72 key] overlaid with Ps[64 row][72 key], Vs[64 key][72 d]
#define QSTR 68
#define FSTR 72
__global__ void __launch_bounds__(128) flash_tc(
    const float* __restrict__ Q, const float* __restrict__ Kg,
    const float* __restrict__ Vx, const float* __restrict__ maskp,
    float* __restrict__ O)
{
    extern __shared__ uint32_t sm[];
    uint32_t* Qs = sm;                      // 64*68
    uint32_t* KP = sm + 64 * QSTR;          // 64*72  (Kt, then Ps)
    uint32_t* Vs = KP + 64 * FSTR;          // 64*72

    const int bh = blockIdx.y;
    const int q0 = blockIdx.x * 64;
    const int b  = bh >> 4, hh = bh & 15;
    const float* Qb = Q  + (size_t)bh * SS * 64;
    const float* Kb = Kg + (size_t)bh * SS * 64;
    const float* Vb = Vx + (size_t)b * SS * HH + hh * 64;   // row stride HH

    const int tid = threadIdx.x;
    const int w = tid >> 5, lane = tid & 31;
    const int g = lane >> 2, c = lane & 3;
    const int wrow = w * 16;

    const int lr  = tid & 63;          // load row 0..63
    const int lc0 = (tid >> 6) * 32;   // load col base 0 or 32

    { // load Q tile -> tf32
        const float4* src = (const float4*)(Qb + (size_t)(q0 + lr) * 64 + lc0);
        #pragma unroll
        for (int i = 0; i < 8; i++) {
            float4 v = src[i];
            uint32_t* d = Qs + lr * QSTR + lc0 + i * 4;
            d[0] = f2tf(v.x); d[1] = f2tf(v.y); d[2] = f2tf(v.z); d[3] = f2tf(v.w);
        }
    }

    float oacc[8][4];
    #pragma unroll
    for (int nf = 0; nf < 8; nf++)
        #pragma unroll
        for (int r = 0; r < 4; r++) oacc[nf][r] = 0.f;
    float m0 = -1e30f, m1 = -1e30f, l0 = 0.f, l1 = 0.f;

    const float* mr0 = maskp + (size_t)(q0 + wrow + g) * SS;
    const float* mr1 = mr0 + 8 * SS;

    for (int k0 = 0; k0 < SS; k0 += 64) {
        __syncthreads();   // prev PV done before overwriting KP/Vs
        { // load K (transposed -> Kt[d][key]) and V (direct -> Vs[key][d]), tf32
            const float4* ks = (const float4*)(Kb + (size_t)(k0 + lr) * 64 + lc0);
            const float4* vs = (const float4*)(Vb + (size_t)(k0 + lr) * HH + lc0);
            #pragma unroll
            for (int i = 0; i < 8; i++) {
                float4 kv = ks[i];
                int d = lc0 + i * 4;
                KP[(d + 0) * FSTR + lr] = f2tf(kv.x);
                KP[(d + 1) * FSTR + lr] = f2tf(kv.y);
                KP[(d + 2) * FSTR + lr] = f2tf(kv.z);
                KP[(d + 3) * FSTR + lr] = f2tf(kv.w);
                float4 vv = vs[i];
                uint32_t* vd = Vs + lr * FSTR + d;
                vd[0] = f2tf(vv.x); vd[1] = f2tf(vv.y); vd[2] = f2tf(vv.z); vd[3] = f2tf(vv.w);
            }
        }
        __syncthreads();

        // S = Q @ K^T  (per warp: 16 x 64)
        float sacc[8][4];
        #pragma unroll
        for (int nf = 0; nf < 8; nf++)
            #pragma unroll
            for (int r = 0; r < 4; r++) sacc[nf][r] = 0.f;
        #pragma unroll
        for (int ks = 0; ks < 64; ks += 8) {
            uint32_t af[4];
            af[0] = Qs[(wrow + g) * QSTR + ks + c];
            af[1] = Qs[(wrow + g + 8) * QSTR + ks + c];
            af[2] = Qs[(wrow + g) * QSTR + ks + c + 4];
            af[3] = Qs[(wrow + g + 8) * QSTR + ks + c + 4];
            #pragma unroll
            for (int nf = 0; nf < 8; nf++) {
                uint32_t bf[2];
                bf[0] = KP[(ks + c) * FSTR + nf * 8 + g];
                bf[1] = KP[(ks + c + 4) * FSTR + nf * 8 + g];
                mma8(sacc[nf], af, bf);
            }
        }

        // scale + mask + online softmax
        float mx0 = -1e30f, mx1 = -1e30f;
        #pragma unroll
        for (int nf = 0; nf < 8; nf++) {
            float2 mk0 = *(const float2*)(mr0 + k0 + nf * 8 + 2 * c);
            float2 mk1 = *(const float2*)(mr1 + k0 + nf * 8 + 2 * c);
            sacc[nf][0] = sacc[nf][0] * 0.125f + mk0.x;
            sacc[nf][1] = sacc[nf][1] * 0.125f + mk0.y;
            sacc[nf][2] = sacc[nf][2] * 0.125f + mk1.x;
            sacc[nf][3] = sacc[nf][3] * 0.125f + mk1.y;
            mx0 = fmaxf(mx0, fmaxf(sacc[nf][0], sacc[nf][1]));
            mx1 = fmaxf(mx1, fmaxf(sacc[nf][2], sacc[nf][3]));
        }
        mx0 = fmaxf(mx0, __shfl_xor_sync(0xffffffffu, mx0, 1));
        mx0 = fmaxf(mx0, __shfl_xor_sync(0xffffffffu, mx0, 2));
        mx1 = fmaxf(mx1, __shfl_xor_sync(0xffffffffu, mx1, 1));
        mx1 = fmaxf(mx1, __shfl_xor_sync(0xffffffffu, mx1, 2));

        float mn0 = fmaxf(m0, mx0), mn1 = fmaxf(m1, mx1);
        float cr0 = __expf(m0 - mn0), cr1 = __expf(m1 - mn1);
        m0 = mn0; m1 = mn1;
        float rs0 = 0.f, rs1 = 0.f;
        #pragma unroll
        for (int nf = 0; nf < 8; nf++) {
            sacc[nf][0] = __expf(sacc[nf][0] - mn0);
            sacc[nf][1] = __expf(sacc[nf][1] - mn0);
            sacc[nf][2] = __expf(sacc[nf][2] - mn1);
            sacc[nf][3] = __expf(sacc[nf][3] - mn1);
            rs0 += sacc[nf][0] + sacc[nf][1];
            rs1 += sacc[nf][2] + sacc[nf][3];
        }
        rs0 += __shfl_xor_sync(0xffffffffu, rs0, 1);
        rs0 += __shfl_xor_sync(0xffffffffu, rs0, 2);
        rs1 += __shfl_xor_sync(0xffffffffu, rs1, 1);
        rs1 += __shfl_xor_sync(0xffffffffu, rs1, 2);
        l0 = l0 * cr0 + rs0;
        l1 = l1 * cr1 + rs1;
        #pragma unroll
        for (int nf = 0; nf < 8; nf++) {
            oacc[nf][0] *= cr0; oacc[nf][1] *= cr0;
            oacc[nf][2] *= cr1; oacc[nf][3] *= cr1;
        }

        __syncthreads();   // all warps finished reading Kt
        // write P (tf32) to Ps[row][key]
        #pragma unroll
        for (int nf = 0; nf < 8; nf++) {
            int col = nf * 8 + 2 * c;
            KP[(wrow + g) * FSTR + col]     = f2tf(sacc[nf][0]);
            KP[(wrow + g) * FSTR + col + 1] = f2tf(sacc[nf][1]);
            KP[(wrow + g + 8) * FSTR + col]     = f2tf(sacc[nf][2]);
            KP[(wrow + g + 8) * FSTR + col + 1] = f2tf(sacc[nf][3]);
        }
        __syncthreads();

        // O += P @ V
        #pragma unroll
        for (int kk = 0; kk < 64; kk += 8) {
            uint32_t af[4];
            af[0] = KP[(wrow + g) * FSTR + kk + c];
            af[1] = KP[(wrow + g + 8) * FSTR + kk + c];
            af[2] = KP[(wrow + g) * FSTR + kk + c + 4];
            af[3] = KP[(wrow + g + 8) * FSTR + kk + c + 4];
            #pragma unroll
            for (int nf = 0; nf < 8; nf++) {
                uint32_t bf[2];
                bf[0] = Vs[(kk + c) * FSTR + nf * 8 + g];
                bf[1] = Vs[(kk + c + 4) * FSTR + nf * 8 + g];
                mma8(oacc[nf], af, bf);
            }
        }
    }

    float inv0 = 1.f / l0, inv1 = 1.f / l1;
    int row0 = q0 + wrow + g;
    float* o0 = O + ((size_t)(b * SS + row0)) * HH + hh * 64;
    float* o1 = o0 + 8 * (size_t)HH;
    #pragma unroll
    for (int nf = 0; nf < 8; nf++) {
        int col = nf * 8 + 2 * c;
        float2 v0 = make_float2(oacc[nf][0] * inv0, oacc[nf][1] * inv0);
        float2 v1 = make_float2(oacc[nf][2] * inv1, oacc[nf][3] * inv1);
        *(float2*)(o0 + col) = v0;
        *(float2*)(o1 + col) = v1;
    }
}

// ---------------- router ----------------
__global__ void router_k(const float* __restrict__ hn, const float* __restrict__ rw,
                         const float* __restrict__ rb,
                         int* __restrict__ cnt, int* __restrict__ tok, float* __restrict__ twt)
{
    int t = blockIdx.x;
    __shared__ float red[128][NE];
    float accv[NE];
    #pragma unroll
    for (int e = 0; e < NE; e++) accv[e] = 0.f;
    const float* xr = hn + (size_t)t * HH;
    for (int k = threadIdx.x; k < HH; k += 128) {
        float xv = xr[k];
        const float* w = rw + (size_t)k * NE;
        #pragma unroll
        for (int e = 0; e < NE; e++) accv[e] += xv * w[e];
    }
    #pragma unroll
    for (int e = 0; e < NE; e++) red[threadIdx.x][e] = accv[e];
    __syncthreads();
    for (int s = 64; s > 0; s >>= 1) {
        if (threadIdx.x < s)
            #pragma unroll
            for (int e = 0; e < NE; e++) red[threadIdx.x][e] += red[threadIdx.x + s][e];
        __syncthreads();
    }
    if (threadIdx.x == 0) {
        float p[NE];
        #pragma unroll
        for (int e = 0; e < NE; e++) {
            float lg = red[0][e] + rb[e];
            p[e] = 1.f / (1.f + expf(-lg));
        }
        int e1 = 0;
        for (int e = 1; e < NE; e++) if (p[e] > p[e1]) e1 = e;
        int e2 = -1;
        for (int e = 0; e < NE; e++) if (e != e1 && (e2 < 0 || p[e] > p[e2])) e2 = e;
        float s2 = p[e1] + p[e2];
        float w1 = p[e1] / s2, w2 = p[e2] / s2;
        int a = atomicAdd(&cnt[e1], 1); tok[e1 * TK + a] = t; twt[e1 * TK + a] = w1;
        int b = atomicAdd(&cnt[e2], 1); tok[e2 * TK + b] = t; twt[e2 * TK + b] = w2;
    }
}

__global__ void silu_mul_k(const float* __restrict__ g, const float* __restrict__ u,
                           float* __restrict__ y, int n)
{
    int i = blockIdx.x * 256 + threadIdx.x;
    if (i < n) {
        float gv = g[i];
        y[i] = (gv / (1.f + expf(-gv))) * u[i];
    }
}

__global__ void usage_k(const int* __restrict__ cnt, float* __restrict__ out)
{
    int e = threadIdx.x;
    if (e < NE) out[e] = (float)cnt[e];
}

// ---------------- host-side GEMM dispatch ----------------
static const int SMEM1 = (2 * 1 * (2560 + 2176) + 128) * 4;   // 38400
static const int SMEM3 = (2 * 2 * (2560 + 2176) + 128) * 4;   // 76288
static const int SMEMF = (64 * QSTR + 2 * 64 * FSTR) * 4;     // 54272

static void G(int prec,
              const float* A, int lda, size_t eas,
              const float* B, int ldb, size_t ebs,
              float* C, int ldc, size_t ecs,
              int M, int N, int K, int nz,
              const int* tokB, int ga, int sc,
              const float* wtB, const float* adds, int accA,
              const int* cntB)
{
    dim3 grid(N / 128, (M + 127) / 128, nz);
    if (prec == 3)
        gemm_tc<3><<<grid, 256, SMEM3>>>(A, lda, eas, B, ldb, ebs, C, ldc, ecs,
                                         M, N, K, tokB, ga, sc, wtB, adds, accA, cntB);
    else
        gemm_tc<1><<<grid, 256, SMEM1>>>(A, lda, eas, B, ldb, ebs, C, ldc, ecs,
                                         M, N, K, tokB, ga, sc, wtB, adds, accA, cntB);
}

extern "C" void kernel_launch(void* const* d_in, const int* in_sizes, int n_in,
                              void* d_out, int out_size)
{
    const float* x        = (const float*)d_in[0];
    const float* cosp     = (const float*)d_in[1];
    const float* sinp     = (const float*)d_in[2];
    const float* maskp    = (const float*)d_in[3];
    const float* ln1      = (const float*)d_in[4];
    const float* ln2      = (const float*)d_in[5];
    const float* kv_down  = (const float*)d_in[6];
    const float* kv_norm  = (const float*)d_in[7];
    const float* w_uk     = (const float*)d_in[8];
    const float* w_ur     = (const float*)d_in[9];
    const float* w_uv     = (const float*)d_in[10];
    const float* q_down   = (const float*)d_in[11];
    const float* q_norm   = (const float*)d_in[12];
    const float* w_uq     = (const float*)d_in[13];
    const float* w_qr     = (const float*)d_in[14];
    const float* o_proj   = (const float*)d_in[15];
    const float* sh_gate  = (const float*)d_in[16];
    const float* sh_up    = (const float*)d_in[17];
    const float* sh_down  = (const float*)d_in[18];
    const float* r_gate   = (const float*)d_in[19];
    const float* r_up     = (const float*)d_in[20];
    const float* r_down   = (const float*)d_in[21];
    const float* router_w = (const float*)d_in[22];
    const float* router_b = (const float*)d_in[23];
    float* out = (float*)d_out;

    float *xi, *cq, *ckv, *qn, *qr, *kn, *kr, *vx, *q, *k, *o, *h, *hn, *gt, *ut, *act, *twt;
    int *cnt, *tok;
    cudaGetSymbolAddress((void**)&xi,  g_xi);
    cudaGetSymbolAddress((void**)&cq,  g_cq);
    cudaGetSymbolAddress((void**)&ckv, g_ckv);
    cudaGetSymbolAddress((void**)&qn,  g_qn);
    cudaGetSymbolAddress((void**)&qr,  g_qr);
    cudaGetSymbolAddress((void**)&kn,  g_kn);
    cudaGetSymbolAddress((void**)&kr,  g_kr);
    cudaGetSymbolAddress((void**)&vx,  g_vx);
    cudaGetSymbolAddress((void**)&q,   g_q);
    cudaGetSymbolAddress((void**)&k,   g_k);
    cudaGetSymbolAddress((void**)&o,   g_o);
    cudaGetSymbolAddress((void**)&h,   g_h);
    cudaGetSymbolAddress((void**)&hn,  g_hn);
    cudaGetSymbolAddress((void**)&gt,  g_gt);
    cudaGetSymbolAddress((void**)&ut,  g_ut);
    cudaGetSymbolAddress((void**)&act, g_act);
    cudaGetSymbolAddress((void**)&twt, g_twt);
    cudaGetSymbolAddress((void**)&cnt, g_cnt);
    cudaGetSymbolAddress((void**)&tok, g_tok);

    cudaFuncSetAttribute(gemm_tc<1>, cudaFuncAttributeMaxDynamicSharedMemorySize, SMEM1);
    cudaFuncSetAttribute(gemm_tc<3>, cudaFuncAttributeMaxDynamicSharedMemorySize, SMEM3);
    cudaFuncSetAttribute(flash_tc,   cudaFuncAttributeMaxDynamicSharedMemorySize, SMEMF);

    const size_t TI = (size_t)TK * II;

    // ---- MLA attention (projections 3xTF32: feed the router downstream) ----
    rms_k<<<TK, 256>>>(x, ln1, xi, HH);
    G(3, xi, HH, 0,  q_down, 128, 0,  cq, 128, 0,  TK, 128, HH, 1,
      nullptr, 0, 0, nullptr, nullptr, 0, nullptr);
    G(3, xi, HH, 0,  kv_down, 128, 0,  ckv, 128, 0,  TK, 128, HH, 1,
      nullptr, 0, 0, nullptr, nullptr, 0, nullptr);
    rms_k<<<TK, 128>>>(cq, q_norm, cq, 128);
    rms_k<<<TK, 128>>>(ckv, kv_norm, ckv, 128);
    G(3, cq, 128, 0,  w_uq, 512, 0,  qn, 512, 0,  TK, 512, 128, 1,
      nullptr, 0, 0, nullptr, nullptr, 0, nullptr);
    G(3, cq, 128, 0,  w_qr, 512, 0,  qr, 512, 0,  TK, 512, 128, 1,
      nullptr, 0, 0, nullptr, nullptr, 0, nullptr);
    G(3, ckv, 128, 0,  w_uk, 512, 0,  kn, 512, 0,  TK, 512, 128, 1,
      nullptr, 0, 0, nullptr, nullptr, 0, nullptr);
    G(3, ckv, 128, 0,  w_ur, 512, 0,  kr, 512, 0,  TK, 512, 128, 1,
      nullptr, 0, 0, nullptr, nullptr, 0, nullptr);
    G(3, ckv, 128, 0,  w_uv, 1024, 0,  vx, 1024, 0,  TK, 1024, 128, 1,
      nullptr, 0, 0, nullptr, nullptr, 0, nullptr);
    assemble_k<<<(BHN * SS * 64) / 256, 256>>>(qn, qr, kn, kr, cosp, sinp, q, k);

    flash_tc<<<dim3(SS / 64, BHN), 128, SMEMF>>>(q, k, vx, maskp, o);

    G(3, o, HH, 0,  o_proj, HH, 0,  h, HH, 0,  TK, HH, HH, 1,
      nullptr, 0, 0, nullptr, x, 0, nullptr);   // h = x + o@Wo

    // ---- MoE ----
    rms_k<<<TK, 256>>>(h, ln2, hn, HH);
    cudaMemsetAsync(cnt, 0, NE * sizeof(int), 0);
    router_k<<<TK, 128>>>(hn, router_w, router_b, cnt, tok, twt);
    cudaMemcpyAsync(out, h, (size_t)TK * HH * sizeof(float), cudaMemcpyDeviceToDevice, 0);

    // shared experts (dense, batched z=2)
    G(1, hn, HH, 0,  sh_gate, II, (size_t)HH * II,  gt, II, TI,  TK, II, HH, 2,
      nullptr, 0, 0, nullptr, nullptr, 0, nullptr);
    G(1, hn, HH, 0,  sh_up, II, (size_t)HH * II,  ut, II, TI,  TK, II, HH, 2,
      nullptr, 0, 0, nullptr, nullptr, 0, nullptr);
    silu_mul_k<<<(2 * (int)TI + 255) / 256, 256>>>(gt, ut, act, 2 * (int)TI);
    G(1, act, II, TI,  sh_down, HH, (size_t)II * HH,  out, HH, 0,  TK, HH, II, 2,
      nullptr, 0, 0, nullptr, nullptr, 1, nullptr);

    // routed experts (sparse compact rows, batched z=8)
    G(1, hn, HH, 0,  r_gate, II, (size_t)HH * II,  gt, II, TI,  TK, II, HH, NE,
      tok, 1, 0, nullptr, nullptr, 0, cnt);
    G(1, hn, HH, 0,  r_up, II, (size_t)HH * II,  ut, II, TI,  TK, II, HH, NE,
      tok, 1, 0, nullptr, nullptr, 0, cnt);
    silu_mul_k<<<(NE * (int)TI + 255) / 256, 256>>>(gt, ut, act, NE * (int)TI);
    G(1, act, II, TI,  r_down, HH, (size_t)II * HH,  out, HH, 0,  TK, HH, II, NE,
      tok, 0, 1, twt, nullptr, 0, cnt);

    usage_k<<<1, NE>>>(cnt, out + (size_t)TK * HH);
}

// round 7
// speedup vs baseline: 3.9483x; 1.4417x over previous
#include <cuda_runtime.h>
#include <cuda_bf16.h>
#include <math.h>
#include <stdint.h>

// ---------------- problem constants ----------------
#define TK   4096      // tokens = B*S
#define HH   1024      // hidden
#define SS   2048      // seq len
#define NHH  16        // heads
#define BHN  32        // B*NH
#define II   384       // expert intermediate
#define NE   8         // routed experts

// ---------------- scratch (device globals; no allocation allowed) ----------------
__device__ float g_xi [TK*HH];
__device__ float g_cq [TK*128];
__device__ float g_ckv[TK*128];
__device__ float g_qn [TK*512];
__device__ float g_qr [TK*512];
__device__ float g_kn [TK*512];
__device__ float g_kr [TK*512];
__device__ float g_vx [TK*HH];
__device__ float g_q  [TK*HH];   // [bh][s][64]
__device__ float g_k  [TK*HH];
__device__ float g_o  [TK*HH];   // [b][s][h*64+d]
__device__ float g_h  [TK*HH];
__device__ float g_hn [TK*HH];
// MoE scratch: shared experts use [0, 2*TK*II), routed use [2*TK*II, 10*TK*II)
__device__ float g_gt [(NE+2)*TK*II];
__device__ float g_ut [(NE+2)*TK*II];
__device__ float g_act[(NE+2)*TK*II];
__device__ int   g_cnt[NE];
__device__ int   g_tok[NE*TK];
__device__ float g_twt[NE*TK];

// ---------------- mma helpers ----------------
__device__ __forceinline__ uint32_t f2tf(float f) {
    uint32_t r;
    asm("cvt.rna.tf32.f32 %0, %1;" : "=r"(r) : "f"(f));
    return r;
}
__device__ __forceinline__ void mma8(float* c, const uint32_t* a, const uint32_t* b) {
    asm volatile(
        "mma.sync.aligned.m16n8k8.row.col.f32.tf32.tf32.f32 "
        "{%0,%1,%2,%3}, {%4,%5,%6,%7}, {%8,%9}, {%0,%1,%2,%3};\n"
        : "+f"(c[0]), "+f"(c[1]), "+f"(c[2]), "+f"(c[3])
        : "r"(a[0]), "r"(a[1]), "r"(a[2]), "r"(a[3]), "r"(b[0]), "r"(b[1]));
}
__device__ __forceinline__ void mma16(float* c, const uint32_t* a, const uint32_t* b) {
    asm volatile(
        "mma.sync.aligned.m16n8k16.row.col.f32.bf16.bf16.f32 "
        "{%0,%1,%2,%3}, {%4,%5,%6,%7}, {%8,%9}, {%0,%1,%2,%3};\n"
        : "+f"(c[0]), "+f"(c[1]), "+f"(c[2]), "+f"(c[3])
        : "r"(a[0]), "r"(a[1]), "r"(a[2]), "r"(a[3]), "r"(b[0]), "r"(b[1]));
}
__device__ __forceinline__ uint32_t pkbf2(float a, float b) {
    __nv_bfloat162 t = __floats2bfloat162_rn(a, b);
    return *reinterpret_cast<uint32_t*>(&t);
}

// ---------------- bf16x3 GEMM (fp32-quality) ----------------
// C = A@B, M,N mult of 128, K mult of 32*splitK. splitK>1 -> atomicAdd into
// pre-zeroed C. addsrc: C = acc + addsrc (only when splitK==1).
#define BASTR 20
#define BBSTR 136
#define BASZ  (128*BASTR)
#define BBSZ  (16*BBSTR)
__global__ void __launch_bounds__(256) gemm_bf3(
    const float* __restrict__ A, int lda,
    const float* __restrict__ B, int ldb,
    float* __restrict__ C, int ldc,
    int M, int N, int K,
    const float* __restrict__ addsrc, int splitK)
{
    extern __shared__ uint32_t sm[];
    uint32_t* As = sm;             // [2 buf][2 copy][BASZ]
    uint32_t* Bs = sm + 4 * BASZ;  // [2 buf][2 copy][BBSZ]

    const int sK = blockIdx.z;
    const int Kc = K / splitK;
    const int kbase = sK * Kc;
    const int m0 = blockIdx.y * 128;
    const int n0 = blockIdx.x * 128;
    const int tid = threadIdx.x;

    auto loadTile = [&](int buf, int kt) {
        uint32_t* Ad = As + buf * 2 * BASZ;
        #pragma unroll
        for (int i = 0; i < 8; i++) {
            int flat = tid + i * 256;
            int m = flat >> 4, k2 = flat & 15;
            float2 v = *(const float2*)(A + (size_t)(m0 + m) * lda + kt + 2 * k2);
            __nv_bfloat162 hi = __floats2bfloat162_rn(v.x, v.y);
            float r0 = v.x - __bfloat162float(hi.x);
            float r1 = v.y - __bfloat162float(hi.y);
            Ad[m * BASTR + k2] = *reinterpret_cast<uint32_t*>(&hi);
            Ad[BASZ + m * BASTR + k2] = pkbf2(r0, r1);
        }
        uint32_t* Bd = Bs + buf * 2 * BBSZ;
        #pragma unroll
        for (int i = 0; i < 8; i++) {
            int flat = tid + i * 256;
            int n = flat & 127, k2 = flat >> 7;
            float v0 = B[(size_t)(kt + 2 * k2) * ldb + n0 + n];
            float v1 = B[(size_t)(kt + 2 * k2 + 1) * ldb + n0 + n];
            __nv_bfloat162 hi = __floats2bfloat162_rn(v0, v1);
            float r0 = v0 - __bfloat162float(hi.x);
            float r1 = v1 - __bfloat162float(hi.y);
            Bd[k2 * BBSTR + n] = *reinterpret_cast<uint32_t*>(&hi);
            Bd[BBSZ + k2 * BBSTR + n] = pkbf2(r0, r1);
        }
    };

    const int lane = tid & 31, wid = tid >> 5;
    const int wm = (wid >> 2) * 64;
    const int wn = (wid & 3) * 32;
    const int g = lane >> 2, c = lane & 3;

    float acc[4][4][4];
    #pragma unroll
    for (int i = 0; i < 4; i++)
        #pragma unroll
        for (int j = 0; j < 4; j++)
            #pragma unroll
            for (int r = 0; r < 4; r++) acc[i][j][r] = 0.f;

    loadTile(0, kbase);
    __syncthreads();

    const int nbuf = Kc >> 5;   // 32 K per buffer
    for (int t = 0; t < nbuf; t++) {
        int cur = t & 1;
        if (t + 1 < nbuf) loadTile(cur ^ 1, kbase + ((t + 1) << 5));

        // passes: (Ahi,Bhi), (Alo,Bhi), (Ahi,Blo)
        #pragma unroll
        for (int pass = 0; pass < 3; pass++) {
            const uint32_t* Ab = As + cur * 2 * BASZ + ((pass == 1) ? BASZ : 0);
            const uint32_t* Bb = Bs + cur * 2 * BBSZ + ((pass == 2) ? BBSZ : 0);
            #pragma unroll
            for (int ks2 = 0; ks2 < 16; ks2 += 8) {
                uint32_t af[4][4];
                #pragma unroll
                for (int mt = 0; mt < 4; mt++) {
                    int mb = wm + mt * 16;
                    af[mt][0] = Ab[(mb + g) * BASTR + ks2 + c];
                    af[mt][1] = Ab[(mb + g + 8) * BASTR + ks2 + c];
                    af[mt][2] = Ab[(mb + g) * BASTR + ks2 + c + 4];
                    af[mt][3] = Ab[(mb + g + 8) * BASTR + ks2 + c + 4];
                }
                uint32_t bf[4][2];
                #pragma unroll
                for (int nt = 0; nt < 4; nt++) {
                    int nb = wn + nt * 8;
                    bf[nt][0] = Bb[(ks2 + c) * BBSTR + nb + g];
                    bf[nt][1] = Bb[(ks2 + c + 4) * BBSTR + nb + g];
                }
                #pragma unroll
                for (int mt = 0; mt < 4; mt++)
                    #pragma unroll
                    for (int nt = 0; nt < 4; nt++)
                        mma16(acc[mt][nt], af[mt], bf[nt]);
            }
        }
        __syncthreads();
    }

    #pragma unroll
    for (int mt = 0; mt < 4; mt++) {
        #pragma unroll
        for (int h2 = 0; h2 < 2; h2++) {
            int m = m0 + wm + mt * 16 + g + h2 * 8;
            #pragma unroll
            for (int nt = 0; nt < 4; nt++) {
                int ncol = n0 + wn + nt * 8 + c * 2;
                float v0 = acc[mt][nt][h2 * 2 + 0];
                float v1 = acc[mt][nt][h2 * 2 + 1];
                float* cp = C + (size_t)m * ldc + ncol;
                if (splitK > 1) {
                    atomicAdd(cp, v0); atomicAdd(cp + 1, v1);
                } else if (addsrc) {
                    const float* ap = addsrc + (size_t)m * ldc + ncol;
                    cp[0] = v0 + ap[0]; cp[1] = v1 + ap[1];
                } else {
                    cp[0] = v0; cp[1] = v1;
                }
            }
        }
    }
}

// ---------------- tf32 single-pass GEMM (MoE: gather/scatter/scale) ----------------
template<int PREC>
__global__ void __launch_bounds__(256) gemm_tc(
    const float* __restrict__ A, int lda, size_t eastride,
    const float* __restrict__ B, int ldb, size_t ebstride,
    float* __restrict__ C, int ldc, size_t ecstride,
    int M, int N, int K,
    const int* __restrict__ tokBase, int gatherA, int scatterC,
    const float* __restrict__ wtBase,
    const float* __restrict__ addsrc, int accAtomic,
    const int* __restrict__ cntBase)
{
    constexpr int NC = 1;
    constexpr int ASTR = 20;
    constexpr int BSTR = 136;
    constexpr int ASZ = 128 * ASTR;
    constexpr int BSZ = 16 * BSTR;

    extern __shared__ uint32_t smem_u[];
    uint32_t* As = smem_u;
    uint32_t* Bs = smem_u + 2 * NC * ASZ;
    int* idxs = (int*)(smem_u + 2 * NC * (ASZ + BSZ));

    const int e = blockIdx.z;
    A += (size_t)e * eastride;
    B += (size_t)e * ebstride;
    C += (size_t)e * ecstride;
    const int* idx = tokBase ? tokBase + (size_t)e * TK : nullptr;
    const float* wt = wtBase ? wtBase + (size_t)e * TK : nullptr;
    const int effM = cntBase ? cntBase[e] : M;

    const int m0 = blockIdx.y * 128;
    const int n0 = blockIdx.x * 128;
    if (m0 >= effM) return;

    const int tid = threadIdx.x;
    if (idx) {
        for (int i = tid; i < 128; i += 256) {
            int m = m0 + i;
            idxs[i] = (m < effM) ? idx[m] : 0;
        }
    }
    __syncthreads();

    auto loadTile = [&](int buf, int kt) {
        uint32_t* Ad = As + buf * NC * ASZ;
        #pragma unroll
        for (int i = 0; i < 8; i++) {
            int flat = tid + i * 256;
            int m = flat >> 4, k = flat & 15;
            float v = 0.f;
            int mg = m0 + m;
            if (mg < effM) {
                int row = gatherA ? idxs[m] : mg;
                v = A[(size_t)row * lda + kt + k];
            }
            Ad[m * ASTR + k] = f2tf(v);
        }
        uint32_t* Bd = Bs + buf * NC * BSZ;
        #pragma unroll
        for (int i = 0; i < 8; i++) {
            int flat = tid + i * 256;
            int n = flat & 127, k = flat >> 7;
            Bd[k * BSTR + n] = f2tf(B[(size_t)(kt + k) * ldb + n0 + n]);
        }
    };

    const int lane = tid & 31, wid = tid >> 5;
    const int wm = (wid >> 2) * 64;
    const int wn = (wid & 3) * 32;
    const int g = lane >> 2, c = lane & 3;

    float acc[4][4][4];
    #pragma unroll
    for (int i = 0; i < 4; i++)
        #pragma unroll
        for (int j = 0; j < 4; j++)
            #pragma unroll
            for (int r = 0; r < 4; r++) acc[i][j][r] = 0.f;

    loadTile(0, 0);
    __syncthreads();

    const int nkt = K >> 4;
    for (int t = 0; t < nkt; t++) {
        int cur = t & 1;
        if (t + 1 < nkt) loadTile(cur ^ 1, (t + 1) << 4);

        const uint32_t* Ab = As + cur * NC * ASZ;
        const uint32_t* Bb = Bs + cur * NC * BSZ;
        #pragma unroll
        for (int ks = 0; ks < 16; ks += 8) {
            uint32_t af[4][4];
            #pragma unroll
            for (int mt = 0; mt < 4; mt++) {
                int mb = wm + mt * 16;
                af[mt][0] = Ab[(mb + g) * ASTR + ks + c];
                af[mt][1] = Ab[(mb + g + 8) * ASTR + ks + c];
                af[mt][2] = Ab[(mb + g) * ASTR + ks + c + 4];
                af[mt][3] = Ab[(mb + g + 8) * ASTR + ks + c + 4];
            }
            uint32_t bf[4][2];
            #pragma unroll
            for (int nt = 0; nt < 4; nt++) {
                int nb = wn + nt * 8;
                bf[nt][0] = Bb[(ks + c) * BSTR + nb + g];
                bf[nt][1] = Bb[(ks + c + 4) * BSTR + nb + g];
            }
            #pragma unroll
            for (int mt = 0; mt < 4; mt++)
                #pragma unroll
                for (int nt = 0; nt < 4; nt++)
                    mma8(acc[mt][nt], af[mt], bf[nt]);
        }
        __syncthreads();
    }

    #pragma unroll
    for (int mt = 0; mt < 4; mt++) {
        #pragma unroll
        for (int h2 = 0; h2 < 2; h2++) {
            int ml = wm + mt * 16 + g + h2 * 8;
            int m = m0 + ml;
            if (m >= effM) continue;
            int crow = scatterC ? idxs[ml] : m;
            float sc = wt ? wt[m] : 1.f;
            #pragma unroll
            for (int nt = 0; nt < 4; nt++) {
                int ncol = n0 + wn + nt * 8 + c * 2;
                float v0 = acc[mt][nt][h2 * 2 + 0];
                float v1 = acc[mt][nt][h2 * 2 + 1];
                float* cp = C + (size_t)crow * ldc + ncol;
                if (wt) {
                    atomicAdd(cp, sc * v0); atomicAdd(cp + 1, sc * v1);
                } else if (accAtomic) {
                    atomicAdd(cp, v0); atomicAdd(cp + 1, v1);
                } else if (addsrc) {
                    const float* ap = addsrc + (size_t)m * ldc + ncol;
                    cp[0] = v0 + ap[0]; cp[1] = v1 + ap[1];
                } else {
                    cp[0] = v0; cp[1] = v1;
                }
            }
        }
    }
}

// ---------------- RMSNorm ----------------
__global__ void rms_k(const float* __restrict__ x, const float* __restrict__ w,
                      float* __restrict__ y, int D)
{
    int t = blockIdx.x;
    const float* xr = x + (size_t)t * D;
    float* yr = y + (size_t)t * D;
    float ss = 0.f;
    for (int k = threadIdx.x; k < D; k += blockDim.x) { float v = xr[k]; ss += v * v; }
    __shared__ float sh[32];
    int lane = threadIdx.x & 31, wid = threadIdx.x >> 5;
    #pragma unroll
    for (int o = 16; o > 0; o >>= 1) ss += __shfl_xor_sync(0xffffffffu, ss, o);
    if (lane == 0) sh[wid] = ss;
    __syncthreads();
    if (threadIdx.x == 0) {
        float tot = 0.f;
        int nw = blockDim.x >> 5;
        for (int i = 0; i < nw; i++) tot += sh[i];
        sh[0] = tot;
    }
    __syncthreads();
    float r = rsqrtf(sh[0] / (float)D + 1e-5f);
    for (int k = threadIdx.x; k < D; k += blockDim.x) yr[k] = w[k] * xr[k] * r;
}

// ---------------- assemble Q/K with RoPE ----------------
__global__ void assemble_k(const float* __restrict__ qn, const float* __restrict__ qr,
                           const float* __restrict__ kn, const float* __restrict__ kr,
                           const float* __restrict__ cosp, const float* __restrict__ sinp,
                           float* __restrict__ Q, float* __restrict__ K)
{
    int idx = blockIdx.x * blockDim.x + threadIdx.x;
    if (idx >= BHN * SS * 64) return;
    int d  = idx & 63;
    int s  = (idx >> 6) & (SS - 1);
    int bh = idx >> 17;
    int b  = bh >> 4, h = bh & 15;
    int t  = b * SS + s;
    float qv, kv;
    if (d < 32) {
        qv = qn[(size_t)t * 512 + h * 32 + d];
        kv = kn[(size_t)t * 512 + h * 32 + d];
    } else {
        int j = d - 32;
        float cc = cosp[s * 32 + j];
        float sn = sinp[s * 32 + j];
        float q1 = qr[(size_t)t * 512 + h * 32 + j];
        float q2 = (j < 16) ? -qr[(size_t)t * 512 + h * 32 + j + 16]
                            :  qr[(size_t)t * 512 + h * 32 + j - 16];
        qv = q1 * cc + q2 * sn;
        float k1 = kr[(size_t)t * 512 + h * 32 + j];
        float k2 = (j < 16) ? -kr[(size_t)t * 512 + h * 32 + j + 16]
                            :  kr[(size_t)t * 512 + h * 32 + j - 16];
        kv = k1 * cc + k2 * sn;
    }
    Q[idx] = qv;
    K[idx] = kv;
}

// ---------------- flash attention, tf32 tensor cores ----------------
#define QSTR 68
#define FSTR 72
__global__ void __launch_bounds__(128) flash_tc(
    const float* __restrict__ Q, const float* __restrict__ Kg,
    const float* __restrict__ Vx, const float* __restrict__ maskp,
    float* __restrict__ O)
{
    extern __shared__ uint32_t sm[];
    uint32_t* Qs = sm;
    uint32_t* KP = sm + 64 * QSTR;
    uint32_t* Vs = KP + 64 * FSTR;

    const int bh = blockIdx.y;
    const int q0 = blockIdx.x * 64;
    const int b  = bh >> 4, hh = bh & 15;
    const float* Qb = Q  + (size_t)bh * SS * 64;
    const float* Kb = Kg + (size_t)bh * SS * 64;
    const float* Vb = Vx + (size_t)b * SS * HH + hh * 64;

    const int tid = threadIdx.x;
    const int w = tid >> 5, lane = tid & 31;
    const int g = lane >> 2, c = lane & 3;
    const int wrow = w * 16;

    const int lr  = tid & 63;
    const int lc0 = (tid >> 6) * 32;

    {
        const float4* src = (const float4*)(Qb + (size_t)(q0 + lr) * 64 + lc0);
        #pragma unroll
        for (int i = 0; i < 8; i++) {
            float4 v = src[i];
            uint32_t* d = Qs + lr * QSTR + lc0 + i * 4;
            d[0] = f2tf(v.x); d[1] = f2tf(v.y); d[2] = f2tf(v.z); d[3] = f2tf(v.w);
        }
    }

    float oacc[8][4];
    #pragma unroll
    for (int nf = 0; nf < 8; nf++)
        #pragma unroll
        for (int r = 0; r < 4; r++) oacc[nf][r] = 0.f;
    float m0 = -1e30f, m1 = -1e30f, l0 = 0.f, l1 = 0.f;

    const float* mr0 = maskp + (size_t)(q0 + wrow + g) * SS;
    const float* mr1 = mr0 + 8 * SS;

    for (int k0 = 0; k0 < SS; k0 += 64) {
        __syncthreads();
        {
            const float4* ks = (const float4*)(Kb + (size_t)(k0 + lr) * 64 + lc0);
            const float4* vs = (const float4*)(Vb + (size_t)(k0 + lr) * HH + lc0);
            #pragma unroll
            for (int i = 0; i < 8; i++) {
                float4 kv = ks[i];
                int d = lc0 + i * 4;
                KP[(d + 0) * FSTR + lr] = f2tf(kv.x);
                KP[(d + 1) * FSTR + lr] = f2tf(kv.y);
                KP[(d + 2) * FSTR + lr] = f2tf(kv.z);
                KP[(d + 3) * FSTR + lr] = f2tf(kv.w);
                float4 vv = vs[i];
                uint32_t* vd = Vs + lr * FSTR + d;
                vd[0] = f2tf(vv.x); vd[1] = f2tf(vv.y); vd[2] = f2tf(vv.z); vd[3] = f2tf(vv.w);
            }
        }
        __syncthreads();

        float sacc[8][4];
        #pragma unroll
        for (int nf = 0; nf < 8; nf++)
            #pragma unroll
            for (int r = 0; r < 4; r++) sacc[nf][r] = 0.f;
        #pragma unroll
        for (int ks = 0; ks < 64; ks += 8) {
            uint32_t af[4];
            af[0] = Qs[(wrow + g) * QSTR + ks + c];
            af[1] = Qs[(wrow + g + 8) * QSTR + ks + c];
            af[2] = Qs[(wrow + g) * QSTR + ks + c + 4];
            af[3] = Qs[(wrow + g + 8) * QSTR + ks + c + 4];
            #pragma unroll
            for (int nf = 0; nf < 8; nf++) {
                uint32_t bf[2];
                bf[0] = KP[(ks + c) * FSTR + nf * 8 + g];
                bf[1] = KP[(ks + c + 4) * FSTR + nf * 8 + g];
                mma8(sacc[nf], af, bf);
            }
        }

        float mx0 = -1e30f, mx1 = -1e30f;
        #pragma unroll
        for (int nf = 0; nf < 8; nf++) {
            float2 mk0 = *(const float2*)(mr0 + k0 + nf * 8 + 2 * c);
            float2 mk1 = *(const float2*)(mr1 + k0 + nf * 8 + 2 * c);
            sacc[nf][0] = sacc[nf][0] * 0.125f + mk0.x;
            sacc[nf][1] = sacc[nf][1] * 0.125f + mk0.y;
            sacc[nf][2] = sacc[nf][2] * 0.125f + mk1.x;
            sacc[nf][3] = sacc[nf][3] * 0.125f + mk1.y;
            mx0 = fmaxf(mx0, fmaxf(sacc[nf][0], sacc[nf][1]));
            mx1 = fmaxf(mx1, fmaxf(sacc[nf][2], sacc[nf][3]));
        }
        mx0 = fmaxf(mx0, __shfl_xor_sync(0xffffffffu, mx0, 1));
        mx0 = fmaxf(mx0, __shfl_xor_sync(0xffffffffu, mx0, 2));
        mx1 = fmaxf(mx1, __shfl_xor_sync(0xffffffffu, mx1, 1));
        mx1 = fmaxf(mx1, __shfl_xor_sync(0xffffffffu, mx1, 2));

        float mn0 = fmaxf(m0, mx0), mn1 = fmaxf(m1, mx1);
        float cr0 = __expf(m0 - mn0), cr1 = __expf(m1 - mn1);
        m0 = mn0; m1 = mn1;
        float rs0 = 0.f, rs1 = 0.f;
        #pragma unroll
        for (int nf = 0; nf < 8; nf++) {
            sacc[nf][0] = __expf(sacc[nf][0] - mn0);
            sacc[nf][1] = __expf(sacc[nf][1] - mn0);
            sacc[nf][2] = __expf(sacc[nf][2] - mn1);
            sacc[nf][3] = __expf(sacc[nf][3] - mn1);
            rs0 += sacc[nf][0] + sacc[nf][1];
            rs1 += sacc[nf][2] + sacc[nf][3];
        }
        rs0 += __shfl_xor_sync(0xffffffffu, rs0, 1);
        rs0 += __shfl_xor_sync(0xffffffffu, rs0, 2);
        rs1 += __shfl_xor_sync(0xffffffffu, rs1, 1);
        rs1 += __shfl_xor_sync(0xffffffffu, rs1, 2);
        l0 = l0 * cr0 + rs0;
        l1 = l1 * cr1 + rs1;
        #pragma unroll
        for (int nf = 0; nf < 8; nf++) {
            oacc[nf][0] *= cr0; oacc[nf][1] *= cr0;
            oacc[nf][2] *= cr1; oacc[nf][3] *= cr1;
        }

        __syncthreads();
        #pragma unroll
        for (int nf = 0; nf < 8; nf++) {
            int col = nf * 8 + 2 * c;
            KP[(wrow + g) * FSTR + col]     = f2tf(sacc[nf][0]);
            KP[(wrow + g) * FSTR + col + 1] = f2tf(sacc[nf][1]);
            KP[(wrow + g + 8) * FSTR + col]     = f2tf(sacc[nf][2]);
            KP[(wrow + g + 8) * FSTR + col + 1] = f2tf(sacc[nf][3]);
        }
        __syncthreads();

        #pragma unroll
        for (int kk = 0; kk < 64; kk += 8) {
            uint32_t af[4];
            af[0] = KP[(wrow + g) * FSTR + kk + c];
            af[1] = KP[(wrow + g + 8) * FSTR + kk + c];
            af[2] = KP[(wrow + g) * FSTR + kk + c + 4];
            af[3] = KP[(wrow + g + 8) * FSTR + kk + c + 4];
            #pragma unroll
            for (int nf = 0; nf < 8; nf++) {
                uint32_t bf[2];
                bf[0] = Vs[(kk + c) * FSTR + nf * 8 + g];
                bf[1] = Vs[(kk + c + 4) * FSTR + nf * 8 + g];
                mma8(oacc[nf], af, bf);
            }
        }
    }

    float inv0 = 1.f / l0, inv1 = 1.f / l1;
    int row0 = q0 + wrow + g;
    float* o0 = O + ((size_t)(b * SS + row0)) * HH + hh * 64;
    float* o1 = o0 + 8 * (size_t)HH;
    #pragma unroll
    for (int nf = 0; nf < 8; nf++) {
        int col = nf * 8 + 2 * c;
        float2 v0 = make_float2(oacc[nf][0] * inv0, oacc[nf][1] * inv0);
        float2 v1 = make_float2(oacc[nf][2] * inv1, oacc[nf][3] * inv1);
        *(float2*)(o0 + col) = v0;
        *(float2*)(o1 + col) = v1;
    }
}

// ---------------- router ----------------
__global__ void router_k(const float* __restrict__ hn, const float* __restrict__ rw,
                         const float* __restrict__ rb,
                         int* __restrict__ cnt, int* __restrict__ tok, float* __restrict__ twt)
{
    int t = blockIdx.x;
    __shared__ float red[128][NE];
    float accv[NE];
    #pragma unroll
    for (int e = 0; e < NE; e++) accv[e] = 0.f;
    const float* xr = hn + (size_t)t * HH;
    for (int k = threadIdx.x; k < HH; k += 128) {
        float xv = xr[k];
        const float* w = rw + (size_t)k * NE;
        #pragma unroll
        for (int e = 0; e < NE; e++) accv[e] += xv * w[e];
    }
    #pragma unroll
    for (int e = 0; e < NE; e++) red[threadIdx.x][e] = accv[e];
    __syncthreads();
    for (int s = 64; s > 0; s >>= 1) {
        if (threadIdx.x < s)
            #pragma unroll
            for (int e = 0; e < NE; e++) red[threadIdx.x][e] += red[threadIdx.x + s][e];
        __syncthreads();
    }
    if (threadIdx.x == 0) {
        float p[NE];
        #pragma unroll
        for (int e = 0; e < NE; e++) {
            float lg = red[0][e] + rb[e];
            p[e] = 1.f / (1.f + expf(-lg));
        }
        int e1 = 0;
        for (int e = 1; e < NE; e++) if (p[e] > p[e1]) e1 = e;
        int e2 = -1;
        for (int e = 0; e < NE; e++) if (e != e1 && (e2 < 0 || p[e] > p[e2])) e2 = e;
        float s2 = p[e1] + p[e2];
        float w1 = p[e1] / s2, w2 = p[e2] / s2;
        int a = atomicAdd(&cnt[e1], 1); tok[e1 * TK + a] = t; twt[e1 * TK + a] = w1;
        int b = atomicAdd(&cnt[e2], 1); tok[e2 * TK + b] = t; twt[e2 * TK + b] = w2;
    }
}

__global__ void silu_mul_k(const float* __restrict__ g, const float* __restrict__ u,
                           float* __restrict__ y, int n)
{
    int i = blockIdx.x * 256 + threadIdx.x;
    if (i < n) {
        float gv = g[i];
        y[i] = (gv / (1.f + expf(-gv))) * u[i];
    }
}

__global__ void usage_k(const int* __restrict__ cnt, float* __restrict__ out)
{
    int e = threadIdx.x;
    if (e < NE) out[e] = (float)cnt[e];
}

// ---------------- host-side dispatch ----------------
static const int SMEM1   = (2 * 1 * (2560 + 2176) + 128) * 4;   // 38400
static const int SMEMBF3 = (4 * BASZ + 4 * BBSZ) * 4;           // 75776
static const int SMEMF   = (64 * QSTR + 2 * 64 * FSTR) * 4;     // 54272

static void GB(cudaStream_t st,
               const float* A, int lda, const float* B, int ldb,
               float* C, int ldc, int M, int N, int K,
               const float* adds, int splitK)
{
    dim3 grid(N / 128, M / 128, splitK);
    gemm_bf3<<<grid, 256, SMEMBF3, st>>>(A, lda, B, ldb, C, ldc, M, N, K, adds, splitK);
}

static void G1(cudaStream_t st,
               const float* A, int lda, size_t eas,
               const float* B, int ldb, size_t ebs,
               float* C, int ldc, size_t ecs,
               int M, int N, int K, int nz,
               const int* tokB, int ga, int sc,
               const float* wtB, const float* adds, int accA,
               const int* cntB)
{
    dim3 grid(N / 128, (M + 127) / 128, nz);
    gemm_tc<1><<<grid, 256, SMEM1, st>>>(A, lda, eas, B, ldb, ebs, C, ldc, ecs,
                                         M, N, K, tokB, ga, sc, wtB, adds, accA, cntB);
}

extern "C" void kernel_launch(void* const* d_in, const int* in_sizes, int n_in,
                              void* d_out, int out_size)
{
    const float* x        = (const float*)d_in[0];
    const float* cosp     = (const float*)d_in[1];
    const float* sinp     = (const float*)d_in[2];
    const float* maskp    = (const float*)d_in[3];
    const float* ln1      = (const float*)d_in[4];
    const float* ln2      = (const float*)d_in[5];
    const float* kv_down  = (const float*)d_in[6];
    const float* kv_norm  = (const float*)d_in[7];
    const float* w_uk     = (const float*)d_in[8];
    const float* w_ur     = (const float*)d_in[9];
    const float* w_uv     = (const float*)d_in[10];
    const float* q_down   = (const float*)d_in[11];
    const float* q_norm   = (const float*)d_in[12];
    const float* w_uq     = (const float*)d_in[13];
    const float* w_qr     = (const float*)d_in[14];
    const float* o_proj   = (const float*)d_in[15];
    const float* sh_gate  = (const float*)d_in[16];
    const float* sh_up    = (const float*)d_in[17];
    const float* sh_down  = (const float*)d_in[18];
    const float* r_gate   = (const float*)d_in[19];
    const float* r_up     = (const float*)d_in[20];
    const float* r_down   = (const float*)d_in[21];
    const float* router_w = (const float*)d_in[22];
    const float* router_b = (const float*)d_in[23];
    float* out = (float*)d_out;

    float *xi, *cq, *ckv, *qn, *qr, *kn, *kr, *vx, *q, *k, *o, *h, *hn, *gt, *ut, *act, *twt;
    int *cnt, *tok;
    cudaGetSymbolAddress((void**)&xi,  g_xi);
    cudaGetSymbolAddress((void**)&cq,  g_cq);
    cudaGetSymbolAddress((void**)&ckv, g_ckv);
    cudaGetSymbolAddress((void**)&qn,  g_qn);
    cudaGetSymbolAddress((void**)&qr,  g_qr);
    cudaGetSymbolAddress((void**)&kn,  g_kn);
    cudaGetSymbolAddress((void**)&kr,  g_kr);
    cudaGetSymbolAddress((void**)&vx,  g_vx);
    cudaGetSymbolAddress((void**)&q,   g_q);
    cudaGetSymbolAddress((void**)&k,   g_k);
    cudaGetSymbolAddress((void**)&o,   g_o);
    cudaGetSymbolAddress((void**)&h,   g_h);
    cudaGetSymbolAddress((void**)&hn,  g_hn);
    cudaGetSymbolAddress((void**)&gt,  g_gt);
    cudaGetSymbolAddress((void**)&ut,  g_ut);
    cudaGetSymbolAddress((void**)&act, g_act);
    cudaGetSymbolAddress((void**)&twt, g_twt);
    cudaGetSymbolAddress((void**)&cnt, g_cnt);
    cudaGetSymbolAddress((void**)&tok, g_tok);

    cudaFuncSetAttribute(gemm_tc<1>, cudaFuncAttributeMaxDynamicSharedMemorySize, SMEM1);
    cudaFuncSetAttribute(gemm_bf3,   cudaFuncAttributeMaxDynamicSharedMemorySize, SMEMBF3);
    cudaFuncSetAttribute(flash_tc,   cudaFuncAttributeMaxDynamicSharedMemorySize, SMEMF);

    // side stream + fork/join events (created per call; ~3 calls total, no frees needed)
    cudaStream_t s0 = 0, s1;
    cudaStreamCreateWithFlags(&s1, cudaStreamNonBlocking);
    cudaEvent_t ev0, ev1, ev2, ev3;
    cudaEventCreateWithFlags(&ev0, cudaEventDisableTiming);
    cudaEventCreateWithFlags(&ev1, cudaEventDisableTiming);
    cudaEventCreateWithFlags(&ev2, cudaEventDisableTiming);
    cudaEventCreateWithFlags(&ev3, cudaEventDisableTiming);

    const size_t TI = (size_t)TK * II;

    // ---- MLA attention ----
    rms_k<<<TK, 256, 0, s0>>>(x, ln1, xi, HH);
    cudaEventRecord(ev0, s0);
    cudaStreamWaitEvent(s1, ev0, 0);

    // q-chain on s0
    cudaMemsetAsync(cq, 0, (size_t)TK * 128 * sizeof(float), s0);
    GB(s0, xi, HH, q_down, 128, cq, 128, TK, 128, HH, nullptr, 4);
    rms_k<<<TK, 128, 0, s0>>>(cq, q_norm, cq, 128);
    GB(s0, cq, 128, w_uq, 512, qn, 512, TK, 512, 128, nullptr, 1);
    GB(s0, cq, 128, w_qr, 512, qr, 512, TK, 512, 128, nullptr, 1);

    // kv-chain on s1
    cudaMemsetAsync(ckv, 0, (size_t)TK * 128 * sizeof(float), s1);
    GB(s1, xi, HH, kv_down, 128, ckv, 128, TK, 128, HH, nullptr, 4);
    rms_k<<<TK, 128, 0, s1>>>(ckv, kv_norm, ckv, 128);
    GB(s1, ckv, 128, w_uk, 512, kn, 512, TK, 512, 128, nullptr, 1);
    GB(s1, ckv, 128, w_ur, 512, kr, 512, TK, 512, 128, nullptr, 1);
    GB(s1, ckv, 128, w_uv, 1024, vx, 1024, TK, 1024, 128, nullptr, 1);
    cudaEventRecord(ev1, s1);
    cudaStreamWaitEvent(s0, ev1, 0);

    assemble_k<<<(BHN * SS * 64) / 256, 256, 0, s0>>>(qn, qr, kn, kr, cosp, sinp, q, k);
    flash_tc<<<dim3(SS / 64, BHN), 128, SMEMF, s0>>>(q, k, vx, maskp, o);
    GB(s0, o, HH, o_proj, HH, h, HH, TK, HH, HH, x, 1);   // h = x + o@Wo

    // ---- MoE ----
    rms_k<<<TK, 256, 0, s0>>>(h, ln2, hn, HH);
    cudaMemsetAsync(cnt, 0, NE * sizeof(int), s0);
    router_k<<<TK, 128, 0, s0>>>(hn, router_w, router_b, cnt, tok, twt);
    cudaMemcpyAsync(out, h, (size_t)TK * HH * sizeof(float), cudaMemcpyDeviceToDevice, s0);
    cudaEventRecord(ev2, s0);
    cudaStreamWaitEvent(s1, ev2, 0);

    // shared experts on s0 (dense, z=2): scratch region [0, 2*TI)
    G1(s0, hn, HH, 0,  sh_gate, II, (size_t)HH * II,  gt, II, TI,  TK, II, HH, 2,
       nullptr, 0, 0, nullptr, nullptr, 0, nullptr);
    G1(s0, hn, HH, 0,  sh_up, II, (size_t)HH * II,  ut, II, TI,  TK, II, HH, 2,
       nullptr, 0, 0, nullptr, nullptr, 0, nullptr);
    silu_mul_k<<<(2 * (int)TI + 255) / 256, 256, 0, s0>>>(gt, ut, act, 2 * (int)TI);
    G1(s0, act, II, TI,  sh_down, HH, (size_t)II * HH,  out, HH, 0,  TK, HH, II, 2,
       nullptr, 0, 0, nullptr, nullptr, 1, nullptr);

    // routed experts on s1 (sparse compact rows, z=8): scratch region [2*TI, 10*TI)
    float* gt2 = gt + 2 * TI;
    float* ut2 = ut + 2 * TI;
    float* act2 = act + 2 * TI;
    G1(s1, hn, HH, 0,  r_gate, II, (size_t)HH * II,  gt2, II, TI,  TK, II, HH, NE,
       tok, 1, 0, nullptr, nullptr, 0, cnt);
    G1(s1, hn, HH, 0,  r_up, II, (size_t)HH * II,  ut2, II, TI,  TK, II, HH, NE,
       tok, 1, 0, nullptr, nullptr, 0, cnt);
    silu_mul_k<<<(NE * (int)TI + 255) / 256, 256, 0, s1>>>(gt2, ut2, act2, NE * (int)TI);
    G1(s1, act2, II, TI,  r_down, HH, (size_t)II * HH,  out, HH, 0,  TK, HH, II, NE,
       tok, 0, 1, twt, nullptr, 0, cnt);
    cudaEventRecord(ev3, s1);
    cudaStreamWaitEvent(s0, ev3, 0);

    usage_k<<<1, NE, 0, s0>>>(cnt, out + (size_t)TK * HH);
}

// round 8
// speedup vs baseline: 4.9888x; 1.2635x over previous
#include <cuda_runtime.h>
#include <math.h>
#include <stdint.h>

// ---------------- problem constants ----------------
#define TK   4096      // tokens = B*S
#define HH   1024      // hidden
#define SS   2048      // seq len
#define NHH  16        // heads
#define BHN  32        // B*NH
#define II   384       // expert intermediate
#define NE   8         // routed experts

// ---------------- scratch (device globals; no allocation allowed) ----------------
__device__ float g_xi [TK*HH];
__device__ float g_cq [TK*128];
__device__ float g_ckv[TK*128];
__device__ float g_qn [TK*512];
__device__ float g_qr [TK*512];
__device__ float g_kn [TK*512];
__device__ float g_kr [TK*512];
__device__ float g_vx [TK*HH];
__device__ float g_q  [TK*HH];   // [bh][s][64]
__device__ float g_k  [TK*HH];
__device__ float g_o  [TK*HH];   // [b][s][h*64+d]
__device__ float g_h  [TK*HH];
__device__ float g_hn [TK*HH];
// MoE scratch: shared experts use [0, 2*TK*II), routed use [2*TK*II, 10*TK*II)
__device__ float g_gt [(NE+2)*TK*II];
__device__ float g_ut [(NE+2)*TK*II];
__device__ float g_act[(NE+2)*TK*II];
__device__ int   g_cnt[NE];
__device__ int   g_tok[NE*TK];
__device__ float g_twt[NE*TK];

// ---------------- mma helpers ----------------
__device__ __forceinline__ uint32_t f2tf(float f) {
    uint32_t r;
    asm("cvt.rna.tf32.f32 %0, %1;" : "=r"(r) : "f"(f));
    return r;
}
__device__ __forceinline__ void mma8(float* c, const uint32_t* a, const uint32_t* b) {
    asm volatile(
        "mma.sync.aligned.m16n8k8.row.col.f32.tf32.tf32.f32 "
        "{%0,%1,%2,%3}, {%4,%5,%6,%7}, {%8,%9}, {%0,%1,%2,%3};\n"
        : "+f"(c[0]), "+f"(c[1]), "+f"(c[2]), "+f"(c[3])
        : "r"(a[0]), "r"(a[1]), "r"(a[2]), "r"(a[3]), "r"(b[0]), "r"(b[1]));
}

// ---------------- tf32 GEMM (1 pass) ----------------
// C = A@B with options: per-z expert offsets, gather/scatter via token lists,
// per-row scale (atomic), accumulate (atomic), fused addsrc, dynamic M, split-K.
// When splitK>1: blockIdx.z = K-chunk index, epilogue atomicAdd into zeroed C.
__global__ void __launch_bounds__(256, 2) gemm_tc(
    const float* __restrict__ A, int lda, size_t eastride,
    const float* __restrict__ B, int ldb, size_t ebstride,
    float* __restrict__ C, int ldc, size_t ecstride,
    int M, int N, int K,
    const int* __restrict__ tokBase, int gatherA, int scatterC,
    const float* __restrict__ wtBase,
    const float* __restrict__ addsrc, int accAtomic,
    const int* __restrict__ cntBase, int splitK)
{
    constexpr int ASTR = 20;
    constexpr int BSTR = 136;
    constexpr int ASZ = 128 * ASTR;
    constexpr int BSZ = 16 * BSTR;

    extern __shared__ uint32_t smem_u[];
    uint32_t* As = smem_u;
    uint32_t* Bs = smem_u + 2 * ASZ;
    int* idxs = (int*)(smem_u + 2 * (ASZ + BSZ));

    int e, kbase, Ke;
    if (splitK > 1) { e = 0; Ke = K / splitK; kbase = blockIdx.z * Ke; }
    else            { e = blockIdx.z; Ke = K; kbase = 0; }

    A += (size_t)e * eastride;
    B += (size_t)e * ebstride;
    C += (size_t)e * ecstride;
    const int* idx = tokBase ? tokBase + (size_t)e * TK : nullptr;
    const float* wt = wtBase ? wtBase + (size_t)e * TK : nullptr;
    const int effM = cntBase ? cntBase[e] : M;

    const int m0 = blockIdx.y * 128;
    const int n0 = blockIdx.x * 128;
    if (m0 >= effM) return;

    const int tid = threadIdx.x;
    if (idx) {
        for (int i = tid; i < 128; i += 256) {
            int m = m0 + i;
            idxs[i] = (m < effM) ? idx[m] : 0;
        }
    }
    __syncthreads();

    auto loadTile = [&](int buf, int kt) {
        uint32_t* Ad = As + buf * ASZ;
        #pragma unroll
        for (int i = 0; i < 8; i++) {
            int flat = tid + i * 256;
            int m = flat >> 4, k = flat & 15;
            float v = 0.f;
            int mg = m0 + m;
            if (mg < effM) {
                int row = gatherA ? idxs[m] : mg;
                v = A[(size_t)row * lda + kt + k];
            }
            Ad[m * ASTR + k] = f2tf(v);
        }
        uint32_t* Bd = Bs + buf * BSZ;
        #pragma unroll
        for (int i = 0; i < 8; i++) {
            int flat = tid + i * 256;
            int n = flat & 127, k = flat >> 7;
            Bd[k * BSTR + n] = f2tf(B[(size_t)(kt + k) * ldb + n0 + n]);
        }
    };

    const int lane = tid & 31, wid = tid >> 5;
    const int wm = (wid >> 2) * 64;
    const int wn = (wid & 3) * 32;
    const int g = lane >> 2, c = lane & 3;

    float acc[4][4][4];
    #pragma unroll
    for (int i = 0; i < 4; i++)
        #pragma unroll
        for (int j = 0; j < 4; j++)
            #pragma unroll
            for (int r = 0; r < 4; r++) acc[i][j][r] = 0.f;

    loadTile(0, kbase);
    __syncthreads();

    const int nkt = Ke >> 4;
    for (int t = 0; t < nkt; t++) {
        int cur = t & 1;
        if (t + 1 < nkt) loadTile(cur ^ 1, kbase + ((t + 1) << 4));

        const uint32_t* Ab = As + cur * ASZ;
        const uint32_t* Bb = Bs + cur * BSZ;
        #pragma unroll
        for (int ks = 0; ks < 16; ks += 8) {
            uint32_t af[4][4];
            #pragma unroll
            for (int mt = 0; mt < 4; mt++) {
                int mb = wm + mt * 16;
                af[mt][0] = Ab[(mb + g) * ASTR + ks + c];
                af[mt][1] = Ab[(mb + g + 8) * ASTR + ks + c];
                af[mt][2] = Ab[(mb + g) * ASTR + ks + c + 4];
                af[mt][3] = Ab[(mb + g + 8) * ASTR + ks + c + 4];
            }
            uint32_t bf[4][2];
            #pragma unroll
            for (int nt = 0; nt < 4; nt++) {
                int nb = wn + nt * 8;
                bf[nt][0] = Bb[(ks + c) * BSTR + nb + g];
                bf[nt][1] = Bb[(ks + c + 4) * BSTR + nb + g];
            }
            #pragma unroll
            for (int mt = 0; mt < 4; mt++)
                #pragma unroll
                for (int nt = 0; nt < 4; nt++)
                    mma8(acc[mt][nt], af[mt], bf[nt]);
        }
        __syncthreads();
    }

    #pragma unroll
    for (int mt = 0; mt < 4; mt++) {
        #pragma unroll
        for (int h2 = 0; h2 < 2; h2++) {
            int ml = wm + mt * 16 + g + h2 * 8;
            int m = m0 + ml;
            if (m >= effM) continue;
            int crow = scatterC ? idxs[ml] : m;
            float sc = wt ? wt[m] : 1.f;
            #pragma unroll
            for (int nt = 0; nt < 4; nt++) {
                int ncol = n0 + wn + nt * 8 + c * 2;
                float v0 = acc[mt][nt][h2 * 2 + 0];
                float v1 = acc[mt][nt][h2 * 2 + 1];
                float* cp = C + (size_t)crow * ldc + ncol;
                if (splitK > 1) {
                    atomicAdd(cp, v0); atomicAdd(cp + 1, v1);
                } else if (wt) {
                    atomicAdd(cp, sc * v0); atomicAdd(cp + 1, sc * v1);
                } else if (accAtomic) {
                    atomicAdd(cp, v0); atomicAdd(cp + 1, v1);
                } else if (addsrc) {
                    const float* ap = addsrc + (size_t)m * ldc + ncol;
                    cp[0] = v0 + ap[0]; cp[1] = v1 + ap[1];
                } else {
                    cp[0] = v0; cp[1] = v1;
                }
            }
        }
    }
}

// ---------------- RMSNorm ----------------
__global__ void rms_k(const float* __restrict__ x, const float* __restrict__ w,
                      float* __restrict__ y, int D)
{
    int t = blockIdx.x;
    const float* xr = x + (size_t)t * D;
    float* yr = y + (size_t)t * D;
    float ss = 0.f;
    for (int k = threadIdx.x; k < D; k += blockDim.x) { float v = xr[k]; ss += v * v; }
    __shared__ float sh[32];
    int lane = threadIdx.x & 31, wid = threadIdx.x >> 5;
    #pragma unroll
    for (int o = 16; o > 0; o >>= 1) ss += __shfl_xor_sync(0xffffffffu, ss, o);
    if (lane == 0) sh[wid] = ss;
    __syncthreads();
    if (threadIdx.x == 0) {
        float tot = 0.f;
        int nw = blockDim.x >> 5;
        for (int i = 0; i < nw; i++) tot += sh[i];
        sh[0] = tot;
    }
    __syncthreads();
    float r = rsqrtf(sh[0] / (float)D + 1e-5f);
    for (int k = threadIdx.x; k < D; k += blockDim.x) yr[k] = w[k] * xr[k] * r;
}

// ---------------- assemble Q/K with RoPE ----------------
__global__ void assemble_k(const float* __restrict__ qn, const float* __restrict__ qr,
                           const float* __restrict__ kn, const float* __restrict__ kr,
                           const float* __restrict__ cosp, const float* __restrict__ sinp,
                           float* __restrict__ Q, float* __restrict__ K)
{
    int idx = blockIdx.x * blockDim.x + threadIdx.x;
    if (idx >= BHN * SS * 64) return;
    int d  = idx & 63;
    int s  = (idx >> 6) & (SS - 1);
    int bh = idx >> 17;
    int b  = bh >> 4, h = bh & 15;
    int t  = b * SS + s;
    float qv, kv;
    if (d < 32) {
        qv = qn[(size_t)t * 512 + h * 32 + d];
        kv = kn[(size_t)t * 512 + h * 32 + d];
    } else {
        int j = d - 32;
        float cc = cosp[s * 32 + j];
        float sn = sinp[s * 32 + j];
        float q1 = qr[(size_t)t * 512 + h * 32 + j];
        float q2 = (j < 16) ? -qr[(size_t)t * 512 + h * 32 + j + 16]
                            :  qr[(size_t)t * 512 + h * 32 + j - 16];
        qv = q1 * cc + q2 * sn;
        float k1 = kr[(size_t)t * 512 + h * 32 + j];
        float k2 = (j < 16) ? -kr[(size_t)t * 512 + h * 32 + j + 16]
                            :  kr[(size_t)t * 512 + h * 32 + j - 16];
        kv = k1 * cc + k2 * sn;
    }
    Q[idx] = qv;
    K[idx] = kv;
}

// ---------------- flash attention, tf32 tensor cores ----------------
#define QSTR 68
#define FSTR 72
__global__ void __launch_bounds__(128) flash_tc(
    const float* __restrict__ Q, const float* __restrict__ Kg,
    const float* __restrict__ Vx, const float* __restrict__ maskp,
    float* __restrict__ O)
{
    extern __shared__ uint32_t sm[];
    uint32_t* Qs = sm;
    uint32_t* KP = sm + 64 * QSTR;
    uint32_t* Vs = KP + 64 * FSTR;

    const int bh = blockIdx.y;
    const int q0 = blockIdx.x * 64;
    const int b  = bh >> 4, hh = bh & 15;
    const float* Qb = Q  + (size_t)bh * SS * 64;
    const float* Kb = Kg + (size_t)bh * SS * 64;
    const float* Vb = Vx + (size_t)b * SS * HH + hh * 64;

    const int tid = threadIdx.x;
    const int w = tid >> 5, lane = tid & 31;
    const int g = lane >> 2, c = lane & 3;
    const int wrow = w * 16;

    const int lr  = tid & 63;
    const int lc0 = (tid >> 6) * 32;

    {
        const float4* src = (const float4*)(Qb + (size_t)(q0 + lr) * 64 + lc0);
        #pragma unroll
        for (int i = 0; i < 8; i++) {
            float4 v = src[i];
            uint32_t* d = Qs + lr * QSTR + lc0 + i * 4;
            d[0] = f2tf(v.x); d[1] = f2tf(v.y); d[2] = f2tf(v.z); d[3] = f2tf(v.w);
        }
    }

    float oacc[8][4];
    #pragma unroll
    for (int nf = 0; nf < 8; nf++)
        #pragma unroll
        for (int r = 0; r < 4; r++) oacc[nf][r] = 0.f;
    float m0 = -1e30f, m1 = -1e30f, l0 = 0.f, l1 = 0.f;

    const float* mr0 = maskp + (size_t)(q0 + wrow + g) * SS;
    const float* mr1 = mr0 + 8 * SS;

    for (int k0 = 0; k0 < SS; k0 += 64) {
        __syncthreads();
        {
            const float4* ks = (const float4*)(Kb + (size_t)(k0 + lr) * 64 + lc0);
            const float4* vs = (const float4*)(Vb + (size_t)(k0 + lr) * HH + lc0);
            #pragma unroll
            for (int i = 0; i < 8; i++) {
                float4 kv = ks[i];
                int d = lc0 + i * 4;
                KP[(d + 0) * FSTR + lr] = f2tf(kv.x);
                KP[(d + 1) * FSTR + lr] = f2tf(kv.y);
                KP[(d + 2) * FSTR + lr] = f2tf(kv.z);
                KP[(d + 3) * FSTR + lr] = f2tf(kv.w);
                float4 vv = vs[i];
                uint32_t* vd = Vs + lr * FSTR + d;
                vd[0] = f2tf(vv.x); vd[1] = f2tf(vv.y); vd[2] = f2tf(vv.z); vd[3] = f2tf(vv.w);
            }
        }
        __syncthreads();

        float sacc[8][4];
        #pragma unroll
        for (int nf = 0; nf < 8; nf++)
            #pragma unroll
            for (int r = 0; r < 4; r++) sacc[nf][r] = 0.f;
        #pragma unroll
        for (int ks = 0; ks < 64; ks += 8) {
            uint32_t af[4];
            af[0] = Qs[(wrow + g) * QSTR + ks + c];
            af[1] = Qs[(wrow + g + 8) * QSTR + ks + c];
            af[2] = Qs[(wrow + g) * QSTR + ks + c + 4];
            af[3] = Qs[(wrow + g + 8) * QSTR + ks + c + 4];
            #pragma unroll
            for (int nf = 0; nf < 8; nf++) {
                uint32_t bf[2];
                bf[0] = KP[(ks + c) * FSTR + nf * 8 + g];
                bf[1] = KP[(ks + c + 4) * FSTR + nf * 8 + g];
                mma8(sacc[nf], af, bf);
            }
        }

        float mx0 = -1e30f, mx1 = -1e30f;
        #pragma unroll
        for (int nf = 0; nf < 8; nf++) {
            float2 mk0 = *(const float2*)(mr0 + k0 + nf * 8 + 2 * c);
            float2 mk1 = *(const float2*)(mr1 + k0 + nf * 8 + 2 * c);
            sacc[nf][0] = sacc[nf][0] * 0.125f + mk0.x;
            sacc[nf][1] = sacc[nf][1] * 0.125f + mk0.y;
            sacc[nf][2] = sacc[nf][2] * 0.125f + mk1.x;
            sacc[nf][3] = sacc[nf][3] * 0.125f + mk1.y;
            mx0 = fmaxf(mx0, fmaxf(sacc[nf][0], sacc[nf][1]));
            mx1 = fmaxf(mx1, fmaxf(sacc[nf][2], sacc[nf][3]));
        }
        mx0 = fmaxf(mx0, __shfl_xor_sync(0xffffffffu, mx0, 1));
        mx0 = fmaxf(mx0, __shfl_xor_sync(0xffffffffu, mx0, 2));
        mx1 = fmaxf(mx1, __shfl_xor_sync(0xffffffffu, mx1, 1));
        mx1 = fmaxf(mx1, __shfl_xor_sync(0xffffffffu, mx1, 2));

        float mn0 = fmaxf(m0, mx0), mn1 = fmaxf(m1, mx1);
        float cr0 = __expf(m0 - mn0), cr1 = __expf(m1 - mn1);
        m0 = mn0; m1 = mn1;
        float rs0 = 0.f, rs1 = 0.f;
        #pragma unroll
        for (int nf = 0; nf < 8; nf++) {
            sacc[nf][0] = __expf(sacc[nf][0] - mn0);
            sacc[nf][1] = __expf(sacc[nf][1] - mn0);
            sacc[nf][2] = __expf(sacc[nf][2] - mn1);
            sacc[nf][3] = __expf(sacc[nf][3] - mn1);
            rs0 += sacc[nf][0] + sacc[nf][1];
            rs1 += sacc[nf][2] + sacc[nf][3];
        }
        rs0 += __shfl_xor_sync(0xffffffffu, rs0, 1);
        rs0 += __shfl_xor_sync(0xffffffffu, rs0, 2);
        rs1 += __shfl_xor_sync(0xffffffffu, rs1, 1);
        rs1 += __shfl_xor_sync(0xffffffffu, rs1, 2);
        l0 = l0 * cr0 + rs0;
        l1 = l1 * cr1 + rs1;
        #pragma unroll
        for (int nf = 0; nf < 8; nf++) {
            oacc[nf][0] *= cr0; oacc[nf][1] *= cr0;
            oacc[nf][2] *= cr1; oacc[nf][3] *= cr1;
        }

        __syncthreads();
        #pragma unroll
        for (int nf = 0; nf < 8; nf++) {
            int col = nf * 8 + 2 * c;
            KP[(wrow + g) * FSTR + col]     = f2tf(sacc[nf][0]);
            KP[(wrow + g) * FSTR + col + 1] = f2tf(sacc[nf][1]);
            KP[(wrow + g + 8) * FSTR + col]     = f2tf(sacc[nf][2]);
            KP[(wrow + g + 8) * FSTR + col + 1] = f2tf(sacc[nf][3]);
        }
        __syncthreads();

        #pragma unroll
        for (int kk = 0; kk < 64; kk += 8) {
            uint32_t af[4];
            af[0] = KP[(wrow + g) * FSTR + kk + c];
            af[1] = KP[(wrow + g + 8) * FSTR + kk + c];
            af[2] = KP[(wrow + g) * FSTR + kk + c + 4];
            af[3] = KP[(wrow + g + 8) * FSTR + kk + c + 4];
            #pragma unroll
            for (int nf = 0; nf < 8; nf++) {
                uint32_t bf[2];
                bf[0] = Vs[(kk + c) * FSTR + nf * 8 + g];
                bf[1] = Vs[(kk + c + 4) * FSTR + nf * 8 + g];
                mma8(oacc[nf], af, bf);
            }
        }
    }

    float inv0 = 1.f / l0, inv1 = 1.f / l1;
    int row0 = q0 + wrow + g;
    float* o0 = O + ((size_t)(b * SS + row0)) * HH + hh * 64;
    float* o1 = o0 + 8 * (size_t)HH;
    #pragma unroll
    for (int nf = 0; nf < 8; nf++) {
        int col = nf * 8 + 2 * c;
        float2 v0 = make_float2(oacc[nf][0] * inv0, oacc[nf][1] * inv0);
        float2 v1 = make_float2(oacc[nf][2] * inv1, oacc[nf][3] * inv1);
        *(float2*)(o0 + col) = v0;
        *(float2*)(o1 + col) = v1;
    }
}

// ---------------- router ----------------
__global__ void router_k(const float* __restrict__ hn, const float* __restrict__ rw,
                         const float* __restrict__ rb,
                         int* __restrict__ cnt, int* __restrict__ tok, float* __restrict__ twt)
{
    int t = blockIdx.x;
    __shared__ float red[128][NE];
    float accv[NE];
    #pragma unroll
    for (int e = 0; e < NE; e++) accv[e] = 0.f;
    const float* xr = hn + (size_t)t * HH;
    for (int k = threadIdx.x; k < HH; k += 128) {
        float xv = xr[k];
        const float* w = rw + (size_t)k * NE;
        #pragma unroll
        for (int e = 0; e < NE; e++) accv[e] += xv * w[e];
    }
    #pragma unroll
    for (int e = 0; e < NE; e++) red[threadIdx.x][e] = accv[e];
    __syncthreads();
    for (int s = 64; s > 0; s >>= 1) {
        if (threadIdx.x < s)
            #pragma unroll
            for (int e = 0; e < NE; e++) red[threadIdx.x][e] += red[threadIdx.x + s][e];
        __syncthreads();
    }
    if (threadIdx.x == 0) {
        float p[NE];
        #pragma unroll
        for (int e = 0; e < NE; e++) {
            float lg = red[0][e] + rb[e];
            p[e] = 1.f / (1.f + expf(-lg));
        }
        int e1 = 0;
        for (int e = 1; e < NE; e++) if (p[e] > p[e1]) e1 = e;
        int e2 = -1;
        for (int e = 0; e < NE; e++) if (e != e1 && (e2 < 0 || p[e] > p[e2])) e2 = e;
        float s2 = p[e1] + p[e2];
        float w1 = p[e1] / s2, w2 = p[e2] / s2;
        int a = atomicAdd(&cnt[e1], 1); tok[e1 * TK + a] = t; twt[e1 * TK + a] = w1;
        int b = atomicAdd(&cnt[e2], 1); tok[e2 * TK + b] = t; twt[e2 * TK + b] = w2;
    }
}

__global__ void silu_mul_k(const float* __restrict__ g, const float* __restrict__ u,
                           float* __restrict__ y, int n)
{
    int i = blockIdx.x * 256 + threadIdx.x;
    if (i < n) {
        float gv = g[i];
        y[i] = (gv / (1.f + expf(-gv))) * u[i];
    }
}

// routed-expert variant: skip rows beyond cnt[e]
__global__ void silu_mul_moe(const float* __restrict__ g, const float* __restrict__ u,
                             float* __restrict__ y, const int* __restrict__ cnt)
{
    const size_t TI = (size_t)TK * II;
    int e = blockIdx.y;
    int i = blockIdx.x * 256 + threadIdx.x;
    if (i / II >= cnt[e]) return;
    size_t idx = (size_t)e * TI + i;
    float gv = g[idx];
    y[idx] = (gv / (1.f + expf(-gv))) * u[idx];
}

__global__ void usage_k(const int* __restrict__ cnt, float* __restrict__ out)
{
    int e = threadIdx.x;
    if (e < NE) out[e] = (float)cnt[e];
}

// ---------------- host-side dispatch ----------------
static const int SMEM1 = (2 * (2560 + 2176) + 128) * 4;       // 38400
static const int SMEMF = (64 * QSTR + 2 * 64 * FSTR) * 4;     // 54272

static void G1(cudaStream_t st,
               const float* A, int lda, size_t eas,
               const float* B, int ldb, size_t ebs,
               float* C, int ldc, size_t ecs,
               int M, int N, int K, int nz,
               const int* tokB, int ga, int sc,
               const float* wtB, const float* adds, int accA,
               const int* cntB, int splitK = 1)
{
    dim3 grid(N / 128, (M + 127) / 128, (splitK > 1) ? splitK : nz);
    gemm_tc<<<grid, 256, SMEM1, st>>>(A, lda, eas, B, ldb, ebs, C, ldc, ecs,
                                      M, N, K, tokB, ga, sc, wtB, adds, accA,
                                      cntB, splitK);
}

extern "C" void kernel_launch(void* const* d_in, const int* in_sizes, int n_in,
                              void* d_out, int out_size)
{
    const float* x        = (const float*)d_in[0];
    const float* cosp     = (const float*)d_in[1];
    const float* sinp     = (const float*)d_in[2];
    const float* maskp    = (const float*)d_in[3];
    const float* ln1      = (const float*)d_in[4];
    const float* ln2      = (const float*)d_in[5];
    const float* kv_down  = (const float*)d_in[6];
    const float* kv_norm  = (const float*)d_in[7];
    const float* w_uk     = (const float*)d_in[8];
    const float* w_ur     = (const float*)d_in[9];
    const float* w_uv     = (const float*)d_in[10];
    const float* q_down   = (const float*)d_in[11];
    const float* q_norm   = (const float*)d_in[12];
    const float* w_uq     = (const float*)d_in[13];
    const float* w_qr     = (const float*)d_in[14];
    const float* o_proj   = (const float*)d_in[15];
    const float* sh_gate  = (const float*)d_in[16];
    const float* sh_up    = (const float*)d_in[17];
    const float* sh_down  = (const float*)d_in[18];
    const float* r_gate   = (const float*)d_in[19];
    const float* r_up     = (const float*)d_in[20];
    const float* r_down   = (const float*)d_in[21];
    const float* router_w = (const float*)d_in[22];
    const float* router_b = (const float*)d_in[23];
    float* out = (float*)d_out;

    float *xi, *cq, *ckv, *qn, *qr, *kn, *kr, *vx, *q, *k, *o, *h, *hn, *gt, *ut, *act, *twt;
    int *cnt, *tok;
    cudaGetSymbolAddress((void**)&xi,  g_xi);
    cudaGetSymbolAddress((void**)&cq,  g_cq);
    cudaGetSymbolAddress((void**)&ckv, g_ckv);
    cudaGetSymbolAddress((void**)&qn,  g_qn);
    cudaGetSymbolAddress((void**)&qr,  g_qr);
    cudaGetSymbolAddress((void**)&kn,  g_kn);
    cudaGetSymbolAddress((void**)&kr,  g_kr);
    cudaGetSymbolAddress((void**)&vx,  g_vx);
    cudaGetSymbolAddress((void**)&q,   g_q);
    cudaGetSymbolAddress((void**)&k,   g_k);
    cudaGetSymbolAddress((void**)&o,   g_o);
    cudaGetSymbolAddress((void**)&h,   g_h);
    cudaGetSymbolAddress((void**)&hn,  g_hn);
    cudaGetSymbolAddress((void**)&gt,  g_gt);
    cudaGetSymbolAddress((void**)&ut,  g_ut);
    cudaGetSymbolAddress((void**)&act, g_act);
    cudaGetSymbolAddress((void**)&twt, g_twt);
    cudaGetSymbolAddress((void**)&cnt, g_cnt);
    cudaGetSymbolAddress((void**)&tok, g_tok);

    cudaFuncSetAttribute(gemm_tc,  cudaFuncAttributeMaxDynamicSharedMemorySize, SMEM1);
    cudaFuncSetAttribute(flash_tc, cudaFuncAttributeMaxDynamicSharedMemorySize, SMEMF);

    cudaStream_t s0 = 0, s1;
    cudaStreamCreateWithFlags(&s1, cudaStreamNonBlocking);
    cudaEvent_t ev0, ev1, ev2, ev3;
    cudaEventCreateWithFlags(&ev0, cudaEventDisableTiming);
    cudaEventCreateWithFlags(&ev1, cudaEventDisableTiming);
    cudaEventCreateWithFlags(&ev2, cudaEventDisableTiming);
    cudaEventCreateWithFlags(&ev3, cudaEventDisableTiming);

    const size_t TI = (size_t)TK * II;

    // ---- MLA attention (all tf32 1-pass; o@Wo term is ~0.003 of |out|) ----
    rms_k<<<TK, 256, 0, s0>>>(x, ln1, xi, HH);
    cudaEventRecord(ev0, s0);
    cudaStreamWaitEvent(s1, ev0, 0);

    // q-chain on s0
    cudaMemsetAsync(cq, 0, (size_t)TK * 128 * sizeof(float), s0);
    G1(s0, xi, HH, 0,  q_down, 128, 0,  cq, 128, 0,  TK, 128, HH, 1,
       nullptr, 0, 0, nullptr, nullptr, 0, nullptr, 4);
    rms_k<<<TK, 128, 0, s0>>>(cq, q_norm, cq, 128);
    G1(s0, cq, 128, 0,  w_uq, 512, 0,  qn, 512, 0,  TK, 512, 128, 1,
       nullptr, 0, 0, nullptr, nullptr, 0, nullptr);
    G1(s0, cq, 128, 0,  w_qr, 512, 0,  qr, 512, 0,  TK, 512, 128, 1,
       nullptr, 0, 0, nullptr, nullptr, 0, nullptr);

    // kv-chain on s1
    cudaMemsetAsync(ckv, 0, (size_t)TK * 128 * sizeof(float), s1);
    G1(s1, xi, HH, 0,  kv_down, 128, 0,  ckv, 128, 0,  TK, 128, HH, 1,
       nullptr, 0, 0, nullptr, nullptr, 0, nullptr, 4);
    rms_k<<<TK, 128, 0, s1>>>(ckv, kv_norm, ckv, 128);
    G1(s1, ckv, 128, 0,  w_uk, 512, 0,  kn, 512, 0,  TK, 512, 128, 1,
       nullptr, 0, 0, nullptr, nullptr, 0, nullptr);
    G1(s1, ckv, 128, 0,  w_ur, 512, 0,  kr, 512, 0,  TK, 512, 128, 1,
       nullptr, 0, 0, nullptr, nullptr, 0, nullptr);
    G1(s1, ckv, 128, 0,  w_uv, 1024, 0,  vx, 1024, 0,  TK, 1024, 128, 1,
       nullptr, 0, 0, nullptr, nullptr, 0, nullptr);
    cudaEventRecord(ev1, s1);
    cudaStreamWaitEvent(s0, ev1, 0);

    assemble_k<<<(BHN * SS * 64) / 256, 256, 0, s0>>>(qn, qr, kn, kr, cosp, sinp, q, k);
    flash_tc<<<dim3(SS / 64, BHN), 128, SMEMF, s0>>>(q, k, vx, maskp, o);
    G1(s0, o, HH, 0,  o_proj, HH, 0,  h, HH, 0,  TK, HH, HH, 1,
       nullptr, 0, 0, nullptr, x, 0, nullptr);   // h = x + o@Wo

    // ---- MoE ----
    rms_k<<<TK, 256, 0, s0>>>(h, ln2, hn, HH);
    cudaMemsetAsync(cnt, 0, NE * sizeof(int), s0);
    router_k<<<TK, 128, 0, s0>>>(hn, router_w, router_b, cnt, tok, twt);
    cudaMemcpyAsync(out, h, (size_t)TK * HH * sizeof(float), cudaMemcpyDeviceToDevice, s0);
    cudaEventRecord(ev2, s0);
    cudaStreamWaitEvent(s1, ev2, 0);

    // shared experts on s0 (dense, z=2): scratch region [0, 2*TI)
    G1(s0, hn, HH, 0,  sh_gate, II, (size_t)HH * II,  gt, II, TI,  TK, II, HH, 2,
       nullptr, 0, 0, nullptr, nullptr, 0, nullptr);
    G1(s0, hn, HH, 0,  sh_up, II, (size_t)HH * II,  ut, II, TI,  TK, II, HH, 2,
       nullptr, 0, 0, nullptr, nullptr, 0, nullptr);
    silu_mul_k<<<(2 * (int)TI + 255) / 256, 256, 0, s0>>>(gt, ut, act, 2 * (int)TI);
    G1(s0, act, II, TI,  sh_down, HH, (size_t)II * HH,  out, HH, 0,  TK, HH, II, 2,
       nullptr, 0, 0, nullptr, nullptr, 1, nullptr);

    // routed experts on s1 (sparse compact rows, z=8): scratch region [2*TI, 10*TI)
    float* gt2 = gt + 2 * TI;
    float* ut2 = ut + 2 * TI;
    float* act2 = act + 2 * TI;
    G1(s1, hn, HH, 0,  r_gate, II, (size_t)HH * II,  gt2, II, TI,  TK, II, HH, NE,
       tok, 1, 0, nullptr, nullptr, 0, cnt);
    G1(s1, hn, HH, 0,  r_up, II, (size_t)HH * II,  ut2, II, TI,  TK, II, HH, NE,
       tok, 1, 0, nullptr, nullptr, 0, cnt);
    silu_mul_moe<<<dim3(((int)TI + 255) / 256, NE), 256, 0, s1>>>(gt2, ut2, act2, cnt);
    G1(s1, act2, II, TI,  r_down, HH, (size_t)II * HH,  out, HH, 0,  TK, HH, II, NE,
       tok, 0, 1, twt, nullptr, 0, cnt);
    cudaEventRecord(ev3, s1);
    cudaStreamWaitEvent(s0, ev3, 0);

    usage_k<<<1, NE, 0, s0>>>(cnt, out + (size_t)TK * HH);
}

// round 10
// speedup vs baseline: 5.6913x; 1.1408x over previous
#include <cuda_runtime.h>
#include <cuda_bf16.h>
#include <math.h>
#include <stdint.h>

// ---------------- problem constants ----------------
#define TK   4096      // tokens = B*S
#define HH   1024      // hidden
#define SS   2048      // seq len
#define NHH  16        // heads
#define BHN  32        // B*NH
#define II   384       // expert intermediate
#define NE   8         // routed experts

// ---------------- scratch ----------------
__device__ float g_xi [TK*HH];
__device__ float g_cq [TK*128];
__device__ float g_ckv[TK*128];
__device__ float g_qn [TK*512];
__device__ float g_qr [TK*512];
__device__ float g_kn [TK*512];
__device__ float g_kr [TK*512];
__device__ float g_vx [TK*HH];
__device__ float g_q  [TK*HH];   // [bh][s][64]
__device__ float g_k  [TK*HH];
__device__ float g_o  [TK*HH];   // [b][s][h*64+d]
__device__ float g_h  [TK*HH];
__device__ float g_hn [TK*HH];
__device__ float g_gt [(NE+2)*TK*II];
__device__ float g_ut [(NE+2)*TK*II];
__device__ float g_act[(NE+2)*TK*II];
__device__ int   g_cnt[NE];
__device__ int   g_tok[NE*TK];
__device__ float g_twt[NE*TK];

// ---------------- mma helpers ----------------
__device__ __forceinline__ uint32_t f2tf(float f) {
    uint32_t r;
    asm("cvt.rna.tf32.f32 %0, %1;" : "=r"(r) : "f"(f));
    return r;
}
__device__ __forceinline__ void mma8(float* c, const uint32_t* a, const uint32_t* b) {
    asm volatile(
        "mma.sync.aligned.m16n8k8.row.col.f32.tf32.tf32.f32 "
        "{%0,%1,%2,%3}, {%4,%5,%6,%7}, {%8,%9}, {%0,%1,%2,%3};\n"
        : "+f"(c[0]), "+f"(c[1]), "+f"(c[2]), "+f"(c[3])
        : "r"(a[0]), "r"(a[1]), "r"(a[2]), "r"(a[3]), "r"(b[0]), "r"(b[1]));
}
__device__ __forceinline__ void mma16(float* c, const uint32_t* a, const uint32_t* b) {
    asm volatile(
        "mma.sync.aligned.m16n8k16.row.col.f32.bf16.bf16.f32 "
        "{%0,%1,%2,%3}, {%4,%5,%6,%7}, {%8,%9}, {%0,%1,%2,%3};\n"
        : "+f"(c[0]), "+f"(c[1]), "+f"(c[2]), "+f"(c[3])
        : "r"(a[0]), "r"(a[1]), "r"(a[2]), "r"(a[3]), "r"(b[0]), "r"(b[1]));
}
__device__ __forceinline__ uint32_t pkbf2(float a, float b) {
    __nv_bfloat162 t = __floats2bfloat162_rn(a, b);
    return *reinterpret_cast<uint32_t*>(&t);
}

// ---------------- bf16 single-pass GEMM (dense; splitK; fused addsrc) ----------------
// Used for everything upstream of the residual add (error attenuated ~300x).
#define GASTR 20
#define GBSTR 136
#define GASZ  (128*GASTR)   // 128 rows x 16 kpairs (BK=32)
#define GBSZ  (16*GBSTR)    // 16 kpairs x 128 n
__global__ void __launch_bounds__(256, 2) gemm_bf(
    const float* __restrict__ A, int lda,
    const float* __restrict__ B, int ldb,
    float* __restrict__ C, int ldc,
    int M, int N, int K,
    const float* __restrict__ addsrc, int splitK)
{
    extern __shared__ uint32_t sm[];
    uint32_t* As = sm;              // [2][GASZ]
    uint32_t* Bs = sm + 2 * GASZ;   // [2][GBSZ]

    const int Ke = K / splitK;
    const int kbase = blockIdx.z * Ke;
    const int m0 = blockIdx.y * 128;
    const int n0 = blockIdx.x * 128;
    const int tid = threadIdx.x;

    auto loadTile = [&](int buf, int kt) {
        uint32_t* Ad = As + buf * GASZ;
        #pragma unroll
        for (int i = 0; i < 8; i++) {
            int flat = tid + i * 256;
            int m = flat >> 4, k2 = flat & 15;
            float2 v = *(const float2*)(A + (size_t)(m0 + m) * lda + kt + 2 * k2);
            Ad[m * GASTR + k2] = pkbf2(v.x, v.y);
        }
        uint32_t* Bd = Bs + buf * GBSZ;
        #pragma unroll
        for (int i = 0; i < 8; i++) {
            int flat = tid + i * 256;
            int n = flat & 127, k2 = flat >> 7;
            float v0 = B[(size_t)(kt + 2 * k2) * ldb + n0 + n];
            float v1 = B[(size_t)(kt + 2 * k2 + 1) * ldb + n0 + n];
            Bd[k2 * GBSTR + n] = pkbf2(v0, v1);
        }
    };

    const int lane = tid & 31, wid = tid >> 5;
    const int wm = (wid >> 2) * 64;
    const int wn = (wid & 3) * 32;
    const int g = lane >> 2, c = lane & 3;

    float acc[4][4][4];
    #pragma unroll
    for (int i = 0; i < 4; i++)
        #pragma unroll
        for (int j = 0; j < 4; j++)
            #pragma unroll
            for (int r = 0; r < 4; r++) acc[i][j][r] = 0.f;

    loadTile(0, kbase);
    __syncthreads();

    const int nbuf = Ke >> 5;
    for (int t = 0; t < nbuf; t++) {
        int cur = t & 1;
        if (t + 1 < nbuf) loadTile(cur ^ 1, kbase + ((t + 1) << 5));

        const uint32_t* Ab = As + cur * GASZ;
        const uint32_t* Bb = Bs + cur * GBSZ;
        #pragma unroll
        for (int kp = 0; kp < 16; kp += 8) {
            uint32_t af[4][4];
            #pragma unroll
            for (int mt = 0; mt < 4; mt++) {
                int mb = wm + mt * 16;
                af[mt][0] = Ab[(mb + g) * GASTR + kp + c];
                af[mt][1] = Ab[(mb + g + 8) * GASTR + kp + c];
                af[mt][2] = Ab[(mb + g) * GASTR + kp + c + 4];
                af[mt][3] = Ab[(mb + g + 8) * GASTR + kp + c + 4];
            }
            uint32_t bf[4][2];
            #pragma unroll
            for (int nt = 0; nt < 4; nt++) {
                int nb = wn + nt * 8;
                bf[nt][0] = Bb[(kp + c) * GBSTR + nb + g];
                bf[nt][1] = Bb[(kp + c + 4) * GBSTR + nb + g];
            }
            #pragma unroll
            for (int mt = 0; mt < 4; mt++)
                #pragma unroll
                for (int nt = 0; nt < 4; nt++)
                    mma16(acc[mt][nt], af[mt], bf[nt]);
        }
        __syncthreads();
    }

    #pragma unroll
    for (int mt = 0; mt < 4; mt++) {
        #pragma unroll
        for (int h2 = 0; h2 < 2; h2++) {
            int m = m0 + wm + mt * 16 + g + h2 * 8;
            #pragma unroll
            for (int nt = 0; nt < 4; nt++) {
                int ncol = n0 + wn + nt * 8 + c * 2;
                float v0 = acc[mt][nt][h2 * 2 + 0];
                float v1 = acc[mt][nt][h2 * 2 + 1];
                float* cp = C + (size_t)m * ldc + ncol;
                if (splitK > 1) {
                    atomicAdd(cp, v0); atomicAdd(cp + 1, v1);
                } else if (addsrc) {
                    const float* ap = addsrc + (size_t)m * ldc + ncol;
                    cp[0] = v0 + ap[0]; cp[1] = v1 + ap[1];
                } else {
                    cp[0] = v0; cp[1] = v1;
                }
            }
        }
    }
}

// ---------------- tf32 GEMM (MoE path: gather/scatter/scale; error-budget holder) ----------------
__global__ void __launch_bounds__(256, 2) gemm_tc(
    const float* __restrict__ A, int lda, size_t eastride,
    const float* __restrict__ B, int ldb, size_t ebstride,
    float* __restrict__ C, int ldc, size_t ecstride,
    int M, int N, int K,
    const int* __restrict__ tokBase, int gatherA, int scatterC,
    const float* __restrict__ wtBase,
    int accAtomic,
    const int* __restrict__ cntBase)
{
    constexpr int ASTR = 20;
    constexpr int BSTR = 136;
    constexpr int ASZ = 128 * ASTR;
    constexpr int BSZ = 16 * BSTR;

    extern __shared__ uint32_t smem_u[];
    uint32_t* As = smem_u;
    uint32_t* Bs = smem_u + 2 * ASZ;
    int* idxs = (int*)(smem_u + 2 * (ASZ + BSZ));

    const int e = blockIdx.z;
    B += (size_t)e * ebstride;
    C += (size_t)e * ecstride;
    const float* Ae = A + (size_t)e * eastride;
    const int* idx = tokBase ? tokBase + (size_t)e * TK : nullptr;
    const float* wt = wtBase ? wtBase + (size_t)e * TK : nullptr;
    const int effM = cntBase ? cntBase[e] : M;

    const int m0 = blockIdx.y * 128;
    const int n0 = blockIdx.x * 128;
    if (m0 >= effM) return;

    const int tid = threadIdx.x;
    if (idx) {
        for (int i = tid; i < 128; i += 256) {
            int m = m0 + i;
            idxs[i] = (m < effM) ? idx[m] : 0;
        }
    }
    __syncthreads();

    auto loadTile = [&](int buf, int kt) {
        uint32_t* Ad = As + buf * ASZ;
        #pragma unroll
        for (int i = 0; i < 8; i++) {
            int flat = tid + i * 256;
            int m = flat >> 4, k = flat & 15;
            float v = 0.f;
            int mg = m0 + m;
            if (mg < effM) {
                int row = gatherA ? idxs[m] : mg;
                v = Ae[(size_t)row * lda + kt + k];
            }
            Ad[m * ASTR + k] = f2tf(v);
        }
        uint32_t* Bd = Bs + buf * BSZ;
        #pragma unroll
        for (int i = 0; i < 8; i++) {
            int flat = tid + i * 256;
            int n = flat & 127, k = flat >> 7;
            Bd[k * BSTR + n] = f2tf(B[(size_t)(kt + k) * ldb + n0 + n]);
        }
    };

    const int lane = tid & 31, wid = tid >> 5;
    const int wm = (wid >> 2) * 64;
    const int wn = (wid & 3) * 32;
    const int g = lane >> 2, c = lane & 3;

    float acc[4][4][4];
    #pragma unroll
    for (int i = 0; i < 4; i++)
        #pragma unroll
        for (int j = 0; j < 4; j++)
            #pragma unroll
            for (int r = 0; r < 4; r++) acc[i][j][r] = 0.f;

    loadTile(0, 0);
    __syncthreads();

    const int nkt = K >> 4;
    for (int t = 0; t < nkt; t++) {
        int cur = t & 1;
        if (t + 1 < nkt) loadTile(cur ^ 1, (t + 1) << 4);

        const uint32_t* Ab = As + cur * ASZ;
        const uint32_t* Bb = Bs + cur * BSZ;
        #pragma unroll
        for (int ks = 0; ks < 16; ks += 8) {
            uint32_t af[4][4];
            #pragma unroll
            for (int mt = 0; mt < 4; mt++) {
                int mb = wm + mt * 16;
                af[mt][0] = Ab[(mb + g) * ASTR + ks + c];
                af[mt][1] = Ab[(mb + g + 8) * ASTR + ks + c];
                af[mt][2] = Ab[(mb + g) * ASTR + ks + c + 4];
                af[mt][3] = Ab[(mb + g + 8) * ASTR + ks + c + 4];
            }
            uint32_t bf[4][2];
            #pragma unroll
            for (int nt = 0; nt < 4; nt++) {
                int nb = wn + nt * 8;
                bf[nt][0] = Bb[(ks + c) * BSTR + nb + g];
                bf[nt][1] = Bb[(ks + c + 4) * BSTR + nb + g];
            }
            #pragma unroll
            for (int mt = 0; mt < 4; mt++)
                #pragma unroll
                for (int nt = 0; nt < 4; nt++)
                    mma8(acc[mt][nt], af[mt], bf[nt]);
        }
        __syncthreads();
    }

    #pragma unroll
    for (int mt = 0; mt < 4; mt++) {
        #pragma unroll
        for (int h2 = 0; h2 < 2; h2++) {
            int ml = wm + mt * 16 + g + h2 * 8;
            int m = m0 + ml;
            if (m >= effM) continue;
            int crow = scatterC ? idxs[ml] : m;
            float sc = wt ? wt[m] : 1.f;
            #pragma unroll
            for (int nt = 0; nt < 4; nt++) {
                int ncol = n0 + wn + nt * 8 + c * 2;
                float v0 = acc[mt][nt][h2 * 2 + 0];
                float v1 = acc[mt][nt][h2 * 2 + 1];
                float* cp = C + (size_t)crow * ldc + ncol;
                if (wt) {
                    atomicAdd(cp, sc * v0); atomicAdd(cp + 1, sc * v1);
                } else if (accAtomic) {
                    atomicAdd(cp, v0); atomicAdd(cp + 1, v1);
                } else {
                    cp[0] = v0; cp[1] = v1;
                }
            }
        }
    }
}

// ---------------- RMSNorm ----------------
__global__ void rms_k(const float* __restrict__ x, const float* __restrict__ w,
                      float* __restrict__ y, int D)
{
    int t = blockIdx.x;
    const float* xr = x + (size_t)t * D;
    float* yr = y + (size_t)t * D;
    float ss = 0.f;
    for (int k = threadIdx.x; k < D; k += blockDim.x) { float v = xr[k]; ss += v * v; }
    __shared__ float sh[32];
    int lane = threadIdx.x & 31, wid = threadIdx.x >> 5;
    #pragma unroll
    for (int o = 16; o > 0; o >>= 1) ss += __shfl_xor_sync(0xffffffffu, ss, o);
    if (lane == 0) sh[wid] = ss;
    __syncthreads();
    if (threadIdx.x == 0) {
        float tot = 0.f;
        int nw = blockDim.x >> 5;
        for (int i = 0; i < nw; i++) tot += sh[i];
        sh[0] = tot;
    }
    __syncthreads();
    float r = rsqrtf(sh[0] / (float)D + 1e-5f);
    for (int k = threadIdx.x; k < D; k += blockDim.x) yr[k] = w[k] * xr[k] * r;
}

// ---------------- assemble Q/K with RoPE ----------------
__global__ void assemble_k(const float* __restrict__ qn, const float* __restrict__ qr,
                           const float* __restrict__ kn, const float* __restrict__ kr,
                           const float* __restrict__ cosp, const float* __restrict__ sinp,
                           float* __restrict__ Q, float* __restrict__ K)
{
    int idx = blockIdx.x * blockDim.x + threadIdx.x;
    if (idx >= BHN * SS * 64) return;
    int d  = idx & 63;
    int s  = (idx >> 6) & (SS - 1);
    int bh = idx >> 17;
    int b  = bh >> 4, h = bh & 15;
    int t  = b * SS + s;
    float qv, kv;
    if (d < 32) {
        qv = qn[(size_t)t * 512 + h * 32 + d];
        kv = kn[(size_t)t * 512 + h * 32 + d];
    } else {
        int j = d - 32;
        float cc = cosp[s * 32 + j];
        float sn = sinp[s * 32 + j];
        float q1 = qr[(size_t)t * 512 + h * 32 + j];
        float q2 = (j < 16) ? -qr[(size_t)t * 512 + h * 32 + j + 16]
                            :  qr[(size_t)t * 512 + h * 32 + j - 16];
        qv = q1 * cc + q2 * sn;
        float k1 = kr[(size_t)t * 512 + h * 32 + j];
        float k2 = (j < 16) ? -kr[(size_t)t * 512 + h * 32 + j + 16]
                            :  kr[(size_t)t * 512 + h * 32 + j - 16];
        kv = k1 * cc + k2 * sn;
    }
    Q[idx] = qv;
    K[idx] = kv;
}

// ---------------- flash attention, bf16 tensor cores ----------------
// smem (u32): Qs[64][36] | Kt[32][72] | Ps[64][36] | Vs[32][72]  = 9216 u32 = 36 KB
#define FQS 36
#define FKS 72
__global__ void __launch_bounds__(128) flash_bf(
    const float* __restrict__ Q, const float* __restrict__ Kg,
    const float* __restrict__ Vx, const float* __restrict__ maskp,
    float* __restrict__ O)
{
    extern __shared__ uint32_t sm[];
    uint32_t* Qs = sm;                       // [row][kpair]  64*36
    uint32_t* Kt = sm + 64 * FQS;            // [kpair][key]  32*72
    uint32_t* Ps = Kt + 32 * FKS;            // [row][keypair] 64*36
    uint32_t* Vs = Ps + 64 * FQS;            // [keypair][d]  32*72

    const int bh = blockIdx.y;
    const int q0 = blockIdx.x * 64;
    const int b  = bh >> 4, hh = bh & 15;
    const float* Qb = Q  + (size_t)bh * SS * 64;
    const float* Kb = Kg + (size_t)bh * SS * 64;
    const float* Vb = Vx + (size_t)b * SS * HH + hh * 64;

    const int tid = threadIdx.x;
    const int w = tid >> 5, lane = tid & 31;
    const int g = lane >> 2, c = lane & 3;
    const int wrow = w * 16;

    const int lr  = tid & 63;          // row 0..63
    const int lc0 = (tid >> 6) * 32;   // d base 0 or 32
    const int vkp = tid & 31;          // V keypair
    const int vdb = (tid >> 5) * 16;   // V d base

    { // Q tile -> packed bf16
        const float4* src = (const float4*)(Qb + (size_t)(q0 + lr) * 64 + lc0);
        #pragma unroll
        for (int i = 0; i < 8; i++) {
            float4 v = src[i];
            uint32_t* d = Qs + lr * FQS + (lc0 >> 1) + i * 2;
            d[0] = pkbf2(v.x, v.y);
            d[1] = pkbf2(v.z, v.w);
        }
    }

    float oacc[8][4];
    #pragma unroll
    for (int nf = 0; nf < 8; nf++)
        #pragma unroll
        for (int r = 0; r < 4; r++) oacc[nf][r] = 0.f;
    float m0 = -1e30f, m1 = -1e30f, l0 = 0.f, l1 = 0.f;

    const float* mr0 = maskp + (size_t)(q0 + wrow + g) * SS;
    const float* mr1 = mr0 + 8 * SS;

    for (int k0 = 0; k0 < SS; k0 += 64) {
        __syncthreads();   // prev PV done before overwriting Kt/Vs
        { // K transposed+packed: Kt[d/2][key]
            const float4* ks = (const float4*)(Kb + (size_t)(k0 + lr) * 64 + lc0);
            #pragma unroll
            for (int i = 0; i < 8; i++) {
                float4 kv = ks[i];
                int dp = (lc0 + i * 4) >> 1;
                Kt[(dp + 0) * FKS + lr] = pkbf2(kv.x, kv.y);
                Kt[(dp + 1) * FKS + lr] = pkbf2(kv.z, kv.w);
            }
        }
        { // V key-pair packed: Vs[keypair][d] = pack(V[2kp][d], V[2kp+1][d])
            const float* v0p = Vb + (size_t)(k0 + 2 * vkp) * HH + vdb;
            const float* v1p = v0p + HH;
            #pragma unroll
            for (int i = 0; i < 4; i++) {
                float4 a = *(const float4*)(v0p + i * 4);
                float4 bb = *(const float4*)(v1p + i * 4);
                uint32_t* vd = Vs + vkp * FKS + vdb + i * 4;
                vd[0] = pkbf2(a.x, bb.x);
                vd[1] = pkbf2(a.y, bb.y);
                vd[2] = pkbf2(a.z, bb.z);
                vd[3] = pkbf2(a.w, bb.w);
            }
        }
        __syncthreads();

        // S = Q @ K^T  (4 k16 steps over d=64)
        float sacc[8][4];
        #pragma unroll
        for (int nf = 0; nf < 8; nf++)
            #pragma unroll
            for (int r = 0; r < 4; r++) sacc[nf][r] = 0.f;
        #pragma unroll
        for (int ks = 0; ks < 32; ks += 8) {
            uint32_t af[4];
            af[0] = Qs[(wrow + g) * FQS + ks + c];
            af[1] = Qs[(wrow + g + 8) * FQS + ks + c];
            af[2] = Qs[(wrow + g) * FQS + ks + c + 4];
            af[3] = Qs[(wrow + g + 8) * FQS + ks + c + 4];
            #pragma unroll
            for (int nf = 0; nf < 8; nf++) {
                uint32_t bf[2];
                bf[0] = Kt[(ks + c) * FKS + nf * 8 + g];
                bf[1] = Kt[(ks + c + 4) * FKS + nf * 8 + g];
                mma16(sacc[nf], af, bf);
            }
        }

        // scale + mask + online softmax (fp32)
        float mx0 = -1e30f, mx1 = -1e30f;
        #pragma unroll
        for (int nf = 0; nf < 8; nf++) {
            float2 mk0 = *(const float2*)(mr0 + k0 + nf * 8 + 2 * c);
            float2 mk1 = *(const float2*)(mr1 + k0 + nf * 8 + 2 * c);
            sacc[nf][0] = sacc[nf][0] * 0.125f + mk0.x;
            sacc[nf][1] = sacc[nf][1] * 0.125f + mk0.y;
            sacc[nf][2] = sacc[nf][2] * 0.125f + mk1.x;
            sacc[nf][3] = sacc[nf][3] * 0.125f + mk1.y;
            mx0 = fmaxf(mx0, fmaxf(sacc[nf][0], sacc[nf][1]));
            mx1 = fmaxf(mx1, fmaxf(sacc[nf][2], sacc[nf][3]));
        }
        mx0 = fmaxf(mx0, __shfl_xor_sync(0xffffffffu, mx0, 1));
        mx0 = fmaxf(mx0, __shfl_xor_sync(0xffffffffu, mx0, 2));
        mx1 = fmaxf(mx1, __shfl_xor_sync(0xffffffffu, mx1, 1));
        mx1 = fmaxf(mx1, __shfl_xor_sync(0xffffffffu, mx1, 2));

        float mn0 = fmaxf(m0, mx0), mn1 = fmaxf(m1, mx1);
        float cr0 = __expf(m0 - mn0), cr1 = __expf(m1 - mn1);
        m0 = mn0; m1 = mn1;
        float rs0 = 0.f, rs1 = 0.f;
        #pragma unroll
        for (int nf = 0; nf < 8; nf++) {
            sacc[nf][0] = __expf(sacc[nf][0] - mn0);
            sacc[nf][1] = __expf(sacc[nf][1] - mn0);
            sacc[nf][2] = __expf(sacc[nf][2] - mn1);
            sacc[nf][3] = __expf(sacc[nf][3] - mn1);
            rs0 += sacc[nf][0] + sacc[nf][1];
            rs1 += sacc[nf][2] + sacc[nf][3];
        }
        rs0 += __shfl_xor_sync(0xffffffffu, rs0, 1);
        rs0 += __shfl_xor_sync(0xffffffffu, rs0, 2);
        rs1 += __shfl_xor_sync(0xffffffffu, rs1, 1);
        rs1 += __shfl_xor_sync(0xffffffffu, rs1, 2);
        l0 = l0 * cr0 + rs0;
        l1 = l1 * cr1 + rs1;
        #pragma unroll
        for (int nf = 0; nf < 8; nf++) {
            oacc[nf][0] *= cr0; oacc[nf][1] *= cr0;
            oacc[nf][2] *= cr1; oacc[nf][3] *= cr1;
        }

        // write P packed bf16 (keys nf*8+2c, +1 are adjacent -> one keypair)
        #pragma unroll
        for (int nf = 0; nf < 8; nf++) {
            int kp = nf * 4 + c;
            Ps[(wrow + g) * FQS + kp]     = pkbf2(sacc[nf][0], sacc[nf][1]);
            Ps[(wrow + g + 8) * FQS + kp] = pkbf2(sacc[nf][2], sacc[nf][3]);
        }
        __syncthreads();

        // O += P @ V  (4 k16 steps over 64 keys)
        #pragma unroll
        for (int kk = 0; kk < 32; kk += 8) {
            uint32_t af[4];
            af[0] = Ps[(wrow + g) * FQS + kk + c];
            af[1] = Ps[(wrow + g + 8) * FQS + kk + c];
            af[2] = Ps[(wrow + g) * FQS + kk + c + 4];
            af[3] = Ps[(wrow + g + 8) * FQS + kk + c + 4];
            #pragma unroll
            for (int nf = 0; nf < 8; nf++) {
                uint32_t bf[2];
                bf[0] = Vs[(kk + c) * FKS + nf * 8 + g];
                bf[1] = Vs[(kk + c + 4) * FKS + nf * 8 + g];
                mma16(oacc[nf], af, bf);
            }
        }
    }

    float inv0 = 1.f / l0, inv1 = 1.f / l1;
    int row0 = q0 + wrow + g;
    float* o0 = O + ((size_t)(b * SS + row0)) * HH + hh * 64;
    float* o1 = o0 + 8 * (size_t)HH;
    #pragma unroll
    for (int nf = 0; nf < 8; nf++) {
        int col = nf * 8 + 2 * c;
        float2 v0 = make_float2(oacc[nf][0] * inv0, oacc[nf][1] * inv0);
        float2 v1 = make_float2(oacc[nf][2] * inv1, oacc[nf][3] * inv1);
        *(float2*)(o0 + col) = v0;
        *(float2*)(o1 + col) = v1;
    }
}

// ---------------- router ----------------
__global__ void router_k(const float* __restrict__ hn, const float* __restrict__ rw,
                         const float* __restrict__ rb,
                         int* __restrict__ cnt, int* __restrict__ tok, float* __restrict__ twt)
{
    int t = blockIdx.x;
    __shared__ float red[128][NE];
    float accv[NE];
    #pragma unroll
    for (int e = 0; e < NE; e++) accv[e] = 0.f;
    const float* xr = hn + (size_t)t * HH;
    for (int k = threadIdx.x; k < HH; k += 128) {
        float xv = xr[k];
        const float* w = rw + (size_t)k * NE;
        #pragma unroll
        for (int e = 0; e < NE; e++) accv[e] += xv * w[e];
    }
    #pragma unroll
    for (int e = 0; e < NE; e++) red[threadIdx.x][e] = accv[e];
    __syncthreads();
    for (int s = 64; s > 0; s >>= 1) {
        if (threadIdx.x < s)
            #pragma unroll
            for (int e = 0; e < NE; e++) red[threadIdx.x][e] += red[threadIdx.x + s][e];
        __syncthreads();
    }
    if (threadIdx.x == 0) {
        float p[NE];
        #pragma unroll
        for (int e = 0; e < NE; e++) {
            float lg = red[0][e] + rb[e];
            p[e] = 1.f / (1.f + expf(-lg));
        }
        int e1 = 0;
        for (int e = 1; e < NE; e++) if (p[e] > p[e1]) e1 = e;
        int e2 = -1;
        for (int e = 0; e < NE; e++) if (e != e1 && (e2 < 0 || p[e] > p[e2])) e2 = e;
        float s2 = p[e1] + p[e2];
        float w1 = p[e1] / s2, w2 = p[e2] / s2;
        int a = atomicAdd(&cnt[e1], 1); tok[e1 * TK + a] = t; twt[e1 * TK + a] = w1;
        int b = atomicAdd(&cnt[e2], 1); tok[e2 * TK + b] = t; twt[e2 * TK + b] = w2;
    }
}

__global__ void silu_mul_k(const float* __restrict__ g, const float* __restrict__ u,
                           float* __restrict__ y, int n)
{
    int i = blockIdx.x * 256 + threadIdx.x;
    if (i < n) {
        float gv = g[i];
        y[i] = (gv / (1.f + expf(-gv))) * u[i];
    }
}

__global__ void silu_mul_moe(const float* __restrict__ g, const float* __restrict__ u,
                             float* __restrict__ y, const int* __restrict__ cnt)
{
    const size_t TI = (size_t)TK * II;
    int e = blockIdx.y;
    int i = blockIdx.x * 256 + threadIdx.x;
    if (i / II >= cnt[e]) return;
    size_t idx = (size_t)e * TI + i;
    float gv = g[idx];
    y[idx] = (gv / (1.f + expf(-gv))) * u[idx];
}

__global__ void usage_k(const int* __restrict__ cnt, float* __restrict__ out)
{
    int e = threadIdx.x;
    if (e < NE) out[e] = (float)cnt[e];
}

// ---------------- host-side dispatch ----------------
static const int SMEM1  = (2 * (2560 + 2176) + 128) * 4;      // 38400 (tf32)
static const int SMEMB  = (2 * (GASZ + GBSZ)) * 4;            // 37888 (bf16)
static const int SMEMF  = (64 * FQS + 32 * FKS + 64 * FQS + 32 * FKS) * 4;  // 36864

static void GB(cudaStream_t st,
               const float* A, int lda, const float* B, int ldb,
               float* C, int ldc, int M, int N, int K,
               const float* adds, int splitK)
{
    dim3 grid(N / 128, M / 128, splitK);
    gemm_bf<<<grid, 256, SMEMB, st>>>(A, lda, B, ldb, C, ldc, M, N, K, adds, splitK);
}

static void G1(cudaStream_t st,
               const float* A, int lda, size_t eas,
               const float* B, int ldb, size_t ebs,
               float* C, int ldc, size_t ecs,
               int M, int N, int K, int nz,
               const int* tokB, int ga, int sc,
               const float* wtB, int accA, const int* cntB)
{
    dim3 grid(N / 128, (M + 127) / 128, nz);
    gemm_tc<<<grid, 256, SMEM1, st>>>(A, lda, eas, B, ldb, ebs, C, ldc, ecs,
                                      M, N, K, tokB, ga, sc, wtB, accA, cntB);
}

extern "C" void kernel_launch(void* const* d_in, const int* in_sizes, int n_in,
                              void* d_out, int out_size)
{
    const float* x        = (const float*)d_in[0];
    const float* cosp     = (const float*)d_in[1];
    const float* sinp     = (const float*)d_in[2];
    const float* maskp    = (const float*)d_in[3];
    const float* ln1      = (const float*)d_in[4];
    const float* ln2      = (const float*)d_in[5];
    const float* kv_down  = (const float*)d_in[6];
    const float* kv_norm  = (const float*)d_in[7];
    const float* w_uk     = (const float*)d_in[8];
    const float* w_ur     = (const float*)d_in[9];
    const float* w_uv     = (const float*)d_in[10];
    const float* q_down   = (const float*)d_in[11];
    const float* q_norm   = (const float*)d_in[12];
    const float* w_uq     = (const float*)d_in[13];
    const float* w_qr     = (const float*)d_in[14];
    const float* o_proj   = (const float*)d_in[15];
    const float* sh_gate  = (const float*)d_in[16];
    const float* sh_up    = (const float*)d_in[17];
    const float* sh_down  = (const float*)d_in[18];
    const float* r_gate   = (const float*)d_in[19];
    const float* r_up     = (const float*)d_in[20];
    const float* r_down   = (const float*)d_in[21];
    const float* router_w = (const float*)d_in[22];
    const float* router_b = (const float*)d_in[23];
    float* out = (float*)d_out;

    float *xi, *cq, *ckv, *qn, *qr, *kn, *kr, *vx, *q, *k, *o, *h, *hn, *gt, *ut, *act, *twt;
    int *cnt, *tok;
    cudaGetSymbolAddress((void**)&xi,  g_xi);
    cudaGetSymbolAddress((void**)&cq,  g_cq);
    cudaGetSymbolAddress((void**)&ckv, g_ckv);
    cudaGetSymbolAddress((void**)&qn,  g_qn);
    cudaGetSymbolAddress((void**)&qr,  g_qr);
    cudaGetSymbolAddress((void**)&kn,  g_kn);
    cudaGetSymbolAddress((void**)&kr,  g_kr);
    cudaGetSymbolAddress((void**)&vx,  g_vx);
    cudaGetSymbolAddress((void**)&q,   g_q);
    cudaGetSymbolAddress((void**)&k,   g_k);
    cudaGetSymbolAddress((void**)&o,   g_o);
    cudaGetSymbolAddress((void**)&h,   g_h);
    cudaGetSymbolAddress((void**)&hn,  g_hn);
    cudaGetSymbolAddress((void**)&gt,  g_gt);
    cudaGetSymbolAddress((void**)&ut,  g_ut);
    cudaGetSymbolAddress((void**)&act, g_act);
    cudaGetSymbolAddress((void**)&twt, g_twt);
    cudaGetSymbolAddress((void**)&cnt, g_cnt);
    cudaGetSymbolAddress((void**)&tok, g_tok);

    cudaFuncSetAttribute(gemm_tc,  cudaFuncAttributeMaxDynamicSharedMemorySize, SMEM1);
    cudaFuncSetAttribute(gemm_bf,  cudaFuncAttributeMaxDynamicSharedMemorySize, SMEMB);
    cudaFuncSetAttribute(flash_bf, cudaFuncAttributeMaxDynamicSharedMemorySize, SMEMF);

    cudaStream_t s0 = 0, s1;
    cudaStreamCreateWithFlags(&s1, cudaStreamNonBlocking);
    cudaEvent_t ev0, ev1, ev2, ev3;
    cudaEventCreateWithFlags(&ev0, cudaEventDisableTiming);
    cudaEventCreateWithFlags(&ev1, cudaEventDisableTiming);
    cudaEventCreateWithFlags(&ev2, cudaEventDisableTiming);
    cudaEventCreateWithFlags(&ev3, cudaEventDisableTiming);

    const size_t TI = (size_t)TK * II;

    // ---- MLA attention (all bf16 single-pass: attenuated ~300x by o_proj scale) ----
    rms_k<<<TK, 256, 0, s0>>>(x, ln1, xi, HH);
    cudaEventRecord(ev0, s0);
    cudaStreamWaitEvent(s1, ev0, 0);

    // q-chain on s0
    cudaMemsetAsync(cq, 0, (size_t)TK * 128 * sizeof(float), s0);
    GB(s0, xi, HH, q_down, 128, cq, 128, TK, 128, HH, nullptr, 4);
    rms_k<<<TK, 128, 0, s0>>>(cq, q_norm, cq, 128);
    GB(s0, cq, 128, w_uq, 512, qn, 512, TK, 512, 128, nullptr, 1);
    GB(s0, cq, 128, w_qr, 512, qr, 512, TK, 512, 128, nullptr, 1);

    // kv-chain on s1
    cudaMemsetAsync(ckv, 0, (size_t)TK * 128 * sizeof(float), s1);
    GB(s1, xi, HH, kv_down, 128, ckv, 128, TK, 128, HH, nullptr, 4);
    rms_k<<<TK, 128, 0, s1>>>(ckv, kv_norm, ckv, 128);
    GB(s1, ckv, 128, w_uk, 512, kn, 512, TK, 512, 128, nullptr, 1);
    GB(s1, ckv, 128, w_ur, 512, kr, 512, TK, 512, 128, nullptr, 1);
    GB(s1, ckv, 128, w_uv, 1024, vx, 1024, TK, 1024, 128, nullptr, 1);
    cudaEventRecord(ev1, s1);
    cudaStreamWaitEvent(s0, ev1, 0);

    assemble_k<<<(BHN * SS * 64) / 256, 256, 0, s0>>>(qn, qr, kn, kr, cosp, sinp, q, k);
    flash_bf<<<dim3(SS / 64, BHN), 128, SMEMF, s0>>>(q, k, vx, maskp, o);
    GB(s0, o, HH, o_proj, HH, h, HH, TK, HH, HH, x, 1);   // h = x + o@Wo

    // ---- MoE (tf32: holds the error budget) ----
    rms_k<<<TK, 256, 0, s0>>>(h, ln2, hn, HH);
    cudaMemsetAsync(cnt, 0, NE * sizeof(int), s0);
    router_k<<<TK, 128, 0, s0>>>(hn, router_w, router_b, cnt, tok, twt);
    cudaMemcpyAsync(out, h, (size_t)TK * HH * sizeof(float), cudaMemcpyDeviceToDevice, s0);
    cudaEventRecord(ev2, s0);
    cudaStreamWaitEvent(s1, ev2, 0);

    // shared experts on s0 (dense, z=2): scratch [0, 2*TI)
    G1(s0, hn, HH, 0,  sh_gate, II, (size_t)HH * II,  gt, II, TI,  TK, II, HH, 2,
       nullptr, 0, 0, nullptr, 0, nullptr);
    G1(s0, hn, HH, 0,  sh_up, II, (size_t)HH * II,  ut, II, TI,  TK, II, HH, 2,
       nullptr, 0, 0, nullptr, 0, nullptr);
    silu_mul_k<<<(2 * (int)TI + 255) / 256, 256, 0, s0>>>(gt, ut, act, 2 * (int)TI);
    G1(s0, act, II, TI,  sh_down, HH, (size_t)II * HH,  out, HH, 0,  TK, HH, II, 2,
       nullptr, 0, 0, nullptr, 1, nullptr);

    // routed experts on s1 (sparse compact rows, z=8): scratch [2*TI, 10*TI)
    float* gt2 = gt + 2 * TI;
    float* ut2 = ut + 2 * TI;
    float* act2 = act + 2 * TI;
    G1(s1, hn, HH, 0,  r_gate, II, (size_t)HH * II,  gt2, II, TI,  TK, II, HH, NE,
       tok, 1, 0, nullptr, 0, cnt);
    G1(s1, hn, HH, 0,  r_up, II, (size_t)HH * II,  ut2, II, TI,  TK, II, HH, NE,
       tok, 1, 0, nullptr, 0, cnt);
    silu_mul_moe<<<dim3(((int)TI + 255) / 256, NE), 256, 0, s1>>>(gt2, ut2, act2, cnt);
    G1(s1, act2, II, TI,  r_down, HH, (size_t)II * HH,  out, HH, 0,  TK, HH, II, NE,
       tok, 0, 1, twt, 0, cnt);
    cudaEventRecord(ev3, s1);
    cudaStreamWaitEvent(s0, ev3, 0);

    usage_k<<<1, NE, 0, s0>>>(cnt, out + (size_t)TK * HH);
}

// round 11
// speedup vs baseline: 6.8026x; 1.1953x over previous
#include <cuda_runtime.h>
#include <cuda_bf16.h>
#include <math.h>
#include <stdint.h>

// ---------------- problem constants ----------------
#define TK   4096      // tokens = B*S
#define HH   1024      // hidden
#define SS   2048      // seq len
#define NHH  16        // heads
#define BHN  32        // B*NH
#define II   384       // expert intermediate
#define NE   8         // routed experts

// ---------------- scratch ----------------
__device__ float g_xi [TK*HH];
__device__ float g_cq [TK*128];
__device__ float g_ckv[TK*128];
__device__ float g_qn [TK*512];
__device__ float g_qr [TK*512];
__device__ float g_kn [TK*512];
__device__ float g_kr [TK*512];
__device__ float g_vx [TK*HH];
__device__ float g_q  [TK*HH];   // [bh][s][64]
__device__ float g_k  [TK*HH];
__device__ float g_o  [TK*HH];   // [b][s][h*64+d]
__device__ float g_h  [TK*HH];
__device__ float g_hn [TK*HH];
__device__ float g_gt [(NE+2)*TK*II];
__device__ float g_ut [(NE+2)*TK*II];
__device__ float g_act[(NE+2)*TK*II];
__device__ int   g_cnt[NE];
__device__ int   g_tok[NE*TK];
__device__ float g_twt[NE*TK];

// ---------------- mma helpers ----------------
__device__ __forceinline__ uint32_t f2tf(float f) {
    uint32_t r;
    asm("cvt.rna.tf32.f32 %0, %1;" : "=r"(r) : "f"(f));
    return r;
}
__device__ __forceinline__ void mma8(float* c, const uint32_t* a, const uint32_t* b) {
    asm volatile(
        "mma.sync.aligned.m16n8k8.row.col.f32.tf32.tf32.f32 "
        "{%0,%1,%2,%3}, {%4,%5,%6,%7}, {%8,%9}, {%0,%1,%2,%3};\n"
        : "+f"(c[0]), "+f"(c[1]), "+f"(c[2]), "+f"(c[3])
        : "r"(a[0]), "r"(a[1]), "r"(a[2]), "r"(a[3]), "r"(b[0]), "r"(b[1]));
}
__device__ __forceinline__ void mma16(float* c, const uint32_t* a, const uint32_t* b) {
    asm volatile(
        "mma.sync.aligned.m16n8k16.row.col.f32.bf16.bf16.f32 "
        "{%0,%1,%2,%3}, {%4,%5,%6,%7}, {%8,%9}, {%0,%1,%2,%3};\n"
        : "+f"(c[0]), "+f"(c[1]), "+f"(c[2]), "+f"(c[3])
        : "r"(a[0]), "r"(a[1]), "r"(a[2]), "r"(a[3]), "r"(b[0]), "r"(b[1]));
}
__device__ __forceinline__ uint32_t pkbf2(float a, float b) {
    __nv_bfloat162 t = __floats2bfloat162_rn(a, b);
    return *reinterpret_cast<uint32_t*>(&t);
}

// ---------------- bf16 GEMM, software-pipelined (LDG early / STS late) ----------------
// Up to 3 N-segments (different B/C per column range; splits multiple of 128).
// splitK>1: atomicAdd into zeroed C (single segment only). addsrc: C = acc + addsrc.
#define GASTR 20
#define GBSTR 136
#define GASZ  (128*GASTR)   // 128 rows x 16 kpairs (BK=32)
#define GBSZ  (16*GBSTR)
__global__ void __launch_bounds__(256) gemm_bf(
    const float* __restrict__ A, int lda,
    const float* __restrict__ B0, int ldb0, float* __restrict__ C0, int ldc0, int n1,
    const float* __restrict__ B1, int ldb1, float* __restrict__ C1, int ldc1, int n2,
    const float* __restrict__ B2, int ldb2, float* __restrict__ C2, int ldc2,
    int M, int N, int K,
    const float* __restrict__ addsrc, int splitK)
{
    extern __shared__ uint32_t sm[];
    uint32_t* As = sm;              // [2][GASZ]
    uint32_t* Bs = sm + 2 * GASZ;   // [2][GBSZ]

    const int Ke = K / splitK;
    const int kbase = blockIdx.z * Ke;
    const int m0 = blockIdx.y * 128;
    const int n0 = blockIdx.x * 128;
    const int tid = threadIdx.x;

    // segment select (per block; splits are multiples of 128)
    const float* B = B0; float* C = C0; int ldb = ldb0, ldc = ldc0; int nloc = n0;
    if (B1 && n0 >= n1) {
        if (B2 && n0 >= n1 + n2) { B = B2; C = C2; ldb = ldb2; ldc = ldc2; nloc = n0 - n1 - n2; }
        else                     { B = B1; C = C1; ldb = ldb1; ldc = ldc1; nloc = n0 - n1; }
    }

    // per-thread load coords
    const int am = tid >> 4, ak2 = tid & 15;       // + i*16 rows
    const int bn = tid & 127, bk2 = tid >> 7;      // + i*2 kpairs

    float2 areg[8];
    float  breg[16];

    auto ldgTile = [&](int kt) {
        #pragma unroll
        for (int i = 0; i < 8; i++)
            areg[i] = *(const float2*)(A + (size_t)(m0 + am + i * 16) * lda + kt + 2 * ak2);
        #pragma unroll
        for (int i = 0; i < 8; i++) {
            int kk = kt + 2 * (bk2 + i * 2);
            breg[2 * i]     = B[(size_t)kk * ldb + nloc + bn];
            breg[2 * i + 1] = B[(size_t)(kk + 1) * ldb + nloc + bn];
        }
    };
    auto stsTile = [&](int buf) {
        uint32_t* Ad = As + buf * GASZ;
        #pragma unroll
        for (int i = 0; i < 8; i++)
            Ad[(am + i * 16) * GASTR + ak2] = pkbf2(areg[i].x, areg[i].y);
        uint32_t* Bd = Bs + buf * GBSZ;
        #pragma unroll
        for (int i = 0; i < 8; i++)
            Bd[(bk2 + i * 2) * GBSTR + bn] = pkbf2(breg[2 * i], breg[2 * i + 1]);
    };

    const int lane = tid & 31, wid = tid >> 5;
    const int wm = (wid >> 2) * 64;
    const int wn = (wid & 3) * 32;
    const int g = lane >> 2, c = lane & 3;

    float acc[4][4][4];
    #pragma unroll
    for (int i = 0; i < 4; i++)
        #pragma unroll
        for (int j = 0; j < 4; j++)
            #pragma unroll
            for (int r = 0; r < 4; r++) acc[i][j][r] = 0.f;

    ldgTile(kbase);
    stsTile(0);
    __syncthreads();

    const int nbuf = Ke >> 5;
    for (int t = 0; t < nbuf; t++) {
        int cur = t & 1;
        if (t + 1 < nbuf) ldgTile(kbase + ((t + 1) << 5));   // non-blocking until sts

        const uint32_t* Ab = As + cur * GASZ;
        const uint32_t* Bb = Bs + cur * GBSZ;
        #pragma unroll
        for (int kp = 0; kp < 16; kp += 8) {
            uint32_t af[4][4];
            #pragma unroll
            for (int mt = 0; mt < 4; mt++) {
                int mb = wm + mt * 16;
                af[mt][0] = Ab[(mb + g) * GASTR + kp + c];
                af[mt][1] = Ab[(mb + g + 8) * GASTR + kp + c];
                af[mt][2] = Ab[(mb + g) * GASTR + kp + c + 4];
                af[mt][3] = Ab[(mb + g + 8) * GASTR + kp + c + 4];
            }
            uint32_t bf[4][2];
            #pragma unroll
            for (int nt = 0; nt < 4; nt++) {
                int nb = wn + nt * 8;
                bf[nt][0] = Bb[(kp + c) * GBSTR + nb + g];
                bf[nt][1] = Bb[(kp + c + 4) * GBSTR + nb + g];
            }
            #pragma unroll
            for (int mt = 0; mt < 4; mt++)
                #pragma unroll
                for (int nt = 0; nt < 4; nt++)
                    mma16(acc[mt][nt], af[mt], bf[nt]);
        }
        if (t + 1 < nbuf) stsTile(cur ^ 1);
        __syncthreads();
    }

    #pragma unroll
    for (int mt = 0; mt < 4; mt++) {
        #pragma unroll
        for (int h2 = 0; h2 < 2; h2++) {
            int m = m0 + wm + mt * 16 + g + h2 * 8;
            #pragma unroll
            for (int nt = 0; nt < 4; nt++) {
                int ncol = nloc + wn + nt * 8 + c * 2;
                float v0 = acc[mt][nt][h2 * 2 + 0];
                float v1 = acc[mt][nt][h2 * 2 + 1];
                float* cp = C + (size_t)m * ldc + ncol;
                if (splitK > 1) {
                    atomicAdd(cp, v0); atomicAdd(cp + 1, v1);
                } else if (addsrc) {
                    const float* ap = addsrc + (size_t)m * ldc + ncol;
                    cp[0] = v0 + ap[0]; cp[1] = v1 + ap[1];
                } else {
                    cp[0] = v0; cp[1] = v1;
                }
            }
        }
    }
}

// ---------------- tf32 GEMM, pipelined (MoE: gather/scatter/scale) ----------------
__global__ void __launch_bounds__(256) gemm_tc(
    const float* __restrict__ A, int lda, size_t eastride,
    const float* __restrict__ B, int ldb, size_t ebstride,
    float* __restrict__ C, int ldc, size_t ecstride,
    int M, int N, int K,
    const int* __restrict__ tokBase, int gatherA, int scatterC,
    const float* __restrict__ wtBase,
    int accAtomic,
    const int* __restrict__ cntBase)
{
    constexpr int ASTR = 20;
    constexpr int BSTR = 136;
    constexpr int ASZ = 128 * ASTR;
    constexpr int BSZ = 16 * BSTR;

    extern __shared__ uint32_t smem_u[];
    uint32_t* As = smem_u;
    uint32_t* Bs = smem_u + 2 * ASZ;
    int* idxs = (int*)(smem_u + 2 * (ASZ + BSZ));

    const int e = blockIdx.z;
    B += (size_t)e * ebstride;
    C += (size_t)e * ecstride;
    const float* Ae = A + (size_t)e * eastride;
    const int* idx = tokBase ? tokBase + (size_t)e * TK : nullptr;
    const float* wt = wtBase ? wtBase + (size_t)e * TK : nullptr;
    const int effM = cntBase ? cntBase[e] : M;

    const int m0 = blockIdx.y * 128;
    const int n0 = blockIdx.x * 128;
    if (m0 >= effM) return;

    const int tid = threadIdx.x;
    if (idx) {
        for (int i = tid; i < 128; i += 256) {
            int m = m0 + i;
            idxs[i] = (m < effM) ? idx[m] : 0;
        }
    }
    __syncthreads();

    const int am = tid >> 4, ak = tid & 15;
    const int bn = tid & 127, bk = tid >> 7;

    float areg[8], breg[8];
    auto ldgTile = [&](int kt) {
        #pragma unroll
        for (int i = 0; i < 8; i++) {
            int m = am + i * 16;
            int mg = m0 + m;
            float v = 0.f;
            if (mg < effM) {
                int row = gatherA ? idxs[m] : mg;
                v = Ae[(size_t)row * lda + kt + ak];
            }
            areg[i] = v;
        }
        #pragma unroll
        for (int i = 0; i < 8; i++)
            breg[i] = B[(size_t)(kt + bk + i * 2) * ldb + n0 + bn];
    };
    auto stsTile = [&](int buf) {
        uint32_t* Ad = As + buf * ASZ;
        #pragma unroll
        for (int i = 0; i < 8; i++)
            Ad[(am + i * 16) * ASTR + ak] = f2tf(areg[i]);
        uint32_t* Bd = Bs + buf * BSZ;
        #pragma unroll
        for (int i = 0; i < 8; i++)
            Bd[(bk + i * 2) * BSTR + bn] = f2tf(breg[i]);
    };

    const int lane = tid & 31, wid = tid >> 5;
    const int wm = (wid >> 2) * 64;
    const int wn = (wid & 3) * 32;
    const int g = lane >> 2, c = lane & 3;

    float acc[4][4][4];
    #pragma unroll
    for (int i = 0; i < 4; i++)
        #pragma unroll
        for (int j = 0; j < 4; j++)
            #pragma unroll
            for (int r = 0; r < 4; r++) acc[i][j][r] = 0.f;

    ldgTile(0);
    stsTile(0);
    __syncthreads();

    const int nkt = K >> 4;
    for (int t = 0; t < nkt; t++) {
        int cur = t & 1;
        if (t + 1 < nkt) ldgTile((t + 1) << 4);

        const uint32_t* Ab = As + cur * ASZ;
        const uint32_t* Bb = Bs + cur * BSZ;
        #pragma unroll
        for (int ks = 0; ks < 16; ks += 8) {
            uint32_t af[4][4];
            #pragma unroll
            for (int mt = 0; mt < 4; mt++) {
                int mb = wm + mt * 16;
                af[mt][0] = Ab[(mb + g) * ASTR + ks + c];
                af[mt][1] = Ab[(mb + g + 8) * ASTR + ks + c];
                af[mt][2] = Ab[(mb + g) * ASTR + ks + c + 4];
                af[mt][3] = Ab[(mb + g + 8) * ASTR + ks + c + 4];
            }
            uint32_t bf[4][2];
            #pragma unroll
            for (int nt = 0; nt < 4; nt++) {
                int nb = wn + nt * 8;
                bf[nt][0] = Bb[(ks + c) * BSTR + nb + g];
                bf[nt][1] = Bb[(ks + c + 4) * BSTR + nb + g];
            }
            #pragma unroll
            for (int mt = 0; mt < 4; mt++)
                #pragma unroll
                for (int nt = 0; nt < 4; nt++)
                    mma8(acc[mt][nt], af[mt], bf[nt]);
        }
        if (t + 1 < nkt) stsTile(cur ^ 1);
        __syncthreads();
    }

    #pragma unroll
    for (int mt = 0; mt < 4; mt++) {
        #pragma unroll
        for (int h2 = 0; h2 < 2; h2++) {
            int ml = wm + mt * 16 + g + h2 * 8;
            int m = m0 + ml;
            if (m >= effM) continue;
            int crow = scatterC ? idxs[ml] : m;
            float sc = wt ? wt[m] : 1.f;
            #pragma unroll
            for (int nt = 0; nt < 4; nt++) {
                int ncol = n0 + wn + nt * 8 + c * 2;
                float v0 = acc[mt][nt][h2 * 2 + 0];
                float v1 = acc[mt][nt][h2 * 2 + 1];
                float* cp = C + (size_t)crow * ldc + ncol;
                if (wt) {
                    atomicAdd(cp, sc * v0); atomicAdd(cp + 1, sc * v1);
                } else if (accAtomic) {
                    atomicAdd(cp, v0); atomicAdd(cp + 1, v1);
                } else {
                    cp[0] = v0; cp[1] = v1;
                }
            }
        }
    }
}

// ---------------- RMSNorm ----------------
__global__ void rms_k(const float* __restrict__ x, const float* __restrict__ w,
                      float* __restrict__ y, int D)
{
    int t = blockIdx.x;
    const float* xr = x + (size_t)t * D;
    float* yr = y + (size_t)t * D;
    float ss = 0.f;
    for (int k = threadIdx.x; k < D; k += blockDim.x) { float v = xr[k]; ss += v * v; }
    __shared__ float sh[32];
    int lane = threadIdx.x & 31, wid = threadIdx.x >> 5;
    #pragma unroll
    for (int o = 16; o > 0; o >>= 1) ss += __shfl_xor_sync(0xffffffffu, ss, o);
    if (lane == 0) sh[wid] = ss;
    __syncthreads();
    if (threadIdx.x == 0) {
        float tot = 0.f;
        int nw = blockDim.x >> 5;
        for (int i = 0; i < nw; i++) tot += sh[i];
        sh[0] = tot;
    }
    __syncthreads();
    float r = rsqrtf(sh[0] / (float)D + 1e-5f);
    for (int k = threadIdx.x; k < D; k += blockDim.x) yr[k] = w[k] * xr[k] * r;
}

// ---------------- assemble Q/K with RoPE ----------------
__global__ void assemble_k(const float* __restrict__ qn, const float* __restrict__ qr,
                           const float* __restrict__ kn, const float* __restrict__ kr,
                           const float* __restrict__ cosp, const float* __restrict__ sinp,
                           float* __restrict__ Q, float* __restrict__ K)
{
    int idx = blockIdx.x * blockDim.x + threadIdx.x;
    if (idx >= BHN * SS * 64) return;
    int d  = idx & 63;
    int s  = (idx >> 6) & (SS - 1);
    int bh = idx >> 17;
    int b  = bh >> 4, h = bh & 15;
    int t  = b * SS + s;
    float qv, kv;
    if (d < 32) {
        qv = qn[(size_t)t * 512 + h * 32 + d];
        kv = kn[(size_t)t * 512 + h * 32 + d];
    } else {
        int j = d - 32;
        float cc = cosp[s * 32 + j];
        float sn = sinp[s * 32 + j];
        float q1 = qr[(size_t)t * 512 + h * 32 + j];
        float q2 = (j < 16) ? -qr[(size_t)t * 512 + h * 32 + j + 16]
                            :  qr[(size_t)t * 512 + h * 32 + j - 16];
        qv = q1 * cc + q2 * sn;
        float k1 = kr[(size_t)t * 512 + h * 32 + j];
        float k2 = (j < 16) ? -kr[(size_t)t * 512 + h * 32 + j + 16]
                            :  kr[(size_t)t * 512 + h * 32 + j - 16];
        kv = k1 * cc + k2 * sn;
    }
    Q[idx] = qv;
    K[idx] = kv;
}

// ---------------- flash attention, bf16 tensor cores, prefetched KV ----------------
// smem (u32): Qs[64][36] | Kt[32][72] | Ps[64][36] | Vs[32][72]  = 9216 u32 = 36 KB
#define FQS 36
#define FKS 72
__global__ void flash_bf(
    const float* __restrict__ Q, const float* __restrict__ Kg,
    const float* __restrict__ Vx, const float* __restrict__ maskp,
    float* __restrict__ O)
{
    extern __shared__ uint32_t sm[];
    uint32_t* Qs = sm;                       // [row][kpair]  64*36
    uint32_t* Kt = sm + 64 * FQS;            // [kpair][key]  32*72
    uint32_t* Ps = Kt + 32 * FKS;            // [row][keypair] 64*36
    uint32_t* Vs = Ps + 64 * FQS;            // [keypair][d]  32*72

    const int bh = blockIdx.y;
    const int q0 = blockIdx.x * 64;
    const int b  = bh >> 4, hh = bh & 15;
    const float* Qb = Q  + (size_t)bh * SS * 64;
    const float* Kb = Kg + (size_t)bh * SS * 64;
    const float* Vb = Vx + (size_t)b * SS * HH + hh * 64;

    const int tid = threadIdx.x;
    const int w = tid >> 5, lane = tid & 31;
    const int g = lane >> 2, c = lane & 3;
    const int wrow = w * 16;

    const int lr  = tid & 63;          // row 0..63
    const int lc0 = (tid >> 6) * 32;   // d base 0 or 32
    const int vkp = tid & 31;          // V keypair
    const int vdb = (tid >> 5) * 16;   // V d base

    { // Q tile -> packed bf16
        const float4* src = (const float4*)(Qb + (size_t)(q0 + lr) * 64 + lc0);
        #pragma unroll
        for (int i = 0; i < 8; i++) {
            float4 v = src[i];
            uint32_t* d = Qs + lr * FQS + (lc0 >> 1) + i * 2;
            d[0] = pkbf2(v.x, v.y);
            d[1] = pkbf2(v.z, v.w);
        }
    }

    float4 kreg[8];
    float4 vreg0[4], vreg1[4];
    auto ldgKV = [&](int k0) {
        const float4* ks = (const float4*)(Kb + (size_t)(k0 + lr) * 64 + lc0);
        #pragma unroll
        for (int i = 0; i < 8; i++) kreg[i] = ks[i];
        const float* v0p = Vb + (size_t)(k0 + 2 * vkp) * HH + vdb;
        const float* v1p = v0p + HH;
        #pragma unroll
        for (int i = 0; i < 4; i++) {
            vreg0[i] = *(const float4*)(v0p + i * 4);
            vreg1[i] = *(const float4*)(v1p + i * 4);
        }
    };
    auto stsKV = [&]() {
        #pragma unroll
        for (int i = 0; i < 8; i++) {
            float4 kv = kreg[i];
            int dp = (lc0 + i * 4) >> 1;
            Kt[(dp + 0) * FKS + lr] = pkbf2(kv.x, kv.y);
            Kt[(dp + 1) * FKS + lr] = pkbf2(kv.z, kv.w);
        }
        #pragma unroll
        for (int i = 0; i < 4; i++) {
            float4 a = vreg0[i];
            float4 bb = vreg1[i];
            uint32_t* vd = Vs + vkp * FKS + vdb + i * 4;
            vd[0] = pkbf2(a.x, bb.x);
            vd[1] = pkbf2(a.y, bb.y);
            vd[2] = pkbf2(a.z, bb.z);
            vd[3] = pkbf2(a.w, bb.w);
        }
    };

    float oacc[8][4];
    #pragma unroll
    for (int nf = 0; nf < 8; nf++)
        #pragma unroll
        for (int r = 0; r < 4; r++) oacc[nf][r] = 0.f;
    float m0 = -1e30f, m1 = -1e30f, l0 = 0.f, l1 = 0.f;

    const float* mr0 = maskp + (size_t)(q0 + wrow + g) * SS;
    const float* mr1 = mr0 + 8 * SS;

    ldgKV(0);
    for (int k0 = 0; k0 < SS; k0 += 64) {
        __syncthreads();   // prev PV done before overwriting Kt/Vs
        stsKV();
        __syncthreads();
        if (k0 + 64 < SS) ldgKV(k0 + 64);   // overlap with this tile's compute

        // S = Q @ K^T  (4 k16 steps over d=64)
        float sacc[8][4];
        #pragma unroll
        for (int nf = 0; nf < 8; nf++)
            #pragma unroll
            for (int r = 0; r < 4; r++) sacc[nf][r] = 0.f;
        #pragma unroll
        for (int ks = 0; ks < 32; ks += 8) {
            uint32_t af[4];
            af[0] = Qs[(wrow + g) * FQS + ks + c];
            af[1] = Qs[(wrow + g + 8) * FQS + ks + c];
            af[2] = Qs[(wrow + g) * FQS + ks + c + 4];
            af[3] = Qs[(wrow + g + 8) * FQS + ks + c + 4];
            #pragma unroll
            for (int nf = 0; nf < 8; nf++) {
                uint32_t bf[2];
                bf[0] = Kt[(ks + c) * FKS + nf * 8 + g];
                bf[1] = Kt[(ks + c + 4) * FKS + nf * 8 + g];
                mma16(sacc[nf], af, bf);
            }
        }

        // scale + mask + online softmax (fp32)
        float mx0 = -1e30f, mx1 = -1e30f;
        #pragma unroll
        for (int nf = 0; nf < 8; nf++) {
            float2 mk0 = *(const float2*)(mr0 + k0 + nf * 8 + 2 * c);
            float2 mk1 = *(const float2*)(mr1 + k0 + nf * 8 + 2 * c);
            sacc[nf][0] = sacc[nf][0] * 0.125f + mk0.x;
            sacc[nf][1] = sacc[nf][1] * 0.125f + mk0.y;
            sacc[nf][2] = sacc[nf][2] * 0.125f + mk1.x;
            sacc[nf][3] = sacc[nf][3] * 0.125f + mk1.y;
            mx0 = fmaxf(mx0, fmaxf(sacc[nf][0], sacc[nf][1]));
            mx1 = fmaxf(mx1, fmaxf(sacc[nf][2], sacc[nf][3]));
        }
        mx0 = fmaxf(mx0, __shfl_xor_sync(0xffffffffu, mx0, 1));
        mx0 = fmaxf(mx0, __shfl_xor_sync(0xffffffffu, mx0, 2));
        mx1 = fmaxf(mx1, __shfl_xor_sync(0xffffffffu, mx1, 1));
        mx1 = fmaxf(mx1, __shfl_xor_sync(0xffffffffu, mx1, 2));

        float mn0 = fmaxf(m0, mx0), mn1 = fmaxf(m1, mx1);
        float cr0 = __expf(m0 - mn0), cr1 = __expf(m1 - mn1);
        m0 = mn0; m1 = mn1;
        float rs0 = 0.f, rs1 = 0.f;
        #pragma unroll
        for (int nf = 0; nf < 8; nf++) {
            sacc[nf][0] = __expf(sacc[nf][0] - mn0);
            sacc[nf][1] = __expf(sacc[nf][1] - mn0);
            sacc[nf][2] = __expf(sacc[nf][2] - mn1);
            sacc[nf][3] = __expf(sacc[nf][3] - mn1);
            rs0 += sacc[nf][0] + sacc[nf][1];
            rs1 += sacc[nf][2] + sacc[nf][3];
        }
        rs0 += __shfl_xor_sync(0xffffffffu, rs0, 1);
        rs0 += __shfl_xor_sync(0xffffffffu, rs0, 2);
        rs1 += __shfl_xor_sync(0xffffffffu, rs1, 1);
        rs1 += __shfl_xor_sync(0xffffffffu, rs1, 2);
        l0 = l0 * cr0 + rs0;
        l1 = l1 * cr1 + rs1;
        #pragma unroll
        for (int nf = 0; nf < 8; nf++) {
            oacc[nf][0] *= cr0; oacc[nf][1] *= cr0;
            oacc[nf][2] *= cr1; oacc[nf][3] *= cr1;
        }

        // write P packed bf16 (keys nf*8+2c, +1 adjacent -> one keypair)
        #pragma unroll
        for (int nf = 0; nf < 8; nf++) {
            int kp = nf * 4 + c;
            Ps[(wrow + g) * FQS + kp]     = pkbf2(sacc[nf][0], sacc[nf][1]);
            Ps[(wrow + g + 8) * FQS + kp] = pkbf2(sacc[nf][2], sacc[nf][3]);
        }
        __syncthreads();

        // O += P @ V  (4 k16 steps over 64 keys)
        #pragma unroll
        for (int kk = 0; kk < 32; kk += 8) {
            uint32_t af[4];
            af[0] = Ps[(wrow + g) * FQS + kk + c];
            af[1] = Ps[(wrow + g + 8) * FQS + kk + c];
            af[2] = Ps[(wrow + g) * FQS + kk + c + 4];
            af[3] = Ps[(wrow + g + 8) * FQS + kk + c + 4];
            #pragma unroll
            for (int nf = 0; nf < 8; nf++) {
                uint32_t bf[2];
                bf[0] = Vs[(kk + c) * FKS + nf * 8 + g];
                bf[1] = Vs[(kk + c + 4) * FKS + nf * 8 + g];
                mma16(oacc[nf], af, bf);
            }
        }
    }

    float inv0 = 1.f / l0, inv1 = 1.f / l1;
    int row0 = q0 + wrow + g;
    float* o0 = O + ((size_t)(b * SS + row0)) * HH + hh * 64;
    float* o1 = o0 + 8 * (size_t)HH;
    #pragma unroll
    for (int nf = 0; nf < 8; nf++) {
        int col = nf * 8 + 2 * c;
        float2 v0 = make_float2(oacc[nf][0] * inv0, oacc[nf][1] * inv0);
        float2 v1 = make_float2(oacc[nf][2] * inv1, oacc[nf][3] * inv1);
        *(float2*)(o0 + col) = v0;
        *(float2*)(o1 + col) = v1;
    }
}

// ---------------- router ----------------
__global__ void router_k(const float* __restrict__ hn, const float* __restrict__ rw,
                         const float* __restrict__ rb,
                         int* __restrict__ cnt, int* __restrict__ tok, float* __restrict__ twt)
{
    int t = blockIdx.x;
    __shared__ float red[128][NE];
    float accv[NE];
    #pragma unroll
    for (int e = 0; e < NE; e++) accv[e] = 0.f;
    const float* xr = hn + (size_t)t * HH;
    for (int k = threadIdx.x; k < HH; k += 128) {
        float xv = xr[k];
        const float* w = rw + (size_t)k * NE;
        #pragma unroll
        for (int e = 0; e < NE; e++) accv[e] += xv * w[e];
    }
    #pragma unroll
    for (int e = 0; e < NE; e++) red[threadIdx.x][e] = accv[e];
    __syncthreads();
    for (int s = 64; s > 0; s >>= 1) {
        if (threadIdx.x < s)
            #pragma unroll
            for (int e = 0; e < NE; e++) red[threadIdx.x][e] += red[threadIdx.x + s][e];
        __syncthreads();
    }
    if (threadIdx.x == 0) {
        float p[NE];
        #pragma unroll
        for (int e = 0; e < NE; e++) {
            float lg = red[0][e] + rb[e];
            p[e] = 1.f / (1.f + expf(-lg));
        }
        int e1 = 0;
        for (int e = 1; e < NE; e++) if (p[e] > p[e1]) e1 = e;
        int e2 = -1;
        for (int e = 0; e < NE; e++) if (e != e1 && (e2 < 0 || p[e] > p[e2])) e2 = e;
        float s2 = p[e1] + p[e2];
        float w1 = p[e1] / s2, w2 = p[e2] / s2;
        int a = atomicAdd(&cnt[e1], 1); tok[e1 * TK + a] = t; twt[e1 * TK + a] = w1;
        int b = atomicAdd(&cnt[e2], 1); tok[e2 * TK + b] = t; twt[e2 * TK + b] = w2;
    }
}

__global__ void silu_mul_k(const float* __restrict__ g, const float* __restrict__ u,
                           float* __restrict__ y, int n)
{
    int i = blockIdx.x * 256 + threadIdx.x;
    if (i < n) {
        float gv = g[i];
        y[i] = (gv / (1.f + expf(-gv))) * u[i];
    }
}

__global__ void silu_mul_moe(const float* __restrict__ g, const float* __restrict__ u,
                             float* __restrict__ y, const int* __restrict__ cnt)
{
    const size_t TI = (size_t)TK * II;
    int e = blockIdx.y;
    int i = blockIdx.x * 256 + threadIdx.x;
    if (i / II >= cnt[e]) return;
    size_t idx = (size_t)e * TI + i;
    float gv = g[idx];
    y[idx] = (gv / (1.f + expf(-gv))) * u[idx];
}

__global__ void usage_k(const int* __restrict__ cnt, float* __restrict__ out)
{
    int e = threadIdx.x;
    if (e < NE) out[e] = (float)cnt[e];
}

// ---------------- host-side dispatch ----------------
static const int SMEM1  = (2 * (2560 + 2176) + 128) * 4;      // 38400 (tf32)
static const int SMEMB  = (2 * (GASZ + GBSZ)) * 4;            // 37888 (bf16)
static const int SMEMF  = (64 * FQS + 32 * FKS + 64 * FQS + 32 * FKS) * 4;  // 36864

// single-segment bf16 GEMM
static void GB(cudaStream_t st,
               const float* A, int lda, const float* B, int ldb,
               float* C, int ldc, int M, int N, int K,
               const float* adds, int splitK)
{
    dim3 grid(N / 128, M / 128, splitK);
    gemm_bf<<<grid, 256, SMEMB, st>>>(A, lda,
                                      B, ldb, C, ldc, N,
                                      nullptr, 0, nullptr, 0, 0,
                                      nullptr, 0, nullptr, 0,
                                      M, N, K, adds, splitK);
}

static void G1(cudaStream_t st,
               const float* A, int lda, size_t eas,
               const float* B, int ldb, size_t ebs,
               float* C, int ldc, size_t ecs,
               int M, int N, int K, int nz,
               const int* tokB, int ga, int sc,
               const float* wtB, int accA, const int* cntB)
{
    dim3 grid(N / 128, (M + 127) / 128, nz);
    gemm_tc<<<grid, 256, SMEM1, st>>>(A, lda, eas, B, ldb, ebs, C, ldc, ecs,
                                      M, N, K, tokB, ga, sc, wtB, accA, cntB);
}

extern "C" void kernel_launch(void* const* d_in, const int* in_sizes, int n_in,
                              void* d_out, int out_size)
{
    const float* x        = (const float*)d_in[0];
    const float* cosp     = (const float*)d_in[1];
    const float* sinp     = (const float*)d_in[2];
    const float* maskp    = (const float*)d_in[3];
    const float* ln1      = (const float*)d_in[4];
    const float* ln2      = (const float*)d_in[5];
    const float* kv_down  = (const float*)d_in[6];
    const float* kv_norm  = (const float*)d_in[7];
    const float* w_uk     = (const float*)d_in[8];
    const float* w_ur     = (const float*)d_in[9];
    const float* w_uv     = (const float*)d_in[10];
    const float* q_down   = (const float*)d_in[11];
    const float* q_norm   = (const float*)d_in[12];
    const float* w_uq     = (const float*)d_in[13];
    const float* w_qr     = (const float*)d_in[14];
    const float* o_proj   = (const float*)d_in[15];
    const float* sh_gate  = (const float*)d_in[16];
    const float* sh_up    = (const float*)d_in[17];
    const float* sh_down  = (const float*)d_in[18];
    const float* r_gate   = (const float*)d_in[19];
    const float* r_up     = (const float*)d_in[20];
    const float* r_down   = (const float*)d_in[21];
    const float* router_w = (const float*)d_in[22];
    const float* router_b = (const float*)d_in[23];
    float* out = (float*)d_out;

    float *xi, *cq, *ckv, *qn, *qr, *kn, *kr, *vx, *q, *k, *o, *h, *hn, *gt, *ut, *act, *twt;
    int *cnt, *tok;
    cudaGetSymbolAddress((void**)&xi,  g_xi);
    cudaGetSymbolAddress((void**)&cq,  g_cq);
    cudaGetSymbolAddress((void**)&ckv, g_ckv);
    cudaGetSymbolAddress((void**)&qn,  g_qn);
    cudaGetSymbolAddress((void**)&qr,  g_qr);
    cudaGetSymbolAddress((void**)&kn,  g_kn);
    cudaGetSymbolAddress((void**)&kr,  g_kr);
    cudaGetSymbolAddress((void**)&vx,  g_vx);
    cudaGetSymbolAddress((void**)&q,   g_q);
    cudaGetSymbolAddress((void**)&k,   g_k);
    cudaGetSymbolAddress((void**)&o,   g_o);
    cudaGetSymbolAddress((void**)&h,   g_h);
    cudaGetSymbolAddress((void**)&hn,  g_hn);
    cudaGetSymbolAddress((void**)&gt,  g_gt);
    cudaGetSymbolAddress((void**)&ut,  g_ut);
    cudaGetSymbolAddress((void**)&act, g_act);
    cudaGetSymbolAddress((void**)&twt, g_twt);
    cudaGetSymbolAddress((void**)&cnt, g_cnt);
    cudaGetSymbolAddress((void**)&tok, g_tok);

    cudaFuncSetAttribute(gemm_tc,  cudaFuncAttributeMaxDynamicSharedMemorySize, SMEM1);
    cudaFuncSetAttribute(gemm_bf,  cudaFuncAttributeMaxDynamicSharedMemorySize, SMEMB);
    cudaFuncSetAttribute(flash_bf, cudaFuncAttributeMaxDynamicSharedMemorySize, SMEMF);

    cudaStream_t s0 = 0, s1;
    cudaStreamCreateWithFlags(&s1, cudaStreamNonBlocking);
    cudaEvent_t ev0, ev1, ev2, ev3;
    cudaEventCreateWithFlags(&ev0, cudaEventDisableTiming);
    cudaEventCreateWithFlags(&ev1, cudaEventDisableTiming);
    cudaEventCreateWithFlags(&ev2, cudaEventDisableTiming);
    cudaEventCreateWithFlags(&ev3, cudaEventDisableTiming);

    const size_t TI = (size_t)TK * II;

    // ---- MLA attention (bf16 single-pass: attenuated ~300x by o_proj scale) ----
    rms_k<<<TK, 256, 0, s0>>>(x, ln1, xi, HH);
    cudaEventRecord(ev0, s0);
    cudaStreamWaitEvent(s1, ev0, 0);

    // q-chain on s0
    cudaMemsetAsync(cq, 0, (size_t)TK * 128 * sizeof(float), s0);
    GB(s0, xi, HH, q_down, 128, cq, 128, TK, 128, HH, nullptr, 4);
    rms_k<<<TK, 128, 0, s0>>>(cq, q_norm, cq, 128);
    {   // merged w_uq | w_qr (2 segments, N=1024)
        dim3 grid(1024 / 128, TK / 128, 1);
        gemm_bf<<<grid, 256, SMEMB, s0>>>(cq, 128,
                                          w_uq, 512, qn, 512, 512,
                                          w_qr, 512, qr, 512, 512,
                                          nullptr, 0, nullptr, 0,
                                          TK, 1024, 128, nullptr, 1);
    }

    // kv-chain on s1
    cudaMemsetAsync(ckv, 0, (size_t)TK * 128 * sizeof(float), s1);
    GB(s1, xi, HH, kv_down, 128, ckv, 128, TK, 128, HH, nullptr, 4);
    rms_k<<<TK, 128, 0, s1>>>(ckv, kv_norm, ckv, 128);
    {   // merged w_uk | w_ur | w_uv (3 segments, N=2048)
        dim3 grid(2048 / 128, TK / 128, 1);
        gemm_bf<<<grid, 256, SMEMB, s1>>>(ckv, 128,
                                          w_uk, 512, kn, 512, 512,
                                          w_ur, 512, kr, 512, 512,
                                          w_uv, 1024, vx, 1024,
                                          TK, 2048, 128, nullptr, 1);
    }
    cudaEventRecord(ev1, s1);
    cudaStreamWaitEvent(s0, ev1, 0);

    assemble_k<<<(BHN * SS * 64) / 256, 256, 0, s0>>>(qn, qr, kn, kr, cosp, sinp, q, k);
    flash_bf<<<dim3(SS / 64, BHN), 128, SMEMF, s0>>>(q, k, vx, maskp, o);
    GB(s0, o, HH, o_proj, HH, h, HH, TK, HH, HH, x, 1);   // h = x + o@Wo

    // ---- MoE (tf32: holds the error budget) ----
    rms_k<<<TK, 256, 0, s0>>>(h, ln2, hn, HH);
    cudaMemsetAsync(cnt, 0, NE * sizeof(int), s0);
    router_k<<<TK, 128, 0, s0>>>(hn, router_w, router_b, cnt, tok, twt);
    cudaMemcpyAsync(out, h, (size_t)TK * HH * sizeof(float), cudaMemcpyDeviceToDevice, s0);
    cudaEventRecord(ev2, s0);
    cudaStreamWaitEvent(s1, ev2, 0);

    // shared experts on s0 (dense, z=2): scratch [0, 2*TI)
    G1(s0, hn, HH, 0,  sh_gate, II, (size_t)HH * II,  gt, II, TI,  TK, II, HH, 2,
       nullptr, 0, 0, nullptr, 0, nullptr);
    G1(s0, hn, HH, 0,  sh_up, II, (size_t)HH * II,  ut, II, TI,  TK, II, HH, 2,
       nullptr, 0, 0, nullptr, 0, nullptr);
    silu_mul_k<<<(2 * (int)TI + 255) / 256, 256, 0, s0>>>(gt, ut, act, 2 * (int)TI);
    G1(s0, act, II, TI,  sh_down, HH, (size_t)II * HH,  out, HH, 0,  TK, HH, II, 2,
       nullptr, 0, 0, nullptr, 1, nullptr);

    // routed experts on s1 (sparse compact rows, z=8): scratch [2*TI, 10*TI)
    float* gt2 = gt + 2 * TI;
    float* ut2 = ut + 2 * TI;
    float* act2 = act + 2 * TI;
    G1(s1, hn, HH, 0,  r_gate, II, (size_t)HH * II,  gt2, II, TI,  TK, II, HH, NE,
       tok, 1, 0, nullptr, 0, cnt);
    G1(s1, hn, HH, 0,  r_up, II, (size_t)HH * II,  ut2, II, TI,  TK, II, HH, NE,
       tok, 1, 0, nullptr, 0, cnt);
    silu_mul_moe<<<dim3(((int)TI + 255) / 256, NE), 256, 0, s1>>>(gt2, ut2, act2, cnt);
    G1(s1, act2, II, TI,  r_down, HH, (size_t)II * HH,  out, HH, 0,  TK, HH, II, NE,
       tok, 0, 1, twt, 0, cnt);
    cudaEventRecord(ev3, s1);
    cudaStreamWaitEvent(s0, ev3, 0);

    usage_k<<<1, NE, 0, s0>>>(cnt, out + (size_t)TK * HH);
}

// round 12
// speedup vs baseline: 7.8035x; 1.1471x over previous
#include <cuda_runtime.h>
#include <cuda_bf16.h>
#include <math.h>
#include <stdint.h>

// ---------------- problem constants ----------------
#define TK   4096      // tokens = B*S
#define HH   1024      // hidden
#define SS   2048      // seq len
#define NHH  16        // heads
#define BHN  32        // B*NH
#define II   384       // expert intermediate
#define NE   8         // routed experts

// ---------------- scratch ----------------
__device__ float g_xi [TK*HH];
__device__ float g_cq [TK*128];
__device__ float g_ckv[TK*128];
__device__ float g_qn [TK*512];
__device__ float g_qr [TK*512];
__device__ float g_kn [TK*512];
__device__ float g_kr [TK*512];
__device__ float g_vx [TK*HH];
__device__ float g_q  [TK*HH];   // [bh][s][64]
__device__ float g_k  [TK*HH];
__device__ float g_o  [TK*HH];   // [b][s][h*64+d]
__device__ float g_h  [TK*HH];
__device__ float g_hn [TK*HH];
__device__ float g_gt [(NE+2)*TK*II];
__device__ float g_ut [(NE+2)*TK*II];
__device__ float g_act[(NE+2)*TK*II];
__device__ int   g_cnt[NE];
__device__ int   g_tok[NE*TK];
__device__ float g_twt[NE*TK];

// ---------------- mma helpers ----------------
__device__ __forceinline__ void mma16(float* c, const uint32_t* a, const uint32_t* b) {
    asm volatile(
        "mma.sync.aligned.m16n8k16.row.col.f32.bf16.bf16.f32 "
        "{%0,%1,%2,%3}, {%4,%5,%6,%7}, {%8,%9}, {%0,%1,%2,%3};\n"
        : "+f"(c[0]), "+f"(c[1]), "+f"(c[2]), "+f"(c[3])
        : "r"(a[0]), "r"(a[1]), "r"(a[2]), "r"(a[3]), "r"(b[0]), "r"(b[1]));
}
__device__ __forceinline__ uint32_t pkbf2(float a, float b) {
    __nv_bfloat162 t = __floats2bfloat162_rn(a, b);
    return *reinterpret_cast<uint32_t*>(&t);
}

// ---------------- unified bf16 GEMM ----------------
// Pipelined (LDG early / STS late), up to 3 N-segments, expert batching over
// blockIdx.z, gather/scatter row lists, per-row scale, atomic acc, fused
// addsrc, split-K (then blockIdx.z = K-chunk, single expert).
#define GASTR 20
#define GBSTR 136
#define GASZ  (128*GASTR)   // 128 rows x 16 kpairs (BK=32)
#define GBSZ  (16*GBSTR)

struct GArgs {
    const float* A; int lda; size_t aes;
    const float* B[3]; int ldb[3]; size_t bes[3];
    float*       C[3]; int ldc[3]; size_t ces[3];
    int n1, n2;
    int M, N, K;
    const int* tok; int gatherA; int scatterC;
    const float* wt; const float* addsrc; int accAtomic;
    const int* cnt; int splitK;
};

__global__ void __launch_bounds__(256) gemm_bfx(GArgs ga)
{
    extern __shared__ uint32_t sm[];
    uint32_t* As = sm;              // [2][GASZ]
    uint32_t* Bs = sm + 2 * GASZ;   // [2][GBSZ]
    __shared__ int idxs[128];

    int e, kbase, Ke;
    if (ga.splitK > 1) { e = 0; Ke = ga.K / ga.splitK; kbase = blockIdx.z * Ke; }
    else               { e = blockIdx.z; Ke = ga.K; kbase = 0; }

    const int m0 = blockIdx.y * 128;
    const int n0 = blockIdx.x * 128;

    // segment select (uniform per block; splits multiple of 128)
    int seg = 0, nloc = n0;
    if (ga.B[1] && n0 >= ga.n1) {
        if (ga.B[2] && n0 >= ga.n1 + ga.n2) { seg = 2; nloc = n0 - ga.n1 - ga.n2; }
        else                                { seg = 1; nloc = n0 - ga.n1; }
    }
    const float* A = ga.A + (size_t)e * ga.aes;
    const float* B = ga.B[seg] + (size_t)e * ga.bes[seg];
    float*       C = ga.C[seg] + (size_t)e * ga.ces[seg];
    const int lda = ga.lda, ldb = ga.ldb[seg], ldc = ga.ldc[seg];
    const int* idx = ga.tok ? ga.tok + (size_t)e * TK : nullptr;
    const float* wt = ga.wt ? ga.wt + (size_t)e * TK : nullptr;
    const int effM = ga.cnt ? ga.cnt[e] : ga.M;
    if (m0 >= effM) return;

    const int tid = threadIdx.x;
    if (idx) {
        for (int i = tid; i < 128; i += 256) {
            int m = m0 + i;
            idxs[i] = (m < effM) ? idx[m] : 0;
        }
        __syncthreads();
    }

    // per-thread load coords
    const int am = tid >> 4, ak2 = tid & 15;       // rows am+i*16, kpair ak2
    const int bn = tid & 127, bk2 = tid >> 7;      // col bn, kpairs bk2+i*2

    float2 areg[8];
    float  breg[16];

    auto ldgTile = [&](int kt) {
        #pragma unroll
        for (int i = 0; i < 8; i++) {
            int m = am + i * 16;
            int mg = m0 + m;
            float2 v = make_float2(0.f, 0.f);
            if (mg < effM) {
                int row = ga.gatherA ? idxs[m] : mg;
                v = *(const float2*)(A + (size_t)row * lda + kt + 2 * ak2);
            }
            areg[i] = v;
        }
        #pragma unroll
        for (int i = 0; i < 8; i++) {
            int kk = kt + 2 * (bk2 + i * 2);
            breg[2 * i]     = B[(size_t)kk * ldb + nloc + bn];
            breg[2 * i + 1] = B[(size_t)(kk + 1) * ldb + nloc + bn];
        }
    };
    auto stsTile = [&](int buf) {
        uint32_t* Ad = As + buf * GASZ;
        #pragma unroll
        for (int i = 0; i < 8; i++)
            Ad[(am + i * 16) * GASTR + ak2] = pkbf2(areg[i].x, areg[i].y);
        uint32_t* Bd = Bs + buf * GBSZ;
        #pragma unroll
        for (int i = 0; i < 8; i++)
            Bd[(bk2 + i * 2) * GBSTR + bn] = pkbf2(breg[2 * i], breg[2 * i + 1]);
    };

    const int lane = tid & 31, wid = tid >> 5;
    const int wm = (wid >> 2) * 64;
    const int wn = (wid & 3) * 32;
    const int g = lane >> 2, c = lane & 3;

    float acc[4][4][4];
    #pragma unroll
    for (int i = 0; i < 4; i++)
        #pragma unroll
        for (int j = 0; j < 4; j++)
            #pragma unroll
            for (int r = 0; r < 4; r++) acc[i][j][r] = 0.f;

    ldgTile(kbase);
    stsTile(0);
    __syncthreads();

    const int nbuf = Ke >> 5;
    for (int t = 0; t < nbuf; t++) {
        int cur = t & 1;
        if (t + 1 < nbuf) ldgTile(kbase + ((t + 1) << 5));

        const uint32_t* Ab = As + cur * GASZ;
        const uint32_t* Bb = Bs + cur * GBSZ;
        #pragma unroll
        for (int kp = 0; kp < 16; kp += 8) {
            uint32_t af[4][4];
            #pragma unroll
            for (int mt = 0; mt < 4; mt++) {
                int mb = wm + mt * 16;
                af[mt][0] = Ab[(mb + g) * GASTR + kp + c];
                af[mt][1] = Ab[(mb + g + 8) * GASTR + kp + c];
                af[mt][2] = Ab[(mb + g) * GASTR + kp + c + 4];
                af[mt][3] = Ab[(mb + g + 8) * GASTR + kp + c + 4];
            }
            uint32_t bf[4][2];
            #pragma unroll
            for (int nt = 0; nt < 4; nt++) {
                int nb = wn + nt * 8;
                bf[nt][0] = Bb[(kp + c) * GBSTR + nb + g];
                bf[nt][1] = Bb[(kp + c + 4) * GBSTR + nb + g];
            }
            #pragma unroll
            for (int mt = 0; mt < 4; mt++)
                #pragma unroll
                for (int nt = 0; nt < 4; nt++)
                    mma16(acc[mt][nt], af[mt], bf[nt]);
        }
        if (t + 1 < nbuf) stsTile(cur ^ 1);
        __syncthreads();
    }

    #pragma unroll
    for (int mt = 0; mt < 4; mt++) {
        #pragma unroll
        for (int h2 = 0; h2 < 2; h2++) {
            int ml = wm + mt * 16 + g + h2 * 8;
            int m = m0 + ml;
            if (m >= effM) continue;
            int crow = ga.scatterC ? idxs[ml] : m;
            float sc = wt ? wt[m] : 1.f;
            #pragma unroll
            for (int nt = 0; nt < 4; nt++) {
                int ncol = nloc + wn + nt * 8 + c * 2;
                float v0 = acc[mt][nt][h2 * 2 + 0];
                float v1 = acc[mt][nt][h2 * 2 + 1];
                float* cp = C + (size_t)crow * ldc + ncol;
                if (ga.splitK > 1) {
                    atomicAdd(cp, v0); atomicAdd(cp + 1, v1);
                } else if (wt) {
                    atomicAdd(cp, sc * v0); atomicAdd(cp + 1, sc * v1);
                } else if (ga.accAtomic) {
                    atomicAdd(cp, v0); atomicAdd(cp + 1, v1);
                } else if (ga.addsrc) {
                    const float* ap = ga.addsrc + (size_t)m * ldc + ncol;
                    cp[0] = v0 + ap[0]; cp[1] = v1 + ap[1];
                } else {
                    cp[0] = v0; cp[1] = v1;
                }
            }
        }
    }
}

// ---------------- RMSNorm ----------------
__global__ void rms_k(const float* __restrict__ x, const float* __restrict__ w,
                      float* __restrict__ y, int D)
{
    int t = blockIdx.x;
    const float* xr = x + (size_t)t * D;
    float* yr = y + (size_t)t * D;
    float ss = 0.f;
    for (int k = threadIdx.x; k < D; k += blockDim.x) { float v = xr[k]; ss += v * v; }
    __shared__ float sh[32];
    int lane = threadIdx.x & 31, wid = threadIdx.x >> 5;
    #pragma unroll
    for (int o = 16; o > 0; o >>= 1) ss += __shfl_xor_sync(0xffffffffu, ss, o);
    if (lane == 0) sh[wid] = ss;
    __syncthreads();
    if (threadIdx.x == 0) {
        float tot = 0.f;
        int nw = blockDim.x >> 5;
        for (int i = 0; i < nw; i++) tot += sh[i];
        sh[0] = tot;
    }
    __syncthreads();
    float r = rsqrtf(sh[0] / (float)D + 1e-5f);
    for (int k = threadIdx.x; k < D; k += blockDim.x) yr[k] = w[k] * xr[k] * r;
}

// ---------------- assemble Q/K with RoPE ----------------
__global__ void assemble_k(const float* __restrict__ qn, const float* __restrict__ qr,
                           const float* __restrict__ kn, const float* __restrict__ kr,
                           const float* __restrict__ cosp, const float* __restrict__ sinp,
                           float* __restrict__ Q, float* __restrict__ K)
{
    int idx = blockIdx.x * blockDim.x + threadIdx.x;
    if (idx >= BHN * SS * 64) return;
    int d  = idx & 63;
    int s  = (idx >> 6) & (SS - 1);
    int bh = idx >> 17;
    int b  = bh >> 4, h = bh & 15;
    int t  = b * SS + s;
    float qv, kv;
    if (d < 32) {
        qv = qn[(size_t)t * 512 + h * 32 + d];
        kv = kn[(size_t)t * 512 + h * 32 + d];
    } else {
        int j = d - 32;
        float cc = cosp[s * 32 + j];
        float sn = sinp[s * 32 + j];
        float q1 = qr[(size_t)t * 512 + h * 32 + j];
        float q2 = (j < 16) ? -qr[(size_t)t * 512 + h * 32 + j + 16]
                            :  qr[(size_t)t * 512 + h * 32 + j - 16];
        qv = q1 * cc + q2 * sn;
        float k1 = kr[(size_t)t * 512 + h * 32 + j];
        float k2 = (j < 16) ? -kr[(size_t)t * 512 + h * 32 + j + 16]
                            :  kr[(size_t)t * 512 + h * 32 + j - 16];
        kv = k1 * cc + k2 * sn;
    }
    Q[idx] = qv;
    K[idx] = kv;
}

// ---------------- flash attention, bf16 tensor cores, prefetched KV ----------------
#define FQS 36
#define FKS 72
__global__ void flash_bf(
    const float* __restrict__ Q, const float* __restrict__ Kg,
    const float* __restrict__ Vx, const float* __restrict__ maskp,
    float* __restrict__ O)
{
    extern __shared__ uint32_t sm[];
    uint32_t* Qs = sm;                       // [row][kpair]  64*36
    uint32_t* Kt = sm + 64 * FQS;            // [kpair][key]  32*72
    uint32_t* Ps = Kt + 32 * FKS;            // [row][keypair] 64*36
    uint32_t* Vs = Ps + 64 * FQS;            // [keypair][d]  32*72

    const int bh = blockIdx.y;
    const int q0 = blockIdx.x * 64;
    const int b  = bh >> 4, hh = bh & 15;
    const float* Qb = Q  + (size_t)bh * SS * 64;
    const float* Kb = Kg + (size_t)bh * SS * 64;
    const float* Vb = Vx + (size_t)b * SS * HH + hh * 64;

    const int tid = threadIdx.x;
    const int w = tid >> 5, lane = tid & 31;
    const int g = lane >> 2, c = lane & 3;
    const int wrow = w * 16;

    const int lr  = tid & 63;
    const int lc0 = (tid >> 6) * 32;
    const int vkp = tid & 31;
    const int vdb = (tid >> 5) * 16;

    {
        const float4* src = (const float4*)(Qb + (size_t)(q0 + lr) * 64 + lc0);
        #pragma unroll
        for (int i = 0; i < 8; i++) {
            float4 v = src[i];
            uint32_t* d = Qs + lr * FQS + (lc0 >> 1) + i * 2;
            d[0] = pkbf2(v.x, v.y);
            d[1] = pkbf2(v.z, v.w);
        }
    }

    float4 kreg[8];
    float4 vreg0[4], vreg1[4];
    auto ldgKV = [&](int k0) {
        const float4* ks = (const float4*)(Kb + (size_t)(k0 + lr) * 64 + lc0);
        #pragma unroll
        for (int i = 0; i < 8; i++) kreg[i] = ks[i];
        const float* v0p = Vb + (size_t)(k0 + 2 * vkp) * HH + vdb;
        const float* v1p = v0p + HH;
        #pragma unroll
        for (int i = 0; i < 4; i++) {
            vreg0[i] = *(const float4*)(v0p + i * 4);
            vreg1[i] = *(const float4*)(v1p + i * 4);
        }
    };
    auto stsKV = [&]() {
        #pragma unroll
        for (int i = 0; i < 8; i++) {
            float4 kv = kreg[i];
            int dp = (lc0 + i * 4) >> 1;
            Kt[(dp + 0) * FKS + lr] = pkbf2(kv.x, kv.y);
            Kt[(dp + 1) * FKS + lr] = pkbf2(kv.z, kv.w);
        }
        #pragma unroll
        for (int i = 0; i < 4; i++) {
            float4 a = vreg0[i];
            float4 bb = vreg1[i];
            uint32_t* vd = Vs + vkp * FKS + vdb + i * 4;
            vd[0] = pkbf2(a.x, bb.x);
            vd[1] = pkbf2(a.y, bb.y);
            vd[2] = pkbf2(a.z, bb.z);
            vd[3] = pkbf2(a.w, bb.w);
        }
    };

    float oacc[8][4];
    #pragma unroll
    for (int nf = 0; nf < 8; nf++)
        #pragma unroll
        for (int r = 0; r < 4; r++) oacc[nf][r] = 0.f;
    float m0 = -1e30f, m1 = -1e30f, l0 = 0.f, l1 = 0.f;

    const float* mr0 = maskp + (size_t)(q0 + wrow + g) * SS;
    const float* mr1 = mr0 + 8 * SS;

    ldgKV(0);
    for (int k0 = 0; k0 < SS; k0 += 64) {
        __syncthreads();
        stsKV();
        __syncthreads();
        if (k0 + 64 < SS) ldgKV(k0 + 64);

        float sacc[8][4];
        #pragma unroll
        for (int nf = 0; nf < 8; nf++)
            #pragma unroll
            for (int r = 0; r < 4; r++) sacc[nf][r] = 0.f;
        #pragma unroll
        for (int ks = 0; ks < 32; ks += 8) {
            uint32_t af[4];
            af[0] = Qs[(wrow + g) * FQS + ks + c];
            af[1] = Qs[(wrow + g + 8) * FQS + ks + c];
            af[2] = Qs[(wrow + g) * FQS + ks + c + 4];
            af[3] = Qs[(wrow + g + 8) * FQS + ks + c + 4];
            #pragma unroll
            for (int nf = 0; nf < 8; nf++) {
                uint32_t bf[2];
                bf[0] = Kt[(ks + c) * FKS + nf * 8 + g];
                bf[1] = Kt[(ks + c + 4) * FKS + nf * 8 + g];
                mma16(sacc[nf], af, bf);
            }
        }

        float mx0 = -1e30f, mx1 = -1e30f;
        #pragma unroll
        for (int nf = 0; nf < 8; nf++) {
            float2 mk0 = *(const float2*)(mr0 + k0 + nf * 8 + 2 * c);
            float2 mk1 = *(const float2*)(mr1 + k0 + nf * 8 + 2 * c);
            sacc[nf][0] = sacc[nf][0] * 0.125f + mk0.x;
            sacc[nf][1] = sacc[nf][1] * 0.125f + mk0.y;
            sacc[nf][2] = sacc[nf][2] * 0.125f + mk1.x;
            sacc[nf][3] = sacc[nf][3] * 0.125f + mk1.y;
            mx0 = fmaxf(mx0, fmaxf(sacc[nf][0], sacc[nf][1]));
            mx1 = fmaxf(mx1, fmaxf(sacc[nf][2], sacc[nf][3]));
        }
        mx0 = fmaxf(mx0, __shfl_xor_sync(0xffffffffu, mx0, 1));
        mx0 = fmaxf(mx0, __shfl_xor_sync(0xffffffffu, mx0, 2));
        mx1 = fmaxf(mx1, __shfl_xor_sync(0xffffffffu, mx1, 1));
        mx1 = fmaxf(mx1, __shfl_xor_sync(0xffffffffu, mx1, 2));

        float mn0 = fmaxf(m0, mx0), mn1 = fmaxf(m1, mx1);
        float cr0 = __expf(m0 - mn0), cr1 = __expf(m1 - mn1);
        m0 = mn0; m1 = mn1;
        float rs0 = 0.f, rs1 = 0.f;
        #pragma unroll
        for (int nf = 0; nf < 8; nf++) {
            sacc[nf][0] = __expf(sacc[nf][0] - mn0);
            sacc[nf][1] = __expf(sacc[nf][1] - mn0);
            sacc[nf][2] = __expf(sacc[nf][2] - mn1);
            sacc[nf][3] = __expf(sacc[nf][3] - mn1);
            rs0 += sacc[nf][0] + sacc[nf][1];
            rs1 += sacc[nf][2] + sacc[nf][3];
        }
        rs0 += __shfl_xor_sync(0xffffffffu, rs0, 1);
        rs0 += __shfl_xor_sync(0xffffffffu, rs0, 2);
        rs1 += __shfl_xor_sync(0xffffffffu, rs1, 1);
        rs1 += __shfl_xor_sync(0xffffffffu, rs1, 2);
        l0 = l0 * cr0 + rs0;
        l1 = l1 * cr1 + rs1;
        #pragma unroll
        for (int nf = 0; nf < 8; nf++) {
            oacc[nf][0] *= cr0; oacc[nf][1] *= cr0;
            oacc[nf][2] *= cr1; oacc[nf][3] *= cr1;
        }

        #pragma unroll
        for (int nf = 0; nf < 8; nf++) {
            int kp = nf * 4 + c;
            Ps[(wrow + g) * FQS + kp]     = pkbf2(sacc[nf][0], sacc[nf][1]);
            Ps[(wrow + g + 8) * FQS + kp] = pkbf2(sacc[nf][2], sacc[nf][3]);
        }
        __syncthreads();

        #pragma unroll
        for (int kk = 0; kk < 32; kk += 8) {
            uint32_t af[4];
            af[0] = Ps[(wrow + g) * FQS + kk + c];
            af[1] = Ps[(wrow + g + 8) * FQS + kk + c];
            af[2] = Ps[(wrow + g) * FQS + kk + c + 4];
            af[3] = Ps[(wrow + g + 8) * FQS + kk + c + 4];
            #pragma unroll
            for (int nf = 0; nf < 8; nf++) {
                uint32_t bf[2];
                bf[0] = Vs[(kk + c) * FKS + nf * 8 + g];
                bf[1] = Vs[(kk + c + 4) * FKS + nf * 8 + g];
                mma16(oacc[nf], af, bf);
            }
        }
    }

    float inv0 = 1.f / l0, inv1 = 1.f / l1;
    int row0 = q0 + wrow + g;
    float* o0 = O + ((size_t)(b * SS + row0)) * HH + hh * 64;
    float* o1 = o0 + 8 * (size_t)HH;
    #pragma unroll
    for (int nf = 0; nf < 8; nf++) {
        int col = nf * 8 + 2 * c;
        float2 v0 = make_float2(oacc[nf][0] * inv0, oacc[nf][1] * inv0);
        float2 v1 = make_float2(oacc[nf][2] * inv1, oacc[nf][3] * inv1);
        *(float2*)(o0 + col) = v0;
        *(float2*)(o1 + col) = v1;
    }
}

// ---------------- router ----------------
__global__ void router_k(const float* __restrict__ hn, const float* __restrict__ rw,
                         const float* __restrict__ rb,
                         int* __restrict__ cnt, int* __restrict__ tok, float* __restrict__ twt)
{
    int t = blockIdx.x;
    __shared__ float red[128][NE];
    float accv[NE];
    #pragma unroll
    for (int e = 0; e < NE; e++) accv[e] = 0.f;
    const float* xr = hn + (size_t)t * HH;
    for (int k = threadIdx.x; k < HH; k += 128) {
        float xv = xr[k];
        const float* w = rw + (size_t)k * NE;
        #pragma unroll
        for (int e = 0; e < NE; e++) accv[e] += xv * w[e];
    }
    #pragma unroll
    for (int e = 0; e < NE; e++) red[threadIdx.x][e] = accv[e];
    __syncthreads();
    for (int s = 64; s > 0; s >>= 1) {
        if (threadIdx.x < s)
            #pragma unroll
            for (int e = 0; e < NE; e++) red[threadIdx.x][e] += red[threadIdx.x + s][e];
        __syncthreads();
    }
    if (threadIdx.x == 0) {
        float p[NE];
        #pragma unroll
        for (int e = 0; e < NE; e++) {
            float lg = red[0][e] + rb[e];
            p[e] = 1.f / (1.f + expf(-lg));
        }
        int e1 = 0;
        for (int e = 1; e < NE; e++) if (p[e] > p[e1]) e1 = e;
        int e2 = -1;
        for (int e = 0; e < NE; e++) if (e != e1 && (e2 < 0 || p[e] > p[e2])) e2 = e;
        float s2 = p[e1] + p[e2];
        float w1 = p[e1] / s2, w2 = p[e2] / s2;
        int a = atomicAdd(&cnt[e1], 1); tok[e1 * TK + a] = t; twt[e1 * TK + a] = w1;
        int b = atomicAdd(&cnt[e2], 1); tok[e2 * TK + b] = t; twt[e2 * TK + b] = w2;
    }
}

__global__ void silu_mul_k(const float* __restrict__ g, const float* __restrict__ u,
                           float* __restrict__ y, int n)
{
    int i = blockIdx.x * 256 + threadIdx.x;
    if (i < n) {
        float gv = g[i];
        y[i] = (gv / (1.f + expf(-gv))) * u[i];
    }
}

__global__ void silu_mul_moe(const float* __restrict__ g, const float* __restrict__ u,
                             float* __restrict__ y, const int* __restrict__ cnt)
{
    const size_t TI = (size_t)TK * II;
    int e = blockIdx.y;
    int i = blockIdx.x * 256 + threadIdx.x;
    if (i / II >= cnt[e]) return;
    size_t idx = (size_t)e * TI + i;
    float gv = g[idx];
    y[idx] = (gv / (1.f + expf(-gv))) * u[idx];
}

__global__ void usage_k(const int* __restrict__ cnt, float* __restrict__ out)
{
    int e = threadIdx.x;
    if (e < NE) out[e] = (float)cnt[e];
}

// ---------------- host-side dispatch ----------------
static const int SMEMB = (2 * (GASZ + GBSZ)) * 4;   // 37888
static const int SMEMF = (64 * FQS + 32 * FKS + 64 * FQS + 32 * FKS) * 4;   // 36864

static GArgs mkargs(const float* A, int lda, size_t aes,
                    const float* B0, int ldb0, size_t bes0,
                    float* C0, int ldc0, size_t ces0,
                    int M, int N, int K)
{
    GArgs ga = {};
    ga.A = A; ga.lda = lda; ga.aes = aes;
    ga.B[0] = B0; ga.ldb[0] = ldb0; ga.bes[0] = bes0;
    ga.C[0] = C0; ga.ldc[0] = ldc0; ga.ces[0] = ces0;
    ga.n1 = N; ga.n2 = 0;
    ga.M = M; ga.N = N; ga.K = K;
    ga.splitK = 1;
    return ga;
}

static void launch(cudaStream_t st, const GArgs& ga, int nz)
{
    dim3 grid(ga.N / 128, (ga.M + 127) / 128, nz);
    gemm_bfx<<<grid, 256, SMEMB, st>>>(ga);
}

extern "C" void kernel_launch(void* const* d_in, const int* in_sizes, int n_in,
                              void* d_out, int out_size)
{
    const float* x        = (const float*)d_in[0];
    const float* cosp     = (const float*)d_in[1];
    const float* sinp     = (const float*)d_in[2];
    const float* maskp    = (const float*)d_in[3];
    const float* ln1      = (const float*)d_in[4];
    const float* ln2      = (const float*)d_in[5];
    const float* kv_down  = (const float*)d_in[6];
    const float* kv_norm  = (const float*)d_in[7];
    const float* w_uk     = (const float*)d_in[8];
    const float* w_ur     = (const float*)d_in[9];
    const float* w_uv     = (const float*)d_in[10];
    const float* q_down   = (const float*)d_in[11];
    const float* q_norm   = (const float*)d_in[12];
    const float* w_uq     = (const float*)d_in[13];
    const float* w_qr     = (const float*)d_in[14];
    const float* o_proj   = (const float*)d_in[15];
    const float* sh_gate  = (const float*)d_in[16];
    const float* sh_up    = (const float*)d_in[17];
    const float* sh_down  = (const float*)d_in[18];
    const float* r_gate   = (const float*)d_in[19];
    const float* r_up     = (const float*)d_in[20];
    const float* r_down   = (const float*)d_in[21];
    const float* router_w = (const float*)d_in[22];
    const float* router_b = (const float*)d_in[23];
    float* out = (float*)d_out;

    float *xi, *cq, *ckv, *qn, *qr, *kn, *kr, *vx, *q, *k, *o, *h, *hn, *gt, *ut, *act, *twt;
    int *cnt, *tok;
    cudaGetSymbolAddress((void**)&xi,  g_xi);
    cudaGetSymbolAddress((void**)&cq,  g_cq);
    cudaGetSymbolAddress((void**)&ckv, g_ckv);
    cudaGetSymbolAddress((void**)&qn,  g_qn);
    cudaGetSymbolAddress((void**)&qr,  g_qr);
    cudaGetSymbolAddress((void**)&kn,  g_kn);
    cudaGetSymbolAddress((void**)&kr,  g_kr);
    cudaGetSymbolAddress((void**)&vx,  g_vx);
    cudaGetSymbolAddress((void**)&q,   g_q);
    cudaGetSymbolAddress((void**)&k,   g_k);
    cudaGetSymbolAddress((void**)&o,   g_o);
    cudaGetSymbolAddress((void**)&h,   g_h);
    cudaGetSymbolAddress((void**)&hn,  g_hn);
    cudaGetSymbolAddress((void**)&gt,  g_gt);
    cudaGetSymbolAddress((void**)&ut,  g_ut);
    cudaGetSymbolAddress((void**)&act, g_act);
    cudaGetSymbolAddress((void**)&twt, g_twt);
    cudaGetSymbolAddress((void**)&cnt, g_cnt);
    cudaGetSymbolAddress((void**)&tok, g_tok);

    cudaFuncSetAttribute(gemm_bfx, cudaFuncAttributeMaxDynamicSharedMemorySize, SMEMB);
    cudaFuncSetAttribute(flash_bf, cudaFuncAttributeMaxDynamicSharedMemorySize, SMEMF);

    cudaStream_t s0 = 0, s1;
    cudaStreamCreateWithFlags(&s1, cudaStreamNonBlocking);
    cudaEvent_t ev0, ev1, ev2, ev3;
    cudaEventCreateWithFlags(&ev0, cudaEventDisableTiming);
    cudaEventCreateWithFlags(&ev1, cudaEventDisableTiming);
    cudaEventCreateWithFlags(&ev2, cudaEventDisableTiming);
    cudaEventCreateWithFlags(&ev3, cudaEventDisableTiming);

    const size_t TI = (size_t)TK * II;
    const size_t WE = (size_t)HH * II;   // expert weight stride (gate/up)
    const size_t WD = (size_t)II * HH;   // expert weight stride (down)

    // ---- MLA attention ----
    rms_k<<<TK, 256, 0, s0>>>(x, ln1, xi, HH);

    // merged q_down|kv_down, split-K=4 (zeroed outputs, atomic combine)
    cudaMemsetAsync(cq, 0, (size_t)TK * 128 * sizeof(float), s0);
    cudaMemsetAsync(ckv, 0, (size_t)TK * 128 * sizeof(float), s0);
    {
        GArgs ga = mkargs(xi, HH, 0, q_down, 128, 0, cq, 128, 0, TK, 256, HH);
        ga.n1 = 128;
        ga.B[1] = kv_down; ga.ldb[1] = 128; ga.bes[1] = 0;
        ga.C[1] = ckv;     ga.ldc[1] = 128; ga.ces[1] = 0;
        ga.splitK = 4;
        launch(s0, ga, 4);
    }
    rms_k<<<TK, 128, 0, s0>>>(cq, q_norm, cq, 128);
    cudaEventRecord(ev0, s0);
    cudaStreamWaitEvent(s1, ev0, 0);
    rms_k<<<TK, 128, 0, s1>>>(ckv, kv_norm, ckv, 128);

    // q-proj on s0: merged w_uq|w_qr (N=1024)
    {
        GArgs ga = mkargs(cq, 128, 0, w_uq, 512, 0, qn, 512, 0, TK, 1024, 128);
        ga.n1 = 512;
        ga.B[1] = w_qr; ga.ldb[1] = 512; ga.bes[1] = 0;
        ga.C[1] = qr;   ga.ldc[1] = 512; ga.ces[1] = 0;
        launch(s0, ga, 1);
    }
    // kv-proj on s1: merged w_uk|w_ur|w_uv (N=2048)
    {
        GArgs ga = mkargs(ckv, 128, 0, w_uk, 512, 0, kn, 512, 0, TK, 2048, 128);
        ga.n1 = 512; ga.n2 = 512;
        ga.B[1] = w_ur; ga.ldb[1] = 512;  ga.bes[1] = 0;
        ga.C[1] = kr;   ga.ldc[1] = 512;  ga.ces[1] = 0;
        ga.B[2] = w_uv; ga.ldb[2] = 1024; ga.bes[2] = 0;
        ga.C[2] = vx;   ga.ldc[2] = 1024; ga.ces[2] = 0;
        launch(s1, ga, 1);
    }
    cudaEventRecord(ev1, s1);
    cudaStreamWaitEvent(s0, ev1, 0);

    assemble_k<<<(BHN * SS * 64) / 256, 256, 0, s0>>>(qn, qr, kn, kr, cosp, sinp, q, k);
    flash_bf<<<dim3(SS / 64, BHN), 128, SMEMF, s0>>>(q, k, vx, maskp, o);
    {   // h = x + o @ o_proj
        GArgs ga = mkargs(o, HH, 0, o_proj, HH, 0, h, HH, 0, TK, HH, HH);
        ga.addsrc = x;
        launch(s0, ga, 1);
    }

    // ---- MoE (bf16; expert term is ~0.15 of |out| -> ~2.5e-4 rel err) ----
    rms_k<<<TK, 256, 0, s0>>>(h, ln2, hn, HH);
    cudaMemsetAsync(cnt, 0, NE * sizeof(int), s0);
    router_k<<<TK, 128, 0, s0>>>(hn, router_w, router_b, cnt, tok, twt);
    cudaMemcpyAsync(out, h, (size_t)TK * HH * sizeof(float), cudaMemcpyDeviceToDevice, s0);
    cudaEventRecord(ev2, s0);
    cudaStreamWaitEvent(s1, ev2, 0);

    // shared experts on s0 (z=2): merged gate|up (N=768), silu, down (atomic acc)
    {
        GArgs ga = mkargs(hn, HH, 0, sh_gate, II, WE, gt, II, TI, TK, 768, HH);
        ga.n1 = II;
        ga.B[1] = sh_up; ga.ldb[1] = II; ga.bes[1] = WE;
        ga.C[1] = ut;    ga.ldc[1] = II; ga.ces[1] = TI;
        launch(s0, ga, 2);
    }
    silu_mul_k<<<(2 * (int)TI + 255) / 256, 256, 0, s0>>>(gt, ut, act, 2 * (int)TI);
    {
        GArgs ga = mkargs(act, II, TI, sh_down, HH, WD, out, HH, 0, TK, HH, II);
        ga.accAtomic = 1;
        launch(s0, ga, 2);
    }

    // routed experts on s1 (z=8, gather): merged gate|up, silu, down (scatter+scale)
    float* gt2 = gt + 2 * TI;
    float* ut2 = ut + 2 * TI;
    float* act2 = act + 2 * TI;
    {
        GArgs ga = mkargs(hn, HH, 0, r_gate, II, WE, gt2, II, TI, TK, 768, HH);
        ga.n1 = II;
        ga.B[1] = r_up; ga.ldb[1] = II; ga.bes[1] = WE;
        ga.C[1] = ut2;  ga.ldc[1] = II; ga.ces[1] = TI;
        ga.tok = tok; ga.gatherA = 1; ga.cnt = cnt;
        launch(s1, ga, NE);
    }
    silu_mul_moe<<<dim3(((int)TI + 255) / 256, NE), 256, 0, s1>>>(gt2, ut2, act2, cnt);
    {
        GArgs ga = mkargs(act2, II, TI, r_down, HH, WD, out, HH, 0, TK, HH, II);
        ga.tok = tok; ga.scatterC = 1; ga.wt = twt; ga.cnt = cnt;
        launch(s1, ga, NE);
    }
    cudaEventRecord(ev3, s1);
    cudaStreamWaitEvent(s0, ev3, 0);

    usage_k<<<1, NE, 0, s0>>>(cnt, out + (size_t)TK * HH);
}

// round 13
// speedup vs baseline: 8.0535x; 1.0320x over previous
#include <cuda_runtime.h>
#include <cuda_bf16.h>
#include <math.h>
#include <stdint.h>

// ---------------- problem constants ----------------
#define TK   4096      // tokens = B*S
#define HH   1024      // hidden
#define SS   2048      // seq len
#define NHH  16        // heads
#define BHN  32        // B*NH
#define II   384       // expert intermediate
#define NE   8         // routed experts

// ---------------- scratch ----------------
__device__ float g_xi [TK*HH];
__device__ float g_cq [TK*128];
__device__ float g_ckv[TK*128];
__device__ float g_qn [TK*512];
__device__ float g_qr [TK*512];
__device__ float g_kn [TK*512];
__device__ float g_kr [TK*512];
__device__ float g_vx [TK*HH];
__device__ float g_q  [TK*HH];   // [bh][s][64]
__device__ float g_k  [TK*HH];
__device__ float g_o  [TK*HH];   // [b][s][h*64+d]
__device__ float g_h  [TK*HH];
__device__ float g_hn [TK*HH];
__device__ float g_gt [(NE+2)*TK*II];
__device__ float g_ut [(NE+2)*TK*II];
__device__ float g_act[(NE+2)*TK*II];
__device__ int   g_cnt[NE];
__device__ int   g_tok[NE*TK];
__device__ float g_twt[NE*TK];

// ---------------- mma helpers ----------------
__device__ __forceinline__ void mma16(float* c, const uint32_t* a, const uint32_t* b) {
    asm volatile(
        "mma.sync.aligned.m16n8k16.row.col.f32.bf16.bf16.f32 "
        "{%0,%1,%2,%3}, {%4,%5,%6,%7}, {%8,%9}, {%0,%1,%2,%3};\n"
        : "+f"(c[0]), "+f"(c[1]), "+f"(c[2]), "+f"(c[3])
        : "r"(a[0]), "r"(a[1]), "r"(a[2]), "r"(a[3]), "r"(b[0]), "r"(b[1]));
}
__device__ __forceinline__ uint32_t pkbf2(float a, float b) {
    __nv_bfloat162 t = __floats2bfloat162_rn(a, b);
    return *reinterpret_cast<uint32_t*>(&t);
}

// ---------------- unified bf16 GEMM ----------------
#define GASTR 20
#define GBSTR 136
#define GASZ  (128*GASTR)
#define GBSZ  (16*GBSTR)

struct GArgs {
    const float* A; int lda; size_t aes;
    const float* B[3]; int ldb[3]; size_t bes[3];
    float*       C[3]; int ldc[3]; size_t ces[3];
    int n1, n2;
    int M, N, K;
    const int* tok; int gatherA; int scatterC;
    const float* wt; const float* addsrc; int accAtomic;
    const int* cnt; int splitK;
};

__global__ void __launch_bounds__(256) gemm_bfx(GArgs ga)
{
    extern __shared__ uint32_t sm[];
    uint32_t* As = sm;
    uint32_t* Bs = sm + 2 * GASZ;
    __shared__ int idxs[128];

    int e, kbase, Ke;
    if (ga.splitK > 1) { e = 0; Ke = ga.K / ga.splitK; kbase = blockIdx.z * Ke; }
    else               { e = blockIdx.z; Ke = ga.K; kbase = 0; }

    const int m0 = blockIdx.y * 128;
    const int n0 = blockIdx.x * 128;

    int seg = 0, nloc = n0;
    if (ga.B[1] && n0 >= ga.n1) {
        if (ga.B[2] && n0 >= ga.n1 + ga.n2) { seg = 2; nloc = n0 - ga.n1 - ga.n2; }
        else                                { seg = 1; nloc = n0 - ga.n1; }
    }
    const float* A = ga.A + (size_t)e * ga.aes;
    const float* B = ga.B[seg] + (size_t)e * ga.bes[seg];
    float*       C = ga.C[seg] + (size_t)e * ga.ces[seg];
    const int lda = ga.lda, ldb = ga.ldb[seg], ldc = ga.ldc[seg];
    const int* idx = ga.tok ? ga.tok + (size_t)e * TK : nullptr;
    const float* wt = ga.wt ? ga.wt + (size_t)e * TK : nullptr;
    const int effM = ga.cnt ? ga.cnt[e] : ga.M;
    if (m0 >= effM) return;

    const int tid = threadIdx.x;
    if (idx) {
        for (int i = tid; i < 128; i += 256) {
            int m = m0 + i;
            idxs[i] = (m < effM) ? idx[m] : 0;
        }
        __syncthreads();
    }

    const int am = tid >> 4, ak2 = tid & 15;
    const int bn = tid & 127, bk2 = tid >> 7;

    float2 areg[8];
    float  breg[16];

    auto ldgTile = [&](int kt) {
        #pragma unroll
        for (int i = 0; i < 8; i++) {
            int m = am + i * 16;
            int mg = m0 + m;
            float2 v = make_float2(0.f, 0.f);
            if (mg < effM) {
                int row = ga.gatherA ? idxs[m] : mg;
                v = *(const float2*)(A + (size_t)row * lda + kt + 2 * ak2);
            }
            areg[i] = v;
        }
        #pragma unroll
        for (int i = 0; i < 8; i++) {
            int kk = kt + 2 * (bk2 + i * 2);
            breg[2 * i]     = B[(size_t)kk * ldb + nloc + bn];
            breg[2 * i + 1] = B[(size_t)(kk + 1) * ldb + nloc + bn];
        }
    };
    auto stsTile = [&](int buf) {
        uint32_t* Ad = As + buf * GASZ;
        #pragma unroll
        for (int i = 0; i < 8; i++)
            Ad[(am + i * 16) * GASTR + ak2] = pkbf2(areg[i].x, areg[i].y);
        uint32_t* Bd = Bs + buf * GBSZ;
        #pragma unroll
        for (int i = 0; i < 8; i++)
            Bd[(bk2 + i * 2) * GBSTR + bn] = pkbf2(breg[2 * i], breg[2 * i + 1]);
    };

    const int lane = tid & 31, wid = tid >> 5;
    const int wm = (wid >> 2) * 64;
    const int wn = (wid & 3) * 32;
    const int g = lane >> 2, c = lane & 3;

    float acc[4][4][4];
    #pragma unroll
    for (int i = 0; i < 4; i++)
        #pragma unroll
        for (int j = 0; j < 4; j++)
            #pragma unroll
            for (int r = 0; r < 4; r++) acc[i][j][r] = 0.f;

    ldgTile(kbase);
    stsTile(0);
    __syncthreads();

    const int nbuf = Ke >> 5;
    for (int t = 0; t < nbuf; t++) {
        int cur = t & 1;
        if (t + 1 < nbuf) ldgTile(kbase + ((t + 1) << 5));

        const uint32_t* Ab = As + cur * GASZ;
        const uint32_t* Bb = Bs + cur * GBSZ;
        #pragma unroll
        for (int kp = 0; kp < 16; kp += 8) {
            uint32_t af[4][4];
            #pragma unroll
            for (int mt = 0; mt < 4; mt++) {
                int mb = wm + mt * 16;
                af[mt][0] = Ab[(mb + g) * GASTR + kp + c];
                af[mt][1] = Ab[(mb + g + 8) * GASTR + kp + c];
                af[mt][2] = Ab[(mb + g) * GASTR + kp + c + 4];
                af[mt][3] = Ab[(mb + g + 8) * GASTR + kp + c + 4];
            }
            uint32_t bf[4][2];
            #pragma unroll
            for (int nt = 0; nt < 4; nt++) {
                int nb = wn + nt * 8;
                bf[nt][0] = Bb[(kp + c) * GBSTR + nb + g];
                bf[nt][1] = Bb[(kp + c + 4) * GBSTR + nb + g];
            }
            #pragma unroll
            for (int mt = 0; mt < 4; mt++)
                #pragma unroll
                for (int nt = 0; nt < 4; nt++)
                    mma16(acc[mt][nt], af[mt], bf[nt]);
        }
        if (t + 1 < nbuf) stsTile(cur ^ 1);
        __syncthreads();
    }

    #pragma unroll
    for (int mt = 0; mt < 4; mt++) {
        #pragma unroll
        for (int h2 = 0; h2 < 2; h2++) {
            int ml = wm + mt * 16 + g + h2 * 8;
            int m = m0 + ml;
            if (m >= effM) continue;
            int crow = ga.scatterC ? idxs[ml] : m;
            float sc = wt ? wt[m] : 1.f;
            #pragma unroll
            for (int nt = 0; nt < 4; nt++) {
                int ncol = nloc + wn + nt * 8 + c * 2;
                float v0 = acc[mt][nt][h2 * 2 + 0];
                float v1 = acc[mt][nt][h2 * 2 + 1];
                float* cp = C + (size_t)crow * ldc + ncol;
                if (ga.splitK > 1) {
                    atomicAdd(cp, v0); atomicAdd(cp + 1, v1);
                } else if (wt) {
                    atomicAdd(cp, sc * v0); atomicAdd(cp + 1, sc * v1);
                } else if (ga.accAtomic) {
                    atomicAdd(cp, v0); atomicAdd(cp + 1, v1);
                } else if (ga.addsrc) {
                    const float* ap = ga.addsrc + (size_t)m * ldc + ncol;
                    cp[0] = v0 + ap[0]; cp[1] = v1 + ap[1];
                } else {
                    cp[0] = v0; cp[1] = v1;
                }
            }
        }
    }
}

// ---------------- RMSNorm ----------------
__global__ void rms_k(const float* __restrict__ x, const float* __restrict__ w,
                      float* __restrict__ y, int D)
{
    int t = blockIdx.x;
    const float* xr = x + (size_t)t * D;
    float* yr = y + (size_t)t * D;
    float ss = 0.f;
    for (int k = threadIdx.x; k < D; k += blockDim.x) { float v = xr[k]; ss += v * v; }
    __shared__ float sh[32];
    int lane = threadIdx.x & 31, wid = threadIdx.x >> 5;
    #pragma unroll
    for (int o = 16; o > 0; o >>= 1) ss += __shfl_xor_sync(0xffffffffu, ss, o);
    if (lane == 0) sh[wid] = ss;
    __syncthreads();
    if (threadIdx.x == 0) {
        float tot = 0.f;
        int nw = blockDim.x >> 5;
        for (int i = 0; i < nw; i++) tot += sh[i];
        sh[0] = tot;
    }
    __syncthreads();
    float r = rsqrtf(sh[0] / (float)D + 1e-5f);
    for (int k = threadIdx.x; k < D; k += blockDim.x) yr[k] = w[k] * xr[k] * r;
}

// ---------------- assemble Q/K with RoPE ----------------
__global__ void assemble_k(const float* __restrict__ qn, const float* __restrict__ qr,
                           const float* __restrict__ kn, const float* __restrict__ kr,
                           const float* __restrict__ cosp, const float* __restrict__ sinp,
                           float* __restrict__ Q, float* __restrict__ K)
{
    int idx = blockIdx.x * blockDim.x + threadIdx.x;
    if (idx >= BHN * SS * 64) return;
    int d  = idx & 63;
    int s  = (idx >> 6) & (SS - 1);
    int bh = idx >> 17;
    int b  = bh >> 4, h = bh & 15;
    int t  = b * SS + s;
    float qv, kv;
    if (d < 32) {
        qv = qn[(size_t)t * 512 + h * 32 + d];
        kv = kn[(size_t)t * 512 + h * 32 + d];
    } else {
        int j = d - 32;
        float cc = cosp[s * 32 + j];
        float sn = sinp[s * 32 + j];
        float q1 = qr[(size_t)t * 512 + h * 32 + j];
        float q2 = (j < 16) ? -qr[(size_t)t * 512 + h * 32 + j + 16]
                            :  qr[(size_t)t * 512 + h * 32 + j - 16];
        qv = q1 * cc + q2 * sn;
        float k1 = kr[(size_t)t * 512 + h * 32 + j];
        float k2 = (j < 16) ? -kr[(size_t)t * 512 + h * 32 + j + 16]
                            :  kr[(size_t)t * 512 + h * 32 + j - 16];
        kv = k1 * cc + k2 * sn;
    }
    Q[idx] = qv;
    K[idx] = kv;
}

// ---------------- flash attention, bf16, BM=128 (256 thr, 8 warps x 16 rows) ----------------
// smem (u32): Qs[128][36] | Kt[32][72] | Ps[128][36] | Vs[32][72] = 13824 u32 = 54 KB
#define FQS 36
#define FKS 72
__global__ void __launch_bounds__(256) flash_bf(
    const float* __restrict__ Q, const float* __restrict__ Kg,
    const float* __restrict__ Vx, const float* __restrict__ maskp,
    float* __restrict__ O)
{
    extern __shared__ uint32_t sm[];
    uint32_t* Qs = sm;                        // [row][kpair]   128*36
    uint32_t* Kt = sm + 128 * FQS;            // [kpair][key]   32*72
    uint32_t* Ps = Kt + 32 * FKS;             // [row][keypair] 128*36
    uint32_t* Vs = Ps + 128 * FQS;            // [keypair][d]   32*72

    const int bh = blockIdx.y;
    const int q0 = blockIdx.x * 128;
    const int b  = bh >> 4, hh = bh & 15;
    const float* Qb = Q  + (size_t)bh * SS * 64;
    const float* Kb = Kg + (size_t)bh * SS * 64;
    const float* Vb = Vx + (size_t)b * SS * HH + hh * 64;

    const int tid = threadIdx.x;
    const int w = tid >> 5, lane = tid & 31;
    const int g = lane >> 2, c = lane & 3;
    const int wrow = w * 16;            // 0..112

    // load coords
    const int qlr  = tid & 127;          // Q row
    const int qlc0 = (tid >> 7) * 32;    // Q d base (0/32)
    const int klr  = tid & 63;           // K key
    const int klc0 = (tid >> 6) * 16;    // K d base (0/16/32/48)
    const int vkp  = tid & 31;           // V keypair
    const int vdb  = (tid >> 5) * 8;     // V d base (0..56)

    { // Q tile -> packed bf16
        const float4* src = (const float4*)(Qb + (size_t)(q0 + qlr) * 64 + qlc0);
        #pragma unroll
        for (int i = 0; i < 8; i++) {
            float4 v = src[i];
            uint32_t* d = Qs + qlr * FQS + (qlc0 >> 1) + i * 2;
            d[0] = pkbf2(v.x, v.y);
            d[1] = pkbf2(v.z, v.w);
        }
    }

    float4 kreg[4];
    float4 vreg0[2], vreg1[2];
    auto ldgKV = [&](int k0) {
        const float4* ks = (const float4*)(Kb + (size_t)(k0 + klr) * 64 + klc0);
        #pragma unroll
        for (int i = 0; i < 4; i++) kreg[i] = ks[i];
        const float* v0p = Vb + (size_t)(k0 + 2 * vkp) * HH + vdb;
        const float* v1p = v0p + HH;
        #pragma unroll
        for (int i = 0; i < 2; i++) {
            vreg0[i] = *(const float4*)(v0p + i * 4);
            vreg1[i] = *(const float4*)(v1p + i * 4);
        }
    };
    auto stsKV = [&]() {
        #pragma unroll
        for (int i = 0; i < 4; i++) {
            float4 kv = kreg[i];
            int dp = (klc0 + i * 4) >> 1;
            Kt[(dp + 0) * FKS + klr] = pkbf2(kv.x, kv.y);
            Kt[(dp + 1) * FKS + klr] = pkbf2(kv.z, kv.w);
        }
        #pragma unroll
        for (int i = 0; i < 2; i++) {
            float4 a = vreg0[i];
            float4 bb = vreg1[i];
            uint32_t* vd = Vs + vkp * FKS + vdb + i * 4;
            vd[0] = pkbf2(a.x, bb.x);
            vd[1] = pkbf2(a.y, bb.y);
            vd[2] = pkbf2(a.z, bb.z);
            vd[3] = pkbf2(a.w, bb.w);
        }
    };

    float oacc[8][4];
    #pragma unroll
    for (int nf = 0; nf < 8; nf++)
        #pragma unroll
        for (int r = 0; r < 4; r++) oacc[nf][r] = 0.f;
    float m0 = -1e30f, m1 = -1e30f, l0 = 0.f, l1 = 0.f;

    const float* mr0 = maskp + (size_t)(q0 + wrow + g) * SS;
    const float* mr1 = mr0 + 8 * SS;

    ldgKV(0);
    for (int k0 = 0; k0 < SS; k0 += 64) {
        __syncthreads();
        stsKV();
        __syncthreads();
        if (k0 + 64 < SS) ldgKV(k0 + 64);

        // S = Q @ K^T
        float sacc[8][4];
        #pragma unroll
        for (int nf = 0; nf < 8; nf++)
            #pragma unroll
            for (int r = 0; r < 4; r++) sacc[nf][r] = 0.f;
        #pragma unroll
        for (int ks = 0; ks < 32; ks += 8) {
            uint32_t af[4];
            af[0] = Qs[(wrow + g) * FQS + ks + c];
            af[1] = Qs[(wrow + g + 8) * FQS + ks + c];
            af[2] = Qs[(wrow + g) * FQS + ks + c + 4];
            af[3] = Qs[(wrow + g + 8) * FQS + ks + c + 4];
            #pragma unroll
            for (int nf = 0; nf < 8; nf++) {
                uint32_t bf[2];
                bf[0] = Kt[(ks + c) * FKS + nf * 8 + g];
                bf[1] = Kt[(ks + c + 4) * FKS + nf * 8 + g];
                mma16(sacc[nf], af, bf);
            }
        }

        // scale + mask + online softmax
        float mx0 = -1e30f, mx1 = -1e30f;
        #pragma unroll
        for (int nf = 0; nf < 8; nf++) {
            float2 mk0 = *(const float2*)(mr0 + k0 + nf * 8 + 2 * c);
            float2 mk1 = *(const float2*)(mr1 + k0 + nf * 8 + 2 * c);
            sacc[nf][0] = sacc[nf][0] * 0.125f + mk0.x;
            sacc[nf][1] = sacc[nf][1] * 0.125f + mk0.y;
            sacc[nf][2] = sacc[nf][2] * 0.125f + mk1.x;
            sacc[nf][3] = sacc[nf][3] * 0.125f + mk1.y;
            mx0 = fmaxf(mx0, fmaxf(sacc[nf][0], sacc[nf][1]));
            mx1 = fmaxf(mx1, fmaxf(sacc[nf][2], sacc[nf][3]));
        }
        mx0 = fmaxf(mx0, __shfl_xor_sync(0xffffffffu, mx0, 1));
        mx0 = fmaxf(mx0, __shfl_xor_sync(0xffffffffu, mx0, 2));
        mx1 = fmaxf(mx1, __shfl_xor_sync(0xffffffffu, mx1, 1));
        mx1 = fmaxf(mx1, __shfl_xor_sync(0xffffffffu, mx1, 2));

        float mn0 = fmaxf(m0, mx0), mn1 = fmaxf(m1, mx1);
        float cr0 = __expf(m0 - mn0), cr1 = __expf(m1 - mn1);
        m0 = mn0; m1 = mn1;
        float rs0 = 0.f, rs1 = 0.f;
        #pragma unroll
        for (int nf = 0; nf < 8; nf++) {
            sacc[nf][0] = __expf(sacc[nf][0] - mn0);
            sacc[nf][1] = __expf(sacc[nf][1] - mn0);
            sacc[nf][2] = __expf(sacc[nf][2] - mn1);
            sacc[nf][3] = __expf(sacc[nf][3] - mn1);
            rs0 += sacc[nf][0] + sacc[nf][1];
            rs1 += sacc[nf][2] + sacc[nf][3];
        }
        rs0 += __shfl_xor_sync(0xffffffffu, rs0, 1);
        rs0 += __shfl_xor_sync(0xffffffffu, rs0, 2);
        rs1 += __shfl_xor_sync(0xffffffffu, rs1, 1);
        rs1 += __shfl_xor_sync(0xffffffffu, rs1, 2);
        l0 = l0 * cr0 + rs0;
        l1 = l1 * cr1 + rs1;
        #pragma unroll
        for (int nf = 0; nf < 8; nf++) {
            oacc[nf][0] *= cr0; oacc[nf][1] *= cr0;
            oacc[nf][2] *= cr1; oacc[nf][3] *= cr1;
        }

        // write P packed bf16
        #pragma unroll
        for (int nf = 0; nf < 8; nf++) {
            int kp = nf * 4 + c;
            Ps[(wrow + g) * FQS + kp]     = pkbf2(sacc[nf][0], sacc[nf][1]);
            Ps[(wrow + g + 8) * FQS + kp] = pkbf2(sacc[nf][2], sacc[nf][3]);
        }
        __syncwarp();   // Ps rows are warp-private (16 rows per warp)

        // O += P @ V
        #pragma unroll
        for (int kk = 0; kk < 32; kk += 8) {
            uint32_t af[4];
            af[0] = Ps[(wrow + g) * FQS + kk + c];
            af[1] = Ps[(wrow + g + 8) * FQS + kk + c];
            af[2] = Ps[(wrow + g) * FQS + kk + c + 4];
            af[3] = Ps[(wrow + g + 8) * FQS + kk + c + 4];
            #pragma unroll
            for (int nf = 0; nf < 8; nf++) {
                uint32_t bf[2];
                bf[0] = Vs[(kk + c) * FKS + nf * 8 + g];
                bf[1] = Vs[(kk + c + 4) * FKS + nf * 8 + g];
                mma16(oacc[nf], af, bf);
            }
        }
    }

    float inv0 = 1.f / l0, inv1 = 1.f / l1;
    int row0 = q0 + wrow + g;
    float* o0 = O + ((size_t)(b * SS + row0)) * HH + hh * 64;
    float* o1 = o0 + 8 * (size_t)HH;
    #pragma unroll
    for (int nf = 0; nf < 8; nf++) {
        int col = nf * 8 + 2 * c;
        float2 v0 = make_float2(oacc[nf][0] * inv0, oacc[nf][1] * inv0);
        float2 v1 = make_float2(oacc[nf][2] * inv1, oacc[nf][3] * inv1);
        *(float2*)(o0 + col) = v0;
        *(float2*)(o1 + col) = v1;
    }
}

// ---------------- router ----------------
__global__ void router_k(const float* __restrict__ hn, const float* __restrict__ rw,
                         const float* __restrict__ rb,
                         int* __restrict__ cnt, int* __restrict__ tok, float* __restrict__ twt)
{
    int t = blockIdx.x;
    __shared__ float red[128][NE];
    float accv[NE];
    #pragma unroll
    for (int e = 0; e < NE; e++) accv[e] = 0.f;
    const float* xr = hn + (size_t)t * HH;
    for (int k = threadIdx.x; k < HH; k += 128) {
        float xv = xr[k];
        const float* w = rw + (size_t)k * NE;
        #pragma unroll
        for (int e = 0; e < NE; e++) accv[e] += xv * w[e];
    }
    #pragma unroll
    for (int e = 0; e < NE; e++) red[threadIdx.x][e] = accv[e];
    __syncthreads();
    for (int s = 64; s > 0; s >>= 1) {
        if (threadIdx.x < s)
            #pragma unroll
            for (int e = 0; e < NE; e++) red[threadIdx.x][e] += red[threadIdx.x + s][e];
        __syncthreads();
    }
    if (threadIdx.x == 0) {
        float p[NE];
        #pragma unroll
        for (int e = 0; e < NE; e++) {
            float lg = red[0][e] + rb[e];
            p[e] = 1.f / (1.f + expf(-lg));
        }
        int e1 = 0;
        for (int e = 1; e < NE; e++) if (p[e] > p[e1]) e1 = e;
        int e2 = -1;
        for (int e = 0; e < NE; e++) if (e != e1 && (e2 < 0 || p[e] > p[e2])) e2 = e;
        float s2 = p[e1] + p[e2];
        float w1 = p[e1] / s2, w2 = p[e2] / s2;
        int a = atomicAdd(&cnt[e1], 1); tok[e1 * TK + a] = t; twt[e1 * TK + a] = w1;
        int b = atomicAdd(&cnt[e2], 1); tok[e2 * TK + b] = t; twt[e2 * TK + b] = w2;
    }
}

__global__ void silu_mul_k(const float* __restrict__ g, const float* __restrict__ u,
                           float* __restrict__ y, int n)
{
    int i = blockIdx.x * 256 + threadIdx.x;
    if (i < n) {
        float gv = g[i];
        y[i] = (gv / (1.f + expf(-gv))) * u[i];
    }
}

__global__ void silu_mul_moe(const float* __restrict__ g, const float* __restrict__ u,
                             float* __restrict__ y, const int* __restrict__ cnt)
{
    const size_t TI = (size_t)TK * II;
    int e = blockIdx.y;
    int i = blockIdx.x * 256 + threadIdx.x;
    if (i / II >= cnt[e]) return;
    size_t idx = (size_t)e * TI + i;
    float gv = g[idx];
    y[idx] = (gv / (1.f + expf(-gv))) * u[idx];
}

__global__ void usage_k(const int* __restrict__ cnt, float* __restrict__ out)
{
    int e = threadIdx.x;
    if (e < NE) out[e] = (float)cnt[e];
}

// ---------------- host-side dispatch ----------------
static const int SMEMB = (2 * (GASZ + GBSZ)) * 4;   // 37888
static const int SMEMF = (128 * FQS + 32 * FKS + 128 * FQS + 32 * FKS) * 4;  // 55296

static GArgs mkargs(const float* A, int lda, size_t aes,
                    const float* B0, int ldb0, size_t bes0,
                    float* C0, int ldc0, size_t ces0,
                    int M, int N, int K)
{
    GArgs ga = {};
    ga.A = A; ga.lda = lda; ga.aes = aes;
    ga.B[0] = B0; ga.ldb[0] = ldb0; ga.bes[0] = bes0;
    ga.C[0] = C0; ga.ldc[0] = ldc0; ga.ces[0] = ces0;
    ga.n1 = N; ga.n2 = 0;
    ga.M = M; ga.N = N; ga.K = K;
    ga.splitK = 1;
    return ga;
}

static void launch(cudaStream_t st, const GArgs& ga, int nz)
{
    dim3 grid(ga.N / 128, (ga.M + 127) / 128, nz);
    gemm_bfx<<<grid, 256, SMEMB, st>>>(ga);
}

extern "C" void kernel_launch(void* const* d_in, const int* in_sizes, int n_in,
                              void* d_out, int out_size)
{
    const float* x        = (const float*)d_in[0];
    const float* cosp     = (const float*)d_in[1];
    const float* sinp     = (const float*)d_in[2];
    const float* maskp    = (const float*)d_in[3];
    const float* ln1      = (const float*)d_in[4];
    const float* ln2      = (const float*)d_in[5];
    const float* kv_down  = (const float*)d_in[6];
    const float* kv_norm  = (const float*)d_in[7];
    const float* w_uk     = (const float*)d_in[8];
    const float* w_ur     = (const float*)d_in[9];
    const float* w_uv     = (const float*)d_in[10];
    const float* q_down   = (const float*)d_in[11];
    const float* q_norm   = (const float*)d_in[12];
    const float* w_uq     = (const float*)d_in[13];
    const float* w_qr     = (const float*)d_in[14];
    const float* o_proj   = (const float*)d_in[15];
    const float* sh_gate  = (const float*)d_in[16];
    const float* sh_up    = (const float*)d_in[17];
    const float* sh_down  = (const float*)d_in[18];
    const float* r_gate   = (const float*)d_in[19];
    const float* r_up     = (const float*)d_in[20];
    const float* r_down   = (const float*)d_in[21];
    const float* router_w = (const float*)d_in[22];
    const float* router_b = (const float*)d_in[23];
    float* out = (float*)d_out;

    float *xi, *cq, *ckv, *qn, *qr, *kn, *kr, *vx, *q, *k, *o, *h, *hn, *gt, *ut, *act, *twt;
    int *cnt, *tok;
    cudaGetSymbolAddress((void**)&xi,  g_xi);
    cudaGetSymbolAddress((void**)&cq,  g_cq);
    cudaGetSymbolAddress((void**)&ckv, g_ckv);
    cudaGetSymbolAddress((void**)&qn,  g_qn);
    cudaGetSymbolAddress((void**)&qr,  g_qr);
    cudaGetSymbolAddress((void**)&kn,  g_kn);
    cudaGetSymbolAddress((void**)&kr,  g_kr);
    cudaGetSymbolAddress((void**)&vx,  g_vx);
    cudaGetSymbolAddress((void**)&q,   g_q);
    cudaGetSymbolAddress((void**)&k,   g_k);
    cudaGetSymbolAddress((void**)&o,   g_o);
    cudaGetSymbolAddress((void**)&h,   g_h);
    cudaGetSymbolAddress((void**)&hn,  g_hn);
    cudaGetSymbolAddress((void**)&gt,  g_gt);
    cudaGetSymbolAddress((void**)&ut,  g_ut);
    cudaGetSymbolAddress((void**)&act, g_act);
    cudaGetSymbolAddress((void**)&twt, g_twt);
    cudaGetSymbolAddress((void**)&cnt, g_cnt);
    cudaGetSymbolAddress((void**)&tok, g_tok);

    cudaFuncSetAttribute(gemm_bfx, cudaFuncAttributeMaxDynamicSharedMemorySize, SMEMB);
    cudaFuncSetAttribute(flash_bf, cudaFuncAttributeMaxDynamicSharedMemorySize, SMEMF);

    cudaStream_t s0 = 0, s1;
    cudaStreamCreateWithFlags(&s1, cudaStreamNonBlocking);
    cudaEvent_t ev0, ev1, ev2, ev3;
    cudaEventCreateWithFlags(&ev0, cudaEventDisableTiming);
    cudaEventCreateWithFlags(&ev1, cudaEventDisableTiming);
    cudaEventCreateWithFlags(&ev2, cudaEventDisableTiming);
    cudaEventCreateWithFlags(&ev3, cudaEventDisableTiming);

    const size_t TI = (size_t)TK * II;
    const size_t WE = (size_t)HH * II;
    const size_t WD = (size_t)II * HH;

    // ---- MLA attention ----
    rms_k<<<TK, 256, 0, s0>>>(x, ln1, xi, HH);

    cudaMemsetAsync(cq, 0, (size_t)TK * 128 * sizeof(float), s0);
    cudaMemsetAsync(ckv, 0, (size_t)TK * 128 * sizeof(float), s0);
    {
        GArgs ga = mkargs(xi, HH, 0, q_down, 128, 0, cq, 128, 0, TK, 256, HH);
        ga.n1 = 128;
        ga.B[1] = kv_down; ga.ldb[1] = 128; ga.bes[1] = 0;
        ga.C[1] = ckv;     ga.ldc[1] = 128; ga.ces[1] = 0;
        ga.splitK = 4;
        launch(s0, ga, 4);
    }
    rms_k<<<TK, 128, 0, s0>>>(cq, q_norm, cq, 128);
    cudaEventRecord(ev0, s0);
    cudaStreamWaitEvent(s1, ev0, 0);
    rms_k<<<TK, 128, 0, s1>>>(ckv, kv_norm, ckv, 128);

    {
        GArgs ga = mkargs(cq, 128, 0, w_uq, 512, 0, qn, 512, 0, TK, 1024, 128);
        ga.n1 = 512;
        ga.B[1] = w_qr; ga.ldb[1] = 512; ga.bes[1] = 0;
        ga.C[1] = qr;   ga.ldc[1] = 512; ga.ces[1] = 0;
        launch(s0, ga, 1);
    }
    {
        GArgs ga = mkargs(ckv, 128, 0, w_uk, 512, 0, kn, 512, 0, TK, 2048, 128);
        ga.n1 = 512; ga.n2 = 512;
        ga.B[1] = w_ur; ga.ldb[1] = 512;  ga.bes[1] = 0;
        ga.C[1] = kr;   ga.ldc[1] = 512;  ga.ces[1] = 0;
        ga.B[2] = w_uv; ga.ldb[2] = 1024; ga.bes[2] = 0;
        ga.C[2] = vx;   ga.ldc[2] = 1024; ga.ces[2] = 0;
        launch(s1, ga, 1);
    }
    cudaEventRecord(ev1, s1);
    cudaStreamWaitEvent(s0, ev1, 0);

    assemble_k<<<(BHN * SS * 64) / 256, 256, 0, s0>>>(qn, qr, kn, kr, cosp, sinp, q, k);
    flash_bf<<<dim3(SS / 128, BHN), 256, SMEMF, s0>>>(q, k, vx, maskp, o);
    {
        GArgs ga = mkargs(o, HH, 0, o_proj, HH, 0, h, HH, 0, TK, HH, HH);
        ga.addsrc = x;
        launch(s0, ga, 1);
    }

    // ---- MoE (bf16) ----
    rms_k<<<TK, 256, 0, s0>>>(h, ln2, hn, HH);
    cudaMemsetAsync(cnt, 0, NE * sizeof(int), s0);
    router_k<<<TK, 128, 0, s0>>>(hn, router_w, router_b, cnt, tok, twt);
    cudaMemcpyAsync(out, h, (size_t)TK * HH * sizeof(float), cudaMemcpyDeviceToDevice, s0);
    cudaEventRecord(ev2, s0);
    cudaStreamWaitEvent(s1, ev2, 0);

    {
        GArgs ga = mkargs(hn, HH, 0, sh_gate, II, WE, gt, II, TI, TK, 768, HH);
        ga.n1 = II;
        ga.B[1] = sh_up; ga.ldb[1] = II; ga.bes[1] = WE;
        ga.C[1] = ut;    ga.ldc[1] = II; ga.ces[1] = TI;
        launch(s0, ga, 2);
    }
    silu_mul_k<<<(2 * (int)TI + 255) / 256, 256, 0, s0>>>(gt, ut, act, 2 * (int)TI);
    {
        GArgs ga = mkargs(act, II, TI, sh_down, HH, WD, out, HH, 0, TK, HH, II);
        ga.accAtomic = 1;
        launch(s0, ga, 2);
    }

    float* gt2 = gt + 2 * TI;
    float* ut2 = ut + 2 * TI;
    float* act2 = act + 2 * TI;
    {
        GArgs ga = mkargs(hn, HH, 0, r_gate, II, WE, gt2, II, TI, TK, 768, HH);
        ga.n1 = II;
        ga.B[1] = r_up; ga.ldb[1] = II; ga.bes[1] = WE;
        ga.C[1] = ut2;  ga.ldc[1] = II; ga.ces[1] = TI;
        ga.tok = tok; ga.gatherA = 1; ga.cnt = cnt;
        launch(s1, ga, NE);
    }
    silu_mul_moe<<<dim3(((int)TI + 255) / 256, NE), 256, 0, s1>>>(gt2, ut2, act2, cnt);
    {
        GArgs ga = mkargs(act2, II, TI, r_down, HH, WD, out, HH, 0, TK, HH, II);
        ga.tok = tok; ga.scatterC = 1; ga.wt = twt; ga.cnt = cnt;
        launch(s1, ga, NE);
    }
    cudaEventRecord(ev3, s1);
    cudaStreamWaitEvent(s0, ev3, 0);

    usage_k<<<1, NE, 0, s0>>>(cnt, out + (size_t)TK * HH);
}